// round 1
// baseline (speedup 1.0000x reference)
#include <cuda_runtime.h>
#include <cuda_bf16.h>
#include <math.h>

// Problem constants
#define BB 16
#define NN_TOK 1024
#define DD 384
#define C2 768
#define C4 1536
#define HEADS 8
#define HD 48
#define T_TOK (BB*NN_TOK)   // 16384

// ---------------- scratch (device globals; no allocation allowed) -------------
__device__ float g_ln[(size_t)T_TOK*C2];
__device__ float g_qkv[(size_t)T_TOK*1152];
__device__ float g_qn[(size_t)BB*HEADS*HD*NN_TOK];
__device__ float g_kn[(size_t)BB*HEADS*HD*NN_TOK];
__device__ float g_attn[(size_t)BB*HEADS*HD*HD];
__device__ float g_attnout[(size_t)T_TOK*DD];
__device__ float g_ch1[(size_t)T_TOK*DD];
__device__ float g_ch2[(size_t)T_TOK*DD];
__device__ float g_n1[(size_t)T_TOK*DD];
__device__ float g_n2[(size_t)T_TOK*DD];
__device__ float g_key[(size_t)BB*DD*NN_TOK];     // [B,D,N]
__device__ float g_query[(size_t)T_TOK*DD];       // token-major
__device__ float g_ctx[(size_t)BB*DD*DD];
__device__ float g_att2[(size_t)T_TOK*DD];
__device__ float g_rep[(size_t)T_TOK*C2];
__device__ float g_crossln[(size_t)T_TOK*C2];
__device__ float g_tx[(size_t)T_TOK*C2];
__device__ float g_h1[(size_t)T_TOK*C4];
__device__ float g_h2[(size_t)T_TOK*C4];

// ---------------- reductions -------------------------------------------------
__device__ __forceinline__ float warpSum(float v){
    #pragma unroll
    for(int o=16;o>0;o>>=1) v += __shfl_down_sync(0xffffffffu, v, o);
    return v;
}
__device__ __forceinline__ float warpMax(float v){
    #pragma unroll
    for(int o=16;o>0;o>>=1) v = fmaxf(v, __shfl_down_sync(0xffffffffu, v, o));
    return v;
}
__device__ __forceinline__ float blockSum(float v, float* sh){
    int lane = threadIdx.x & 31, wid = threadIdx.x >> 5;
    v = warpSum(v);
    if(lane==0) sh[wid]=v;
    __syncthreads();
    int nw = blockDim.x >> 5;
    float r = (threadIdx.x < (unsigned)nw) ? sh[threadIdx.x] : 0.f;
    if(wid==0){ r = warpSum(r); if(lane==0) sh[0]=r; }
    __syncthreads();
    r = sh[0];
    __syncthreads();
    return r;
}
__device__ __forceinline__ float blockMax(float v, float* sh){
    int lane = threadIdx.x & 31, wid = threadIdx.x >> 5;
    v = warpMax(v);
    if(lane==0) sh[wid]=v;
    __syncthreads();
    int nw = blockDim.x >> 5;
    float r = (threadIdx.x < (unsigned)nw) ? sh[threadIdx.x] : -INFINITY;
    if(wid==0){ r = warpMax(r); if(lane==0) sh[0]=r; }
    __syncthreads();
    r = sh[0];
    __syncthreads();
    return r;
}

// ---------------- LayerNorm (W = 384 or 768; block=128) ----------------------
__global__ void ln_kernel(const float* __restrict__ x, const float* __restrict__ g,
                          const float* __restrict__ b, float* __restrict__ y, int W){
    long row = blockIdx.x;
    const float* xr = x + row*(long)W;
    int vpt = W >> 7;
    float v[6];
    float s=0.f, s2=0.f;
    for(int i=0;i<vpt;i++){
        float t = xr[i*128 + threadIdx.x];
        v[i]=t; s+=t; s2+=t*t;
    }
    __shared__ float sh[32];
    s  = blockSum(s, sh);
    s2 = blockSum(s2, sh);
    float mu = s / (float)W;
    float var = s2 / (float)W - mu*mu;
    float rstd = rsqrtf(var + 1e-5f);
    float* yr = y + row*(long)W;
    for(int i=0;i<vpt;i++){
        int c = i*128 + threadIdx.x;
        yr[c] = (v[i]-mu)*rstd*g[c] + b[c];
    }
}

// ---------------- L2-norm over tokens + transpose to [B,h,d,N] ---------------
// grid = 2*B*H*HD = 12288, block = 256
__global__ void l2norm_qk_kernel(const float* __restrict__ qkv,
                                 float* __restrict__ qn, float* __restrict__ kn){
    int idx = blockIdx.x;
    int which = idx / (BB*HEADS*HD);     // 0 = q, 1 = k
    int r = idx % (BB*HEADS*HD);
    int b = r / (HEADS*HD);
    int hj = r % (HEADS*HD);
    int col = which*DD + hj;
    const float* base = qkv + (long)b*NN_TOK*1152 + col;
    float v[4]; float s=0.f;
    #pragma unroll
    for(int i=0;i<4;i++){
        int n = threadIdx.x + i*256;
        float t = base[(long)n*1152];
        v[i]=t; s+=t*t;
    }
    __shared__ float sh[32];
    s = blockSum(s, sh);
    float nrm = sqrtf(s);
    float scale = 1.0f / fmaxf(nrm, 1e-12f);
    float* out = (which==0 ? qn : kn) + ((long)b*(HEADS*HD) + hj)*NN_TOK;
    #pragma unroll
    for(int i=0;i<4;i++){
        int n = threadIdx.x + i*256;
        out[n] = v[i]*scale;
    }
}

// ---------------- attn logits: q@k^T per (b,h), 48x48, K=1024 ----------------
// grid = B*H = 128, block = 256
__global__ void qk_kernel(const float* __restrict__ qn, const float* __restrict__ kn,
                          float* __restrict__ attn){
    int bh = blockIdx.x;
    const float* q = qn + (long)bh*HD*NN_TOK;
    const float* k = kn + (long)bh*HD*NN_TOK;
    __shared__ float qs[48*64];
    __shared__ float ks[48*64];
    float acc[9];
    #pragma unroll
    for(int t=0;t<9;t++) acc[t]=0.f;
    for(int n0=0;n0<NN_TOK;n0+=64){
        __syncthreads();
        #pragma unroll
        for(int i=0;i<12;i++){
            int e = threadIdx.x + i*256;
            int rr = e>>6, cc = e&63;
            qs[e] = q[rr*NN_TOK + n0 + cc];
            ks[e] = k[rr*NN_TOK + n0 + cc];
        }
        __syncthreads();
        #pragma unroll
        for(int t=0;t<9;t++){
            int o = threadIdx.x + t*256;
            int i_ = o/48, j_ = o%48;
            float a = 0.f;
            #pragma unroll
            for(int kk=0;kk<64;kk++) a = fmaf(qs[i_*64+kk], ks[j_*64+kk], a);
            acc[t] += a;
        }
    }
    #pragma unroll
    for(int t=0;t<9;t++){
        int o = threadIdx.x + t*256;
        attn[(long)bh*2304 + o] = acc[t];
    }
}

// ---------------- softmax over last-48 with temp ------------------------------
// grid = B*H*HD = 6144, block = 64
__global__ void softmax_attn_kernel(float* __restrict__ attn, const float* __restrict__ temp){
    int row = blockIdx.x;
    int h = (row / HD) & (HEADS-1);
    float t = temp[h];
    float* a = attn + (long)row*HD;
    int tid = threadIdx.x;
    float v = (tid<HD) ? a[tid]*t : -INFINITY;
    __shared__ float sh[32];
    float m = blockMax(v, sh);
    float e = (tid<HD) ? expf(v - m) : 0.f;
    float s = blockSum(e, sh);
    if(tid<HD) a[tid] = e / s;
}

// ---------------- attn @ v -> token-major out --------------------------------
// grid = B*H = 128, block = 256
__global__ void pv_kernel(const float* __restrict__ attn, const float* __restrict__ qkv,
                          float* __restrict__ out){
    int bh = blockIdx.x;
    int b = bh >> 3, h = bh & 7;
    __shared__ float as[48*48];
    __shared__ float vs[64*48];
    for(int i=threadIdx.x;i<2304;i+=256) as[i] = attn[(long)bh*2304 + i];
    const float* vbase = qkv + (long)b*NN_TOK*1152 + 2*DD + h*HD;
    for(int n0=0;n0<NN_TOK;n0+=64){
        __syncthreads();
        #pragma unroll
        for(int i=0;i<12;i++){
            int e = threadIdx.x + i*256;
            int nn = e/48, j = e%48;
            vs[e] = vbase[(long)(n0+nn)*1152 + j];
        }
        __syncthreads();
        #pragma unroll
        for(int t=0;t<12;t++){
            int o = threadIdx.x + t*256;
            int nn = o/48, i_ = o%48;
            float a = 0.f;
            #pragma unroll
            for(int j=0;j<48;j++) a = fmaf(as[i_*48+j], vs[nn*48+j], a);
            out[((long)b*NN_TOK + n0 + nn)*DD + h*HD + i_] = a;
        }
    }
}

// ---------------- column softmax (over tokens) -> key [B,D,N] ----------------
// grid = B*D = 6144, block = 256
__global__ void colsoftmax_kernel(const float* __restrict__ x, float* __restrict__ key){
    int idx = blockIdx.x;
    int b = idx / DD, d = idx % DD;
    const float* base = x + (long)b*NN_TOK*DD + d;
    float v[4]; float m = -INFINITY;
    #pragma unroll
    for(int i=0;i<4;i++){
        int n = threadIdx.x + i*256;
        float t = base[(long)n*DD];
        v[i]=t; m = fmaxf(m,t);
    }
    __shared__ float sh[32];
    m = blockMax(m, sh);
    float s = 0.f;
    #pragma unroll
    for(int i=0;i<4;i++){ v[i] = expf(v[i]-m); s += v[i]; }
    s = blockSum(s, sh);
    float inv = 1.0f / s;
    float* out = key + ((long)b*DD + d)*NN_TOK;
    #pragma unroll
    for(int i=0;i<4;i++) out[threadIdx.x + i*256] = v[i]*inv;
}

// ---------------- row softmax (over channels, 384) -> query token-major ------
// grid = T, block = 128
__global__ void rowsoftmax_kernel(const float* __restrict__ x, float* __restrict__ y){
    long row = blockIdx.x;
    const float* xr = x + row*DD;
    float v[3]; float m = -INFINITY;
    #pragma unroll
    for(int i=0;i<3;i++){
        float t = xr[i*128 + threadIdx.x];
        v[i]=t; m=fmaxf(m,t);
    }
    __shared__ float sh[32];
    m = blockMax(m, sh);
    float s=0.f;
    #pragma unroll
    for(int i=0;i<3;i++){ v[i]=expf(v[i]-m); s+=v[i]; }
    s = blockSum(s, sh);
    float inv = 1.0f/s;
    float* yr = y + row*DD;
    #pragma unroll
    for(int i=0;i<3;i++) yr[i*128 + threadIdx.x] = v[i]*inv;
}

// ---------------- tx = concat(ch1,ch2) + cross --------------------------------
__global__ void tx_add_kernel(const float* __restrict__ ch1, const float* __restrict__ ch2,
                              const float* __restrict__ cl, float* __restrict__ tx){
    long i = (long)blockIdx.x*blockDim.x + threadIdx.x;
    long t = i / C2; int f = (int)(i % C2);
    float base = (f < DD) ? ch1[t*DD + f] : ch2[t*DD + f - DD];
    tx[i] = base + cl[i];
}

// ---------------- depthwise 3x3 + exact GELU ----------------------------------
// grid = (C4/256, N, B), block = 256
__global__ void dwconv_gelu_kernel(const float* __restrict__ h1, const float* __restrict__ w,
                                   const float* __restrict__ bias, float* __restrict__ h2){
    int c = blockIdx.x*blockDim.x + threadIdx.x;
    int n = blockIdx.y, b = blockIdx.z;
    int y = n >> 5, x = n & 31;
    float acc = bias[c];
    const float* wc = w + c*9;
    const float* base = h1 + (long)b*NN_TOK*C4 + c;
    #pragma unroll
    for(int ky=0;ky<3;ky++){
        int yy = y + ky - 1;
        if(yy < 0 || yy > 31) continue;
        #pragma unroll
        for(int kx=0;kx<3;kx++){
            int xx = x + kx - 1;
            if(xx < 0 || xx > 31) continue;
            acc = fmaf(base[(long)(yy*32+xx)*C4], wc[ky*3+kx], acc);
        }
    }
    float g = 0.5f*acc*(1.f + erff(acc*0.70710678118654752f));
    h2[((long)b*NN_TOK + n)*C4 + c] = g;
}

// ---------------- tiled SGEMM: C = A@B (+bias)(+res), optional B^T ------------
// 64x64x16 tile, block=256, each thread 4x4. Requires M%64==0, N%64==0, K%16==0.
template<bool TB, bool BIAS, bool RES>
__global__ __launch_bounds__(256)
void sgemm_kernel(const float* __restrict__ A, const float* __restrict__ Bm,
                  const float* __restrict__ bias, const float* __restrict__ res,
                  float* __restrict__ C,
                  int M, int N, int K, int lda, int ldb, int ldc,
                  long long sA, long long sB, long long sC){
    int bz = blockIdx.z;
    A  += (long long)bz*sA;
    Bm += (long long)bz*sB;
    C  += (long long)bz*sC;
    const float* R = RES ? res + (long long)bz*sC : nullptr;

    int rowT = blockIdx.y*64, colT = blockIdx.x*64;
    __shared__ float As[16][68];
    __shared__ float Bs[16][68];
    int tid = threadIdx.x;
    int txx = tid & 15, tyy = tid >> 4;

    float acc[4][4];
    #pragma unroll
    for(int i=0;i<4;i++)
        #pragma unroll
        for(int j=0;j<4;j++) acc[i][j]=0.f;

    for(int k0=0;k0<K;k0+=16){
        #pragma unroll
        for(int i=0;i<4;i++){
            int e = tid + i*256;
            int r = e>>4, c = e&15;
            As[c][r] = A[(long)(rowT+r)*lda + k0 + c];
        }
        if(!TB){
            #pragma unroll
            for(int i=0;i<4;i++){
                int e = tid + i*256;
                int r = e>>6, c = e&63;
                Bs[r][c] = Bm[(long)(k0+r)*ldb + colT + c];
            }
        }else{
            #pragma unroll
            for(int i=0;i<4;i++){
                int e = tid + i*256;
                int r = e&15, c = e>>4;
                Bs[r][c] = Bm[(long)(colT+c)*ldb + k0 + r];
            }
        }
        __syncthreads();
        #pragma unroll
        for(int k=0;k<16;k++){
            float4 a4 = *(const float4*)&As[k][tyy*4];
            float4 b4 = *(const float4*)&Bs[k][txx*4];
            float a[4] = {a4.x,a4.y,a4.z,a4.w};
            float b[4] = {b4.x,b4.y,b4.z,b4.w};
            #pragma unroll
            for(int i=0;i<4;i++)
                #pragma unroll
                for(int j=0;j<4;j++) acc[i][j] = fmaf(a[i], b[j], acc[i][j]);
        }
        __syncthreads();
    }

    #pragma unroll
    for(int i=0;i<4;i++){
        int row = rowT + tyy*4 + i;
        int col = colT + txx*4;
        float4 o;
        o.x = acc[i][0]; o.y = acc[i][1]; o.z = acc[i][2]; o.w = acc[i][3];
        if(BIAS){
            o.x += bias[col+0]; o.y += bias[col+1];
            o.z += bias[col+2]; o.w += bias[col+3];
        }
        if(RES){
            const float4 r4 = *(const float4*)&R[(long)row*ldc + col];
            o.x += r4.x; o.y += r4.y; o.z += r4.z; o.w += r4.w;
        }
        *(float4*)&C[(long)row*ldc + col] = o;
    }
}

// ---------------- host side ---------------------------------------------------
static float* symaddr(const void* sym){
    void* p = nullptr;
    cudaGetSymbolAddress(&p, sym);
    return (float*)p;
}

extern "C" void kernel_launch(void* const* d_in, const int* in_sizes, int n_in,
                              void* d_out, int out_size){
    const float* x1       = (const float*)d_in[0];
    const float* x2       = (const float*)d_in[1];
    const float* ln1_g    = (const float*)d_in[2];
    const float* ln1_b    = (const float*)d_in[3];
    const float* ca_qkv_w = (const float*)d_in[4];
    const float* ca_temp  = (const float*)d_in[5];
    const float* ca_proj_w= (const float*)d_in[6];
    const float* ca_proj_b= (const float*)d_in[7];
    const float* ln3_g    = (const float*)d_in[8];
    const float* ln3_b    = (const float*)d_in[9];
    const float* rp_w     = (const float*)d_in[10];
    const float* rp_b     = (const float*)d_in[11];
    const float* cn_g     = (const float*)d_in[12];
    const float* cn_b     = (const float*)d_in[13];
    const float* ln2_g    = (const float*)d_in[14];
    const float* ln2_b    = (const float*)d_in[15];
    const float* fc1_w    = (const float*)d_in[16];
    const float* fc1_b    = (const float*)d_in[17];
    const float* dw_w     = (const float*)d_in[18];
    const float* dw_b     = (const float*)d_in[19];
    const float* fc2_w    = (const float*)d_in[20];
    const float* fc2_b    = (const float*)d_in[21];
    float* out = (float*)d_out;

    float* p_ln     = symaddr(g_ln);
    float* p_qkv    = symaddr(g_qkv);
    float* p_qn     = symaddr(g_qn);
    float* p_kn     = symaddr(g_kn);
    float* p_attn   = symaddr(g_attn);
    float* p_attnout= symaddr(g_attnout);
    float* p_ch1    = symaddr(g_ch1);
    float* p_ch2    = symaddr(g_ch2);
    float* p_n1     = symaddr(g_n1);
    float* p_n2     = symaddr(g_n2);
    float* p_key    = symaddr(g_key);
    float* p_query  = symaddr(g_query);
    float* p_ctx    = symaddr(g_ctx);
    float* p_att2   = symaddr(g_att2);
    float* p_rep    = symaddr(g_rep);
    float* p_crossln= symaddr(g_crossln);
    float* p_tx     = symaddr(g_tx);
    float* p_h1     = symaddr(g_h1);
    float* p_h2     = symaddr(g_h2);

    // ---- channel attention for both streams (shared weights) ----
    for(int s=0;s<2;s++){
        const float* x   = (s==0) ? x1 : x2;
        float* ch        = (s==0) ? p_ch1 : p_ch2;

        ln_kernel<<<T_TOK, 128>>>(x, ln1_g, ln1_b, p_ln, DD);

        // qkv: [T,384] @ [384,1152]
        sgemm_kernel<false,false,false><<<dim3(1152/64, T_TOK/64, 1), 256>>>(
            p_ln, ca_qkv_w, nullptr, nullptr, p_qkv,
            T_TOK, 1152, DD, DD, 1152, 1152, 0, 0, 0);

        l2norm_qk_kernel<<<2*BB*HEADS*HD, 256>>>(p_qkv, p_qn, p_kn);
        qk_kernel<<<BB*HEADS, 256>>>(p_qn, p_kn, p_attn);
        softmax_attn_kernel<<<BB*HEADS*HD, 64>>>(p_attn, ca_temp);
        pv_kernel<<<BB*HEADS, 256>>>(p_attn, p_qkv, p_attnout);

        // proj + bias + residual x
        sgemm_kernel<false,true,true><<<dim3(DD/64, T_TOK/64, 1), 256>>>(
            p_attnout, ca_proj_w, ca_proj_b, x, ch,
            T_TOK, DD, DD, DD, DD, DD, 0, 0, 0);
    }

    // ---- ln3 ----
    ln_kernel<<<T_TOK, 128>>>(p_ch1, ln3_g, ln3_b, p_n1, DD);
    ln_kernel<<<T_TOK, 128>>>(p_ch2, ln3_g, ln3_b, p_n2, DD);

    // ---- cross attention ----
    colsoftmax_kernel<<<BB*DD, 256>>>(p_n2, p_key);      // softmax over tokens
    rowsoftmax_kernel<<<T_TOK, 128>>>(p_n2, p_query);    // softmax over channels

    // context[b] = key[b] (D x N) @ n1[b] (N x D)
    sgemm_kernel<false,false,false><<<dim3(DD/64, DD/64, BB), 256>>>(
        p_key, p_n1, nullptr, nullptr, p_ctx,
        DD, DD, NN_TOK, NN_TOK, DD, DD,
        (long long)DD*NN_TOK, (long long)NN_TOK*DD, (long long)DD*DD);

    // attended[b] = query[b] (N x D) @ context[b] (D x D)
    sgemm_kernel<false,false,false><<<dim3(DD/64, NN_TOK/64, BB), 256>>>(
        p_query, p_ctx, nullptr, nullptr, p_att2,
        NN_TOK, DD, DD, DD, DD, DD,
        (long long)NN_TOK*DD, (long long)DD*DD, (long long)NN_TOK*DD);

    // rep = attended (T x 384) @ rp_w^T (384 x 768) + rp_b
    sgemm_kernel<true,true,false><<<dim3(C2/64, T_TOK/64, 1), 256>>>(
        p_att2, rp_w, rp_b, nullptr, p_rep,
        T_TOK, C2, DD, DD, DD, C2, 0, 0, 0);

    ln_kernel<<<T_TOK, 128>>>(p_rep, cn_g, cn_b, p_crossln, C2);

    // ---- tx = concat + cross ----
    tx_add_kernel<<<(T_TOK*C2)/256, 256>>>(p_ch1, p_ch2, p_crossln, p_tx);

    // ---- MixFFN ----
    ln_kernel<<<T_TOK, 128>>>(p_tx, ln2_g, ln2_b, p_ln, C2);

    sgemm_kernel<false,true,false><<<dim3(C4/64, T_TOK/64, 1), 256>>>(
        p_ln, fc1_w, fc1_b, nullptr, p_h1,
        T_TOK, C4, C2, C2, C4, C4, 0, 0, 0);

    dwconv_gelu_kernel<<<dim3(C4/256, NN_TOK, BB), 256>>>(p_h1, dw_w, dw_b, p_h2);

    sgemm_kernel<false,true,true><<<dim3(C2/64, T_TOK/64, 1), 256>>>(
        p_h2, fc2_w, fc2_b, p_tx, out,
        T_TOK, C2, C4, C4, C2, C2, 0, 0, 0);
}

// round 2
// speedup vs baseline: 2.6006x; 2.6006x over previous
#include <cuda_runtime.h>
#include <cuda_bf16.h>
#include <math.h>

// Problem constants
#define BB 16
#define NN_TOK 1024
#define DD 384
#define C2 768
#define C4 1536
#define HEADS 8
#define HD 48
#define T_TOK (BB*NN_TOK)   // 16384

// ---------------- scratch (device globals; no allocation allowed) -------------
__device__ float g_ln[(size_t)T_TOK*C2];
__device__ float g_qkv[(size_t)T_TOK*1152];
__device__ float g_qn[(size_t)BB*HEADS*HD*NN_TOK];
__device__ float g_kn[(size_t)BB*HEADS*HD*NN_TOK];
__device__ float g_attn[(size_t)BB*HEADS*HD*HD];
__device__ float g_attnout[(size_t)T_TOK*DD];
__device__ float g_ch1[(size_t)T_TOK*DD];
__device__ float g_ch2[(size_t)T_TOK*DD];
__device__ float g_n1[(size_t)T_TOK*DD];
__device__ float g_n2[(size_t)T_TOK*DD];
__device__ float g_key[(size_t)BB*DD*NN_TOK];     // [B,D,N]
__device__ float g_query[(size_t)T_TOK*DD];       // token-major
__device__ float g_ctx[(size_t)BB*DD*DD];
__device__ float g_att2[(size_t)T_TOK*DD];
__device__ float g_rep[(size_t)T_TOK*C2];
__device__ float g_crossln[(size_t)T_TOK*C2];
__device__ float g_tx[(size_t)T_TOK*C2];
__device__ float g_h1[(size_t)T_TOK*C4];
__device__ float g_h2[(size_t)T_TOK*C4];

// ---------------- reductions -------------------------------------------------
__device__ __forceinline__ float warpSum(float v){
    #pragma unroll
    for(int o=16;o>0;o>>=1) v += __shfl_down_sync(0xffffffffu, v, o);
    return v;
}
__device__ __forceinline__ float warpMax(float v){
    #pragma unroll
    for(int o=16;o>0;o>>=1) v = fmaxf(v, __shfl_down_sync(0xffffffffu, v, o));
    return v;
}
__device__ __forceinline__ float blockSum(float v, float* sh){
    int lane = threadIdx.x & 31, wid = threadIdx.x >> 5;
    v = warpSum(v);
    if(lane==0) sh[wid]=v;
    __syncthreads();
    int nw = blockDim.x >> 5;
    float r = (threadIdx.x < (unsigned)nw) ? sh[threadIdx.x] : 0.f;
    if(wid==0){ r = warpSum(r); if(lane==0) sh[0]=r; }
    __syncthreads();
    r = sh[0];
    __syncthreads();
    return r;
}
__device__ __forceinline__ float blockMax(float v, float* sh){
    int lane = threadIdx.x & 31, wid = threadIdx.x >> 5;
    v = warpMax(v);
    if(lane==0) sh[wid]=v;
    __syncthreads();
    int nw = blockDim.x >> 5;
    float r = (threadIdx.x < (unsigned)nw) ? sh[threadIdx.x] : -INFINITY;
    if(wid==0){ r = warpMax(r); if(lane==0) sh[0]=r; }
    __syncthreads();
    r = sh[0];
    __syncthreads();
    return r;
}

// ---------------- tf32 helpers ------------------------------------------------
__device__ __forceinline__ float to_tf32(float x){
    unsigned u;
    asm("cvt.rna.tf32.f32 %0, %1;" : "=r"(u) : "f"(x));
    return __uint_as_float(u);
}
__device__ __forceinline__ void mma_tf32(float* c, const float* a, const float* b){
    asm volatile(
        "mma.sync.aligned.m16n8k8.row.col.f32.tf32.tf32.f32 "
        "{%0,%1,%2,%3}, {%4,%5,%6,%7}, {%8,%9}, {%0,%1,%2,%3};\n"
        : "+f"(c[0]), "+f"(c[1]), "+f"(c[2]), "+f"(c[3])
        : "r"(__float_as_uint(a[0])), "r"(__float_as_uint(a[1])),
          "r"(__float_as_uint(a[2])), "r"(__float_as_uint(a[3])),
          "r"(__float_as_uint(b[0])), "r"(__float_as_uint(b[1])));
}

// ---------------- LayerNorm (W = 384 or 768; block=128) ----------------------
__global__ void ln_kernel(const float* __restrict__ x, const float* __restrict__ g,
                          const float* __restrict__ b, float* __restrict__ y, int W){
    long row = blockIdx.x;
    const float* xr = x + row*(long)W;
    int vpt = W >> 7;
    float v[6];
    float s=0.f, s2=0.f;
    for(int i=0;i<vpt;i++){
        float t = xr[i*128 + threadIdx.x];
        v[i]=t; s+=t; s2+=t*t;
    }
    __shared__ float sh[32];
    s  = blockSum(s, sh);
    s2 = blockSum(s2, sh);
    float mu = s / (float)W;
    float var = s2 / (float)W - mu*mu;
    float rstd = rsqrtf(var + 1e-5f);
    float* yr = y + row*(long)W;
    for(int i=0;i<vpt;i++){
        int c = i*128 + threadIdx.x;
        yr[c] = (v[i]-mu)*rstd*g[c] + b[c];
    }
}

// ---------------- L2-norm over tokens + transpose to [B,h,d,N] ---------------
__global__ void l2norm_qk_kernel(const float* __restrict__ qkv,
                                 float* __restrict__ qn, float* __restrict__ kn){
    int idx = blockIdx.x;
    int which = idx / (BB*HEADS*HD);     // 0 = q, 1 = k
    int r = idx % (BB*HEADS*HD);
    int b = r / (HEADS*HD);
    int hj = r % (HEADS*HD);
    int col = which*DD + hj;
    const float* base = qkv + (long)b*NN_TOK*1152 + col;
    float v[4]; float s=0.f;
    #pragma unroll
    for(int i=0;i<4;i++){
        int n = threadIdx.x + i*256;
        float t = base[(long)n*1152];
        v[i]=t; s+=t*t;
    }
    __shared__ float sh[32];
    s = blockSum(s, sh);
    float nrm = sqrtf(s);
    float scale = 1.0f / fmaxf(nrm, 1e-12f);
    float* out = (which==0 ? qn : kn) + ((long)b*(HEADS*HD) + hj)*NN_TOK;
    #pragma unroll
    for(int i=0;i<4;i++){
        int n = threadIdx.x + i*256;
        out[n] = v[i]*scale;
    }
}

// ---------------- attn logits: split-K over token chunks, atomic accumulate --
// grid = (8, B*H), block = 256. Each block: 48x48 partial over 128 tokens.
__global__ __launch_bounds__(256) void qk_kernel(const float* __restrict__ qn,
                                                 const float* __restrict__ kn,
                                                 float* __restrict__ attn){
    int bh = blockIdx.y;
    int n0 = blockIdx.x * 128;
    const float* q = qn + (long)bh*HD*NN_TOK;
    const float* k = kn + (long)bh*HD*NN_TOK;
    __shared__ float qs[48*128];
    __shared__ float ks[48*128];
    int tid = threadIdx.x;
    #pragma unroll
    for(int i=0;i<24;i++){
        int e = tid + i*256;
        int rr = e>>7, cc = e&127;
        qs[e] = q[rr*NN_TOK + n0 + cc];
        ks[e] = k[rr*NN_TOK + n0 + cc];
    }
    __syncthreads();
    int tx = tid & 15, ty = tid >> 4;
    float acc[3][3];
    #pragma unroll
    for(int r=0;r<3;r++)
        #pragma unroll
        for(int c=0;c<3;c++) acc[r][c]=0.f;
    #pragma unroll 4
    for(int kk=0;kk<128;kk++){
        float qv[3], kv[3];
        #pragma unroll
        for(int r=0;r<3;r++) qv[r] = qs[(ty*3+r)*128 + kk];
        #pragma unroll
        for(int c=0;c<3;c++) kv[c] = ks[(tx*3+c)*128 + kk];
        #pragma unroll
        for(int r=0;r<3;r++)
            #pragma unroll
            for(int c=0;c<3;c++) acc[r][c] = fmaf(qv[r], kv[c], acc[r][c]);
    }
    float* ab = attn + (long)bh*2304;
    #pragma unroll
    for(int r=0;r<3;r++)
        #pragma unroll
        for(int c=0;c<3;c++)
            atomicAdd(&ab[(ty*3+r)*48 + tx*3+c], acc[r][c]);
}

// ---------------- softmax over last-48 with temp ------------------------------
__global__ void softmax_attn_kernel(float* __restrict__ attn, const float* __restrict__ temp){
    int row = blockIdx.x;
    int h = (row / HD) & (HEADS-1);
    float t = temp[h];
    float* a = attn + (long)row*HD;
    int tid = threadIdx.x;
    float v = (tid<HD) ? a[tid]*t : -INFINITY;
    __shared__ float sh[32];
    float m = blockMax(v, sh);
    float e = (tid<HD) ? expf(v - m) : 0.f;
    float s = blockSum(e, sh);
    if(tid<HD) a[tid] = e / s;
}

// ---------------- attn @ v, chunked over tokens ------------------------------
// grid = (16, B*H) chunks of 64 tokens, block = 256
__global__ __launch_bounds__(256) void pv_kernel(const float* __restrict__ attn,
                                                 const float* __restrict__ qkv,
                                                 float* __restrict__ out){
    int bh = blockIdx.y;
    int n0 = blockIdx.x * 64;
    int b = bh >> 3, h = bh & 7;
    __shared__ float as[48*52];
    __shared__ float vs[64*52];
    int tid = threadIdx.x;
    for(int i=tid;i<2304;i+=256){
        int r = i/48, c = i%48;
        as[r*52+c] = attn[(long)bh*2304 + i];
    }
    const float* vbase = qkv + (long)b*NN_TOK*1152 + 2*DD + h*HD;
    #pragma unroll
    for(int i=0;i<12;i++){
        int e = tid + i*256;
        int nn = e/48, j = e%48;
        vs[nn*52+j] = vbase[(long)(n0+nn)*1152 + j];
    }
    __syncthreads();
    int tx = tid & 15;   // i-block (output channel within head)
    int ty = tid >> 4;   // n-block (token)
    float acc[4][3];
    #pragma unroll
    for(int s=0;s<4;s++)
        #pragma unroll
        for(int r=0;r<3;r++) acc[s][r]=0.f;
    #pragma unroll 4
    for(int j=0;j<48;j++){
        float av[3], vv[4];
        #pragma unroll
        for(int r=0;r<3;r++) av[r] = as[(tx*3+r)*52 + j];
        #pragma unroll
        for(int s=0;s<4;s++) vv[s] = vs[(ty*4+s)*52 + j];
        #pragma unroll
        for(int s=0;s<4;s++)
            #pragma unroll
            for(int r=0;r<3;r++) acc[s][r] = fmaf(av[r], vv[s], acc[s][r]);
    }
    #pragma unroll
    for(int s=0;s<4;s++)
        #pragma unroll
        for(int r=0;r<3;r++)
            out[((long)b*NN_TOK + n0 + ty*4+s)*DD + h*HD + tx*3 + r] = acc[s][r];
}

// ---------------- column softmax (over tokens) -> key [B,D,N] ----------------
__global__ void colsoftmax_kernel(const float* __restrict__ x, float* __restrict__ key){
    int idx = blockIdx.x;
    int b = idx / DD, d = idx % DD;
    const float* base = x + (long)b*NN_TOK*DD + d;
    float v[4]; float m = -INFINITY;
    #pragma unroll
    for(int i=0;i<4;i++){
        int n = threadIdx.x + i*256;
        float t = base[(long)n*DD];
        v[i]=t; m = fmaxf(m,t);
    }
    __shared__ float sh[32];
    m = blockMax(m, sh);
    float s = 0.f;
    #pragma unroll
    for(int i=0;i<4;i++){ v[i] = expf(v[i]-m); s += v[i]; }
    s = blockSum(s, sh);
    float inv = 1.0f / s;
    float* out = key + ((long)b*DD + d)*NN_TOK;
    #pragma unroll
    for(int i=0;i<4;i++) out[threadIdx.x + i*256] = v[i]*inv;
}

// ---------------- row softmax (over channels, 384) -> query token-major ------
__global__ void rowsoftmax_kernel(const float* __restrict__ x, float* __restrict__ y){
    long row = blockIdx.x;
    const float* xr = x + row*DD;
    float v[3]; float m = -INFINITY;
    #pragma unroll
    for(int i=0;i<3;i++){
        float t = xr[i*128 + threadIdx.x];
        v[i]=t; m=fmaxf(m,t);
    }
    __shared__ float sh[32];
    m = blockMax(m, sh);
    float s=0.f;
    #pragma unroll
    for(int i=0;i<3;i++){ v[i]=expf(v[i]-m); s+=v[i]; }
    s = blockSum(s, sh);
    float inv = 1.0f/s;
    float* yr = y + row*DD;
    #pragma unroll
    for(int i=0;i<3;i++) yr[i*128 + threadIdx.x] = v[i]*inv;
}

// ---------------- tx = concat(ch1,ch2) + cross --------------------------------
__global__ void tx_add_kernel(const float* __restrict__ ch1, const float* __restrict__ ch2,
                              const float* __restrict__ cl, float* __restrict__ tx){
    long i = (long)blockIdx.x*blockDim.x + threadIdx.x;
    long t = i / C2; int f = (int)(i % C2);
    float base = (f < DD) ? ch1[t*DD + f] : ch2[t*DD + f - DD];
    tx[i] = base + cl[i];
}

// ---------------- depthwise 3x3 + exact GELU ----------------------------------
__global__ void dwconv_gelu_kernel(const float* __restrict__ h1, const float* __restrict__ w,
                                   const float* __restrict__ bias, float* __restrict__ h2){
    int c = blockIdx.x*blockDim.x + threadIdx.x;
    int n = blockIdx.y, b = blockIdx.z;
    int y = n >> 5, x = n & 31;
    float acc = bias[c];
    const float* wc = w + c*9;
    const float* base = h1 + (long)b*NN_TOK*C4 + c;
    #pragma unroll
    for(int ky=0;ky<3;ky++){
        int yy = y + ky - 1;
        if(yy < 0 || yy > 31) continue;
        #pragma unroll
        for(int kx=0;kx<3;kx++){
            int xx = x + kx - 1;
            if(xx < 0 || xx > 31) continue;
            acc = fmaf(base[(long)(yy*32+xx)*C4], wc[ky*3+kx], acc);
        }
    }
    float g = 0.5f*acc*(1.f + erff(acc*0.70710678118654752f));
    h2[((long)b*NN_TOK + n)*C4 + c] = g;
}

// ---------------- tf32 tensor-core GEMM: C = A@B (+bias)(+res), optional B^T --
// 128x128x32 block tile, 256 threads (8 warps, 4x2), warp tile 32x64.
// Requires M%128==0, N%128==0, K%32==0.
template<bool TB, bool BIAS, bool RES>
__global__ __launch_bounds__(256,2)
void mma_gemm_kernel(const float* __restrict__ A, const float* __restrict__ Bm,
                     const float* __restrict__ bias, const float* __restrict__ res,
                     float* __restrict__ C,
                     int M, int N, int K, int lda, int ldb, int ldc,
                     long long sA, long long sB, long long sC){
    int bz = blockIdx.z;
    A  += (long long)bz*sA;
    Bm += (long long)bz*sB;
    C  += (long long)bz*sC;
    const float* R = RES ? res + (long long)bz*sC : nullptr;

    const int rowT = blockIdx.y*128, colT = blockIdx.x*128;
    __shared__ float As[128*36];   // [row][k], stride 36 (conflict-free frag loads)
    __shared__ float Bs[32*136];   // [k][n],  stride 136

    const int tid = threadIdx.x;
    const int warp = tid >> 5, lane = tid & 31;
    const int grp = lane >> 2, tg = lane & 3;
    const int warpRow = (warp & 3) * 32;
    const int warpCol = (warp >> 2) * 64;

    float acc[2][8][4];
    #pragma unroll
    for(int mi=0;mi<2;mi++)
        #pragma unroll
        for(int ni=0;ni<8;ni++)
            #pragma unroll
            for(int t=0;t<4;t++) acc[mi][ni][t]=0.f;

    for(int k0=0;k0<K;k0+=32){
        // stage A tile (128x32) with tf32 rounding
        #pragma unroll
        for(int i=0;i<4;i++){
            int idx = tid + i*256;
            int r = idx >> 3, c4 = (idx & 7) * 4;
            const float4 v = *(const float4*)&A[(long)(rowT+r)*lda + k0 + c4];
            As[r*36 + c4+0] = to_tf32(v.x);
            As[r*36 + c4+1] = to_tf32(v.y);
            As[r*36 + c4+2] = to_tf32(v.z);
            As[r*36 + c4+3] = to_tf32(v.w);
        }
        // stage B tile (32x128)
        if(!TB){
            #pragma unroll
            for(int i=0;i<4;i++){
                int idx = tid + i*256;
                int r = idx >> 5, c4 = (idx & 31) * 4;
                const float4 v = *(const float4*)&Bm[(long)(k0+r)*ldb + colT + c4];
                Bs[r*136 + c4+0] = to_tf32(v.x);
                Bs[r*136 + c4+1] = to_tf32(v.y);
                Bs[r*136 + c4+2] = to_tf32(v.z);
                Bs[r*136 + c4+3] = to_tf32(v.w);
            }
        }else{
            #pragma unroll
            for(int i=0;i<4;i++){
                int idx = tid + i*256;
                int n = idx >> 3, k4 = (idx & 7) * 4;
                const float4 v = *(const float4*)&Bm[(long)(colT+n)*ldb + k0 + k4];
                Bs[(k4+0)*136 + n] = to_tf32(v.x);
                Bs[(k4+1)*136 + n] = to_tf32(v.y);
                Bs[(k4+2)*136 + n] = to_tf32(v.z);
                Bs[(k4+3)*136 + n] = to_tf32(v.w);
            }
        }
        __syncthreads();
        #pragma unroll
        for(int kk=0;kk<4;kk++){
            float a[2][4], b[8][2];
            #pragma unroll
            for(int mi=0;mi<2;mi++){
                int rb = warpRow + mi*16 + grp;
                a[mi][0] = As[rb*36 + kk*8 + tg];
                a[mi][1] = As[(rb+8)*36 + kk*8 + tg];
                a[mi][2] = As[rb*36 + kk*8 + tg + 4];
                a[mi][3] = As[(rb+8)*36 + kk*8 + tg + 4];
            }
            #pragma unroll
            for(int ni=0;ni<8;ni++){
                int cb = warpCol + ni*8 + grp;
                b[ni][0] = Bs[(kk*8 + tg)*136 + cb];
                b[ni][1] = Bs[(kk*8 + tg + 4)*136 + cb];
            }
            #pragma unroll
            for(int mi=0;mi<2;mi++)
                #pragma unroll
                for(int ni=0;ni<8;ni++)
                    mma_tf32(acc[mi][ni], a[mi], b[ni]);
        }
        __syncthreads();
    }

    // epilogue
    #pragma unroll
    for(int mi=0;mi<2;mi++){
        #pragma unroll
        for(int ni=0;ni<8;ni++){
            int r0 = rowT + warpRow + mi*16 + grp;
            int col = colT + warpCol + ni*8 + tg*2;
            float2 o0, o1;
            o0.x = acc[mi][ni][0]; o0.y = acc[mi][ni][1];
            o1.x = acc[mi][ni][2]; o1.y = acc[mi][ni][3];
            if(BIAS){
                float b0 = bias[col], b1 = bias[col+1];
                o0.x += b0; o0.y += b1;
                o1.x += b0; o1.y += b1;
            }
            if(RES){
                const float2 r0v = *(const float2*)&R[(long)r0*ldc + col];
                const float2 r1v = *(const float2*)&R[(long)(r0+8)*ldc + col];
                o0.x += r0v.x; o0.y += r0v.y;
                o1.x += r1v.x; o1.y += r1v.y;
            }
            *(float2*)&C[(long)r0*ldc + col] = o0;
            *(float2*)&C[(long)(r0+8)*ldc + col] = o1;
        }
    }
}

// ---------------- host side ---------------------------------------------------
static float* symaddr(const void* sym){
    void* p = nullptr;
    cudaGetSymbolAddress(&p, sym);
    return (float*)p;
}

extern "C" void kernel_launch(void* const* d_in, const int* in_sizes, int n_in,
                              void* d_out, int out_size){
    const float* x1       = (const float*)d_in[0];
    const float* x2       = (const float*)d_in[1];
    const float* ln1_g    = (const float*)d_in[2];
    const float* ln1_b    = (const float*)d_in[3];
    const float* ca_qkv_w = (const float*)d_in[4];
    const float* ca_temp  = (const float*)d_in[5];
    const float* ca_proj_w= (const float*)d_in[6];
    const float* ca_proj_b= (const float*)d_in[7];
    const float* ln3_g    = (const float*)d_in[8];
    const float* ln3_b    = (const float*)d_in[9];
    const float* rp_w     = (const float*)d_in[10];
    const float* rp_b     = (const float*)d_in[11];
    const float* cn_g     = (const float*)d_in[12];
    const float* cn_b     = (const float*)d_in[13];
    const float* ln2_g    = (const float*)d_in[14];
    const float* ln2_b    = (const float*)d_in[15];
    const float* fc1_w    = (const float*)d_in[16];
    const float* fc1_b    = (const float*)d_in[17];
    const float* dw_w     = (const float*)d_in[18];
    const float* dw_b     = (const float*)d_in[19];
    const float* fc2_w    = (const float*)d_in[20];
    const float* fc2_b    = (const float*)d_in[21];
    float* out = (float*)d_out;

    float* p_ln     = symaddr(g_ln);
    float* p_qkv    = symaddr(g_qkv);
    float* p_qn     = symaddr(g_qn);
    float* p_kn     = symaddr(g_kn);
    float* p_attn   = symaddr(g_attn);
    float* p_attnout= symaddr(g_attnout);
    float* p_ch1    = symaddr(g_ch1);
    float* p_ch2    = symaddr(g_ch2);
    float* p_n1     = symaddr(g_n1);
    float* p_n2     = symaddr(g_n2);
    float* p_key    = symaddr(g_key);
    float* p_query  = symaddr(g_query);
    float* p_ctx    = symaddr(g_ctx);
    float* p_att2   = symaddr(g_att2);
    float* p_rep    = symaddr(g_rep);
    float* p_crossln= symaddr(g_crossln);
    float* p_tx     = symaddr(g_tx);
    float* p_h1     = symaddr(g_h1);
    float* p_h2     = symaddr(g_h2);

    // ---- channel attention for both streams (shared weights) ----
    for(int s=0;s<2;s++){
        const float* x   = (s==0) ? x1 : x2;
        float* ch        = (s==0) ? p_ch1 : p_ch2;

        ln_kernel<<<T_TOK, 128>>>(x, ln1_g, ln1_b, p_ln, DD);

        // qkv: [T,384] @ [384,1152]
        mma_gemm_kernel<false,false,false><<<dim3(1152/128, T_TOK/128, 1), 256>>>(
            p_ln, ca_qkv_w, nullptr, nullptr, p_qkv,
            T_TOK, 1152, DD, DD, 1152, 1152, 0, 0, 0);

        l2norm_qk_kernel<<<2*BB*HEADS*HD, 256>>>(p_qkv, p_qn, p_kn);
        cudaMemsetAsync(p_attn, 0, (size_t)BB*HEADS*HD*HD*sizeof(float));
        qk_kernel<<<dim3(8, BB*HEADS), 256>>>(p_qn, p_kn, p_attn);
        softmax_attn_kernel<<<BB*HEADS*HD, 64>>>(p_attn, ca_temp);
        pv_kernel<<<dim3(16, BB*HEADS), 256>>>(p_attn, p_qkv, p_attnout);

        // proj + bias + residual x
        mma_gemm_kernel<false,true,true><<<dim3(DD/128, T_TOK/128, 1), 256>>>(
            p_attnout, ca_proj_w, ca_proj_b, x, ch,
            T_TOK, DD, DD, DD, DD, DD, 0, 0, 0);
    }

    // ---- ln3 ----
    ln_kernel<<<T_TOK, 128>>>(p_ch1, ln3_g, ln3_b, p_n1, DD);
    ln_kernel<<<T_TOK, 128>>>(p_ch2, ln3_g, ln3_b, p_n2, DD);

    // ---- cross attention ----
    colsoftmax_kernel<<<BB*DD, 256>>>(p_n2, p_key);      // softmax over tokens
    rowsoftmax_kernel<<<T_TOK, 128>>>(p_n2, p_query);    // softmax over channels

    // context[b] = key[b] (D x N) @ n1[b] (N x D)
    mma_gemm_kernel<false,false,false><<<dim3(DD/128, DD/128, BB), 256>>>(
        p_key, p_n1, nullptr, nullptr, p_ctx,
        DD, DD, NN_TOK, NN_TOK, DD, DD,
        (long long)DD*NN_TOK, (long long)NN_TOK*DD, (long long)DD*DD);

    // attended[b] = query[b] (N x D) @ context[b] (D x D)
    mma_gemm_kernel<false,false,false><<<dim3(DD/128, NN_TOK/128, BB), 256>>>(
        p_query, p_ctx, nullptr, nullptr, p_att2,
        NN_TOK, DD, DD, DD, DD, DD,
        (long long)NN_TOK*DD, (long long)DD*DD, (long long)NN_TOK*DD);

    // rep = attended (T x 384) @ rp_w^T (384 x 768) + rp_b
    mma_gemm_kernel<true,true,false><<<dim3(C2/128, T_TOK/128, 1), 256>>>(
        p_att2, rp_w, rp_b, nullptr, p_rep,
        T_TOK, C2, DD, DD, DD, C2, 0, 0, 0);

    ln_kernel<<<T_TOK, 128>>>(p_rep, cn_g, cn_b, p_crossln, C2);

    // ---- tx = concat + cross ----
    tx_add_kernel<<<(T_TOK*C2)/256, 256>>>(p_ch1, p_ch2, p_crossln, p_tx);

    // ---- MixFFN ----
    ln_kernel<<<T_TOK, 128>>>(p_tx, ln2_g, ln2_b, p_ln, C2);

    mma_gemm_kernel<false,true,false><<<dim3(C4/128, T_TOK/128, 1), 256>>>(
        p_ln, fc1_w, fc1_b, nullptr, p_h1,
        T_TOK, C4, C2, C2, C4, C4, 0, 0, 0);

    dwconv_gelu_kernel<<<dim3(C4/256, NN_TOK, BB), 256>>>(p_h1, dw_w, dw_b, p_h2);

    mma_gemm_kernel<false,true,true><<<dim3(C2/128, T_TOK/128, 1), 256>>>(
        p_h2, fc2_w, fc2_b, p_tx, out,
        T_TOK, C2, C4, C4, C2, C2, 0, 0, 0);
}

// round 5
// speedup vs baseline: 2.9459x; 1.1328x over previous
#include <cuda_runtime.h>
#include <cuda_bf16.h>
#include <math.h>
#include <stdint.h>

// Problem constants
#define BB 16
#define NN_TOK 1024
#define DD 384
#define C2 768
#define C4 1536
#define HEADS 8
#define HD 48
#define T_TOK (BB*NN_TOK)   // 16384

// ---------------- scratch (device globals; no allocation allowed) -------------
__device__ float g_ln[(size_t)T_TOK*C2];
__device__ float g_qkv[(size_t)T_TOK*1152];
__device__ float g_qn[(size_t)BB*HEADS*HD*NN_TOK];
__device__ float g_kn[(size_t)BB*HEADS*HD*NN_TOK];
__device__ float g_attnp[(size_t)8*BB*HEADS*HD*HD];   // 8 split-K partials
__device__ float g_attn[(size_t)BB*HEADS*HD*HD];
__device__ float g_attnout[(size_t)T_TOK*DD];
__device__ float g_ch1[(size_t)T_TOK*DD];
__device__ float g_ch2[(size_t)T_TOK*DD];
__device__ float g_n1[(size_t)T_TOK*DD];
__device__ float g_n2[(size_t)T_TOK*DD];
__device__ float g_key[(size_t)BB*DD*NN_TOK];     // [B,D,N]
__device__ float g_query[(size_t)T_TOK*DD];       // token-major
__device__ float g_ctx[(size_t)BB*DD*DD];
__device__ float g_att2[(size_t)T_TOK*DD];
__device__ float g_rep[(size_t)T_TOK*C2];
__device__ float g_crossln[(size_t)T_TOK*C2];
__device__ float g_tx[(size_t)T_TOK*C2];
__device__ float g_h1[(size_t)T_TOK*C4];
__device__ float g_h2[(size_t)T_TOK*C4];
// pre-rounded / pre-transposed weights
__device__ float g_wqkv[(size_t)DD*1152];
__device__ float g_wproj[(size_t)DD*DD];
__device__ float g_wrpT[(size_t)DD*C2];     // transposed rp_w
__device__ float g_wfc1[(size_t)C2*C4];
__device__ float g_wfc2[(size_t)C4*C2];

// ---------------- reductions -------------------------------------------------
__device__ __forceinline__ float warpSum(float v){
    #pragma unroll
    for(int o=16;o>0;o>>=1) v += __shfl_down_sync(0xffffffffu, v, o);
    return v;
}
__device__ __forceinline__ float warpMax(float v){
    #pragma unroll
    for(int o=16;o>0;o>>=1) v = fmaxf(v, __shfl_down_sync(0xffffffffu, v, o));
    return v;
}
__device__ __forceinline__ float blockSum(float v, float* sh){
    int lane = threadIdx.x & 31, wid = threadIdx.x >> 5;
    v = warpSum(v);
    if(lane==0) sh[wid]=v;
    __syncthreads();
    int nw = blockDim.x >> 5;
    float r = (threadIdx.x < (unsigned)nw) ? sh[threadIdx.x] : 0.f;
    if(wid==0){ r = warpSum(r); if(lane==0) sh[0]=r; }
    __syncthreads();
    r = sh[0];
    __syncthreads();
    return r;
}
__device__ __forceinline__ float blockMax(float v, float* sh){
    int lane = threadIdx.x & 31, wid = threadIdx.x >> 5;
    v = warpMax(v);
    if(lane==0) sh[wid]=v;
    __syncthreads();
    int nw = blockDim.x >> 5;
    float r = (threadIdx.x < (unsigned)nw) ? sh[threadIdx.x] : -INFINITY;
    if(wid==0){ r = warpMax(r); if(lane==0) sh[0]=r; }
    __syncthreads();
    r = sh[0];
    __syncthreads();
    return r;
}

// ---------------- tf32 helpers ------------------------------------------------
__device__ __forceinline__ float to_tf32(float x){
    unsigned u;
    asm("cvt.rna.tf32.f32 %0, %1;" : "=r"(u) : "f"(x));
    return __uint_as_float(u);
}
__device__ __forceinline__ void mma_tf32(float* c, const float* a, const float* b){
    asm volatile(
        "mma.sync.aligned.m16n8k8.row.col.f32.tf32.tf32.f32 "
        "{%0,%1,%2,%3}, {%4,%5,%6,%7}, {%8,%9}, {%0,%1,%2,%3};\n"
        : "+f"(c[0]), "+f"(c[1]), "+f"(c[2]), "+f"(c[3])
        : "r"(__float_as_uint(a[0])), "r"(__float_as_uint(a[1])),
          "r"(__float_as_uint(a[2])), "r"(__float_as_uint(a[3])),
          "r"(__float_as_uint(b[0])), "r"(__float_as_uint(b[1])));
}
__device__ __forceinline__ void cp16(uint32_t s, const void* g){
    asm volatile("cp.async.cg.shared.global [%0], [%1], 16;\n" :: "r"(s), "l"(g));
}
__device__ __forceinline__ void cp_commit(){ asm volatile("cp.async.commit_group;\n"); }
__device__ __forceinline__ void cp_wait1(){ asm volatile("cp.async.wait_group 1;\n"); }
__device__ __forceinline__ void cp_wait0(){ asm volatile("cp.async.wait_group 0;\n"); }

// ---------------- weight prep: round to tf32 ----------------------------------
__global__ void round_kernel(const float* __restrict__ in, float* __restrict__ out, int n){
    int i = blockIdx.x*blockDim.x + threadIdx.x;
    if(i < n) out[i] = to_tf32(in[i]);
}
// rp_w [768][384] -> rpT [384][768], rounded
__global__ void transpose_round_kernel(const float* __restrict__ in, float* __restrict__ out){
    __shared__ float t[32][33];
    int k0 = blockIdx.x*32, n0 = blockIdx.y*32;
    int tx = threadIdx.x, ty = threadIdx.y;   // 32 x 8
    #pragma unroll
    for(int j=0;j<4;j++) t[ty+8*j][tx] = in[(n0+ty+8*j)*DD + k0+tx];
    __syncthreads();
    #pragma unroll
    for(int j=0;j<4;j++) out[(k0+ty+8*j)*C2 + n0+tx] = to_tf32(t[tx][ty+8*j]);
}

// ---------------- LayerNorm (W = 384 or 768; block=128) ----------------------
template<bool ROUND>
__global__ void ln_kernel(const float* __restrict__ x, const float* __restrict__ g,
                          const float* __restrict__ b, float* __restrict__ y, int W){
    long row = blockIdx.x;
    const float* xr = x + row*(long)W;
    int vpt = W >> 7;
    float v[6];
    float s=0.f, s2=0.f;
    for(int i=0;i<vpt;i++){
        float t = xr[i*128 + threadIdx.x];
        v[i]=t; s+=t; s2+=t*t;
    }
    __shared__ float sh[32];
    s  = blockSum(s, sh);
    s2 = blockSum(s2, sh);
    float mu = s / (float)W;
    float var = s2 / (float)W - mu*mu;
    float rstd = rsqrtf(var + 1e-5f);
    float* yr = y + row*(long)W;
    for(int i=0;i<vpt;i++){
        int c = i*128 + threadIdx.x;
        float o = (v[i]-mu)*rstd*g[c] + b[c];
        yr[c] = ROUND ? to_tf32(o) : o;
    }
}

// ---------------- L2-norm over tokens + transpose to [B,h,d,N] ---------------
__global__ void l2norm_qk_kernel(const float* __restrict__ qkv,
                                 float* __restrict__ qn, float* __restrict__ kn){
    int idx = blockIdx.x;
    int which = idx / (BB*HEADS*HD);     // 0 = q, 1 = k
    int r = idx % (BB*HEADS*HD);
    int b = r / (HEADS*HD);
    int hj = r % (HEADS*HD);
    int col = which*DD + hj;
    const float* base = qkv + (long)b*NN_TOK*1152 + col;
    float v[4]; float s=0.f;
    #pragma unroll
    for(int i=0;i<4;i++){
        int n = threadIdx.x + i*256;
        float t = base[(long)n*1152];
        v[i]=t; s+=t*t;
    }
    __shared__ float sh[32];
    s = blockSum(s, sh);
    float nrm = sqrtf(s);
    float scale = 1.0f / fmaxf(nrm, 1e-12f);
    float* out = (which==0 ? qn : kn) + ((long)b*(HEADS*HD) + hj)*NN_TOK;
    #pragma unroll
    for(int i=0;i<4;i++){
        int n = threadIdx.x + i*256;
        out[n] = v[i]*scale;
    }
}

// ---------------- attn logits: split-K partials (no atomics) ------------------
// grid = (8, B*H), block = 256. Each block: 48x48 partial over 128 tokens.
// smem stride 65 => conflict-free (3*65 mod 32 = 3, coprime with 32).
__global__ __launch_bounds__(256) void qk_kernel(const float* __restrict__ qn,
                                                 const float* __restrict__ kn,
                                                 float* __restrict__ attnp){
    int bh = blockIdx.y;
    int s = blockIdx.x;
    const float* q = qn + (long)bh*HD*NN_TOK;
    const float* k = kn + (long)bh*HD*NN_TOK;
    __shared__ float qs[48*65];
    __shared__ float ks[48*65];
    int tid = threadIdx.x;
    int tx = tid & 15, ty = tid >> 4;
    float acc[3][3];
    #pragma unroll
    for(int r=0;r<3;r++)
        #pragma unroll
        for(int c=0;c<3;c++) acc[r][c]=0.f;

    for(int sub=0; sub<2; sub++){
        int n0 = s*128 + sub*64;
        __syncthreads();
        #pragma unroll
        for(int i=0;i<12;i++){
            int e = tid + i*256;
            int rr = e>>6, cc = e&63;
            qs[rr*65+cc] = q[rr*NN_TOK + n0 + cc];
            ks[rr*65+cc] = k[rr*NN_TOK + n0 + cc];
        }
        __syncthreads();
        #pragma unroll 4
        for(int kk=0;kk<64;kk++){
            float qv[3], kv[3];
            #pragma unroll
            for(int r=0;r<3;r++) qv[r] = qs[(ty*3+r)*65 + kk];
            #pragma unroll
            for(int c=0;c<3;c++) kv[c] = ks[(tx*3+c)*65 + kk];
            #pragma unroll
            for(int r=0;r<3;r++)
                #pragma unroll
                for(int c=0;c<3;c++) acc[r][c] = fmaf(qv[r], kv[c], acc[r][c]);
        }
    }
    float* ab = attnp + ((long)s*(BB*HEADS) + bh)*2304;
    #pragma unroll
    for(int r=0;r<3;r++)
        #pragma unroll
        for(int c=0;c<3;c++)
            ab[(ty*3+r)*48 + tx*3+c] = acc[r][c];
}

// ---------------- softmax over last-48: reduce 8 partials, temp, softmax ------
__global__ void softmax_attn_kernel(const float* __restrict__ attnp,
                                    float* __restrict__ attn,
                                    const float* __restrict__ temp){
    int row = blockIdx.x;              // bh*48 + i
    int bh = row / HD;
    int h = bh & (HEADS-1);
    float t = temp[h];
    int tid = threadIdx.x;
    float v = -INFINITY;
    if(tid < HD){
        float s = 0.f;
        #pragma unroll
        for(int p=0;p<8;p++)
            s += attnp[((long)p*(BB*HEADS) + bh)*2304 + (row % HD)*48 + tid];
        v = s * t;
    }
    __shared__ float sh[32];
    float m = blockMax(v, sh);
    float e = (tid<HD) ? expf(v - m) : 0.f;
    float s = blockSum(e, sh);
    if(tid<HD) attn[(long)row*HD + tid] = e / s;
}

// ---------------- attn @ v, chunked over tokens (stride 49: conflict-free) ----
__global__ __launch_bounds__(256) void pv_kernel(const float* __restrict__ attn,
                                                 const float* __restrict__ qkv,
                                                 float* __restrict__ out){
    int bh = blockIdx.y;
    int n0 = blockIdx.x * 64;
    int b = bh >> 3, h = bh & 7;
    __shared__ float as[48*49];
    __shared__ float vs[64*49];
    int tid = threadIdx.x;
    for(int i=tid;i<2304;i+=256){
        int r = i/48, c = i%48;
        as[r*49+c] = attn[(long)bh*2304 + i];
    }
    const float* vbase = qkv + (long)b*NN_TOK*1152 + 2*DD + h*HD;
    #pragma unroll
    for(int i=0;i<12;i++){
        int e = tid + i*256;
        int nn = e/48, j = e%48;
        vs[nn*49+j] = vbase[(long)(n0+nn)*1152 + j];
    }
    __syncthreads();
    int tx = tid & 15;   // i-block (output channel within head)
    int ty = tid >> 4;   // n-block (token)
    float acc[4][3];
    #pragma unroll
    for(int s=0;s<4;s++)
        #pragma unroll
        for(int r=0;r<3;r++) acc[s][r]=0.f;
    #pragma unroll 4
    for(int j=0;j<48;j++){
        float av[3], vv[4];
        #pragma unroll
        for(int r=0;r<3;r++) av[r] = as[(tx*3+r)*49 + j];
        #pragma unroll
        for(int s=0;s<4;s++) vv[s] = vs[(ty*4+s)*49 + j];
        #pragma unroll
        for(int s=0;s<4;s++)
            #pragma unroll
            for(int r=0;r<3;r++) acc[s][r] = fmaf(av[r], vv[s], acc[s][r]);
    }
    #pragma unroll
    for(int s=0;s<4;s++)
        #pragma unroll
        for(int r=0;r<3;r++)
            out[((long)b*NN_TOK + n0 + ty*4+s)*DD + h*HD + tx*3 + r] = to_tf32(acc[s][r]);
}

// ---------------- column softmax (over tokens) -> key [B,D,N], tf32-rounded --
__global__ void colsoftmax_kernel(const float* __restrict__ x, float* __restrict__ key){
    int idx = blockIdx.x;
    int b = idx / DD, d = idx % DD;
    const float* base = x + (long)b*NN_TOK*DD + d;
    float v[4]; float m = -INFINITY;
    #pragma unroll
    for(int i=0;i<4;i++){
        int n = threadIdx.x + i*256;
        float t = base[(long)n*DD];
        v[i]=t; m = fmaxf(m,t);
    }
    __shared__ float sh[32];
    m = blockMax(m, sh);
    float s = 0.f;
    #pragma unroll
    for(int i=0;i<4;i++){ v[i] = expf(v[i]-m); s += v[i]; }
    s = blockSum(s, sh);
    float inv = 1.0f / s;
    float* out = key + ((long)b*DD + d)*NN_TOK;
    #pragma unroll
    for(int i=0;i<4;i++) out[threadIdx.x + i*256] = to_tf32(v[i]*inv);
}

// ---------------- row softmax (over channels) -> query, tf32-rounded ----------
__global__ void rowsoftmax_kernel(const float* __restrict__ x, float* __restrict__ y){
    long row = blockIdx.x;
    const float* xr = x + row*DD;
    float v[3]; float m = -INFINITY;
    #pragma unroll
    for(int i=0;i<3;i++){
        float t = xr[i*128 + threadIdx.x];
        v[i]=t; m=fmaxf(m,t);
    }
    __shared__ float sh[32];
    m = blockMax(m, sh);
    float s=0.f;
    #pragma unroll
    for(int i=0;i<3;i++){ v[i]=expf(v[i]-m); s+=v[i]; }
    s = blockSum(s, sh);
    float inv = 1.0f/s;
    float* yr = y + row*DD;
    #pragma unroll
    for(int i=0;i<3;i++) yr[i*128 + threadIdx.x] = to_tf32(v[i]*inv);
}

// ---------------- tx = concat(ch1,ch2) + cross --------------------------------
__global__ void tx_add_kernel(const float* __restrict__ ch1, const float* __restrict__ ch2,
                              const float* __restrict__ cl, float* __restrict__ tx){
    long i = (long)blockIdx.x*blockDim.x + threadIdx.x;
    long t = i / C2; int f = (int)(i % C2);
    float base = (f < DD) ? ch1[t*DD + f] : ch2[t*DD + f - DD];
    tx[i] = base + cl[i];
}

// ---------------- depthwise 3x3 + exact GELU: sliding window ------------------
// grid = (C4/256, 32, B), block = 256. Each thread: one channel, one row.
__global__ void dwconv_gelu_kernel(const float* __restrict__ h1, const float* __restrict__ w,
                                   const float* __restrict__ bias, float* __restrict__ h2){
    int c = blockIdx.x*blockDim.x + threadIdx.x;
    int y = blockIdx.y, b = blockIdx.z;
    const float* rowc = h1 + ((long)b*NN_TOK + y*32)*C4 + c;
    const float* rowm = rowc - 32*C4;
    const float* rowp = rowc + 32*C4;
    bool ym = (y > 0), yp = (y < 31);
    const float* wc = w + c*9;
    float w0=wc[0],w1=wc[1],w2=wc[2],w3=wc[3],w4=wc[4],w5=wc[5],w6=wc[6],w7=wc[7],w8=wc[8];
    float bs = bias[c];
    float* outr = h2 + ((long)b*NN_TOK + y*32)*C4 + c;

    float pt=0.f, pm=0.f, pb=0.f;                               // col x-1
    float ct = ym ? rowm[0] : 0.f;                              // col x
    float cm = rowc[0];
    float cb = yp ? rowp[0] : 0.f;
    #pragma unroll 4
    for(int x=0;x<32;x++){
        float nt=0.f, nm=0.f, nb=0.f;                           // col x+1
        if(x < 31){
            long o = (long)(x+1)*C4;
            nt = ym ? rowm[o] : 0.f;
            nm = rowc[o];
            nb = yp ? rowp[o] : 0.f;
        }
        float acc = bs;
        acc = fmaf(pt,w0,acc); acc = fmaf(ct,w1,acc); acc = fmaf(nt,w2,acc);
        acc = fmaf(pm,w3,acc); acc = fmaf(cm,w4,acc); acc = fmaf(nm,w5,acc);
        acc = fmaf(pb,w6,acc); acc = fmaf(cb,w7,acc); acc = fmaf(nb,w8,acc);
        float g = 0.5f*acc*(1.f + erff(acc*0.70710678118654752f));
        outr[(long)x*C4] = to_tf32(g);
        pt=ct; pm=cm; pb=cb; ct=nt; cm=nm; cb=nb;
    }
}

// ---------------- cp.async double-buffered tf32 GEMM (static smem <48KB) ------
// C = A@B (+bias)(+res)(tf32-round out). Inputs must be pre-rounded to tf32.
// 128x128 tile, K-chunk 16, 2 stages. 256 threads, warp tile 32x64.
// M%128==0, N%128==0, K%16==0.
#define AST 20
#define BST 132
#define A_STAGE (128*AST)
#define B_STAGE (16*BST)

template<bool BIAS, bool RES, bool ROUND>
__global__ __launch_bounds__(256,2)
void mma_gemm_kernel(const float* __restrict__ A, const float* __restrict__ Bm,
                     const float* __restrict__ bias, const float* __restrict__ res,
                     float* __restrict__ C,
                     int M, int N, int K, int lda, int ldb, int ldc,
                     long long sA, long long sB, long long sC){
    int bz = blockIdx.z;
    A  += (long long)bz*sA;
    Bm += (long long)bz*sB;
    C  += (long long)bz*sC;
    const float* R = RES ? res + (long long)bz*sC : nullptr;

    __shared__ __align__(16) float As[2*A_STAGE];   // [2][128][AST]
    __shared__ __align__(16) float Bs[2*B_STAGE];   // [2][16][BST]

    const int rowT = blockIdx.y*128, colT = blockIdx.x*128;
    const int tid = threadIdx.x;
    const int warp = tid >> 5, lane = tid & 31;
    const int grp = lane >> 2, tg = lane & 3;
    const int warpRow = (warp & 3) * 32;
    const int warpCol = (warp >> 2) * 64;

    // per-thread load coordinates
    const int ar = tid >> 2,  ac4 = (tid & 3) * 4;     // 64 rows per pass, 2 passes
    const int br = tid >> 5,  bc4 = (tid & 31) * 4;    // 8 rows per pass, 2 passes

    const int nIt = K >> 4;

    auto issue = [&](int it, int st){
        int k0 = it << 4;
        float* Ad = As + st*A_STAGE;
        float* Bd = Bs + st*B_STAGE;
        #pragma unroll
        for(int i=0;i<2;i++){
            int r = ar + i*64;
            cp16((uint32_t)__cvta_generic_to_shared(&Ad[r*AST + ac4]),
                 &A[(long)(rowT+r)*lda + k0 + ac4]);
        }
        #pragma unroll
        for(int i=0;i<2;i++){
            int r = br + i*8;
            cp16((uint32_t)__cvta_generic_to_shared(&Bd[r*BST + bc4]),
                 &Bm[(long)(k0+r)*ldb + colT + bc4]);
        }
        cp_commit();
    };

    float acc[2][8][4];
    #pragma unroll
    for(int mi=0;mi<2;mi++)
        #pragma unroll
        for(int ni=0;ni<8;ni++)
            #pragma unroll
            for(int t=0;t<4;t++) acc[mi][ni][t]=0.f;

    issue(0, 0);
    for(int it=0; it<nIt; it++){
        bool more = (it+1 < nIt);
        if(more) issue(it+1, (it+1)&1);
        if(more) cp_wait1(); else cp_wait0();
        __syncthreads();
        const float* Ac = As + (it&1)*A_STAGE;
        const float* Bc = Bs + (it&1)*B_STAGE;
        #pragma unroll
        for(int kk=0;kk<2;kk++){
            float a[2][4], b[8][2];
            #pragma unroll
            for(int mi=0;mi<2;mi++){
                int rb = warpRow + mi*16 + grp;
                a[mi][0] = Ac[rb*AST + kk*8 + tg];
                a[mi][1] = Ac[(rb+8)*AST + kk*8 + tg];
                a[mi][2] = Ac[rb*AST + kk*8 + tg + 4];
                a[mi][3] = Ac[(rb+8)*AST + kk*8 + tg + 4];
            }
            #pragma unroll
            for(int ni=0;ni<8;ni++){
                int cb = warpCol + ni*8 + grp;
                b[ni][0] = Bc[(kk*8 + tg)*BST + cb];
                b[ni][1] = Bc[(kk*8 + tg + 4)*BST + cb];
            }
            #pragma unroll
            for(int mi=0;mi<2;mi++)
                #pragma unroll
                for(int ni=0;ni<8;ni++)
                    mma_tf32(acc[mi][ni], a[mi], b[ni]);
        }
        __syncthreads();
    }

    // epilogue
    #pragma unroll
    for(int mi=0;mi<2;mi++){
        #pragma unroll
        for(int ni=0;ni<8;ni++){
            int r0 = rowT + warpRow + mi*16 + grp;
            int col = colT + warpCol + ni*8 + tg*2;
            float2 o0, o1;
            o0.x = acc[mi][ni][0]; o0.y = acc[mi][ni][1];
            o1.x = acc[mi][ni][2]; o1.y = acc[mi][ni][3];
            if(BIAS){
                float b0 = bias[col], b1 = bias[col+1];
                o0.x += b0; o0.y += b1;
                o1.x += b0; o1.y += b1;
            }
            if(RES){
                const float2 r0v = *(const float2*)&R[(long)r0*ldc + col];
                const float2 r1v = *(const float2*)&R[(long)(r0+8)*ldc + col];
                o0.x += r0v.x; o0.y += r0v.y;
                o1.x += r1v.x; o1.y += r1v.y;
            }
            if(ROUND){
                o0.x = to_tf32(o0.x); o0.y = to_tf32(o0.y);
                o1.x = to_tf32(o1.x); o1.y = to_tf32(o1.y);
            }
            *(float2*)&C[(long)r0*ldc + col] = o0;
            *(float2*)&C[(long)(r0+8)*ldc + col] = o1;
        }
    }
}

// ---------------- host side ---------------------------------------------------
static float* symaddr(const void* sym){
    void* p = nullptr;
    cudaGetSymbolAddress(&p, sym);
    return (float*)p;
}

extern "C" void kernel_launch(void* const* d_in, const int* in_sizes, int n_in,
                              void* d_out, int out_size){
    const float* x1       = (const float*)d_in[0];
    const float* x2       = (const float*)d_in[1];
    const float* ln1_g    = (const float*)d_in[2];
    const float* ln1_b    = (const float*)d_in[3];
    const float* ca_qkv_w = (const float*)d_in[4];
    const float* ca_temp  = (const float*)d_in[5];
    const float* ca_proj_w= (const float*)d_in[6];
    const float* ca_proj_b= (const float*)d_in[7];
    const float* ln3_g    = (const float*)d_in[8];
    const float* ln3_b    = (const float*)d_in[9];
    const float* rp_w     = (const float*)d_in[10];
    const float* rp_b     = (const float*)d_in[11];
    const float* cn_g     = (const float*)d_in[12];
    const float* cn_b     = (const float*)d_in[13];
    const float* ln2_g    = (const float*)d_in[14];
    const float* ln2_b    = (const float*)d_in[15];
    const float* fc1_w    = (const float*)d_in[16];
    const float* fc1_b    = (const float*)d_in[17];
    const float* dw_w     = (const float*)d_in[18];
    const float* dw_b     = (const float*)d_in[19];
    const float* fc2_w    = (const float*)d_in[20];
    const float* fc2_b    = (const float*)d_in[21];
    float* out = (float*)d_out;

    float* p_ln     = symaddr(g_ln);
    float* p_qkv    = symaddr(g_qkv);
    float* p_qn     = symaddr(g_qn);
    float* p_kn     = symaddr(g_kn);
    float* p_attnp  = symaddr(g_attnp);
    float* p_attn   = symaddr(g_attn);
    float* p_attnout= symaddr(g_attnout);
    float* p_ch1    = symaddr(g_ch1);
    float* p_ch2    = symaddr(g_ch2);
    float* p_n1     = symaddr(g_n1);
    float* p_n2     = symaddr(g_n2);
    float* p_key    = symaddr(g_key);
    float* p_query  = symaddr(g_query);
    float* p_ctx    = symaddr(g_ctx);
    float* p_att2   = symaddr(g_att2);
    float* p_rep    = symaddr(g_rep);
    float* p_crossln= symaddr(g_crossln);
    float* p_tx     = symaddr(g_tx);
    float* p_h1     = symaddr(g_h1);
    float* p_h2     = symaddr(g_h2);
    float* p_wqkv   = symaddr(g_wqkv);
    float* p_wproj  = symaddr(g_wproj);
    float* p_wrpT   = symaddr(g_wrpT);
    float* p_wfc1   = symaddr(g_wfc1);
    float* p_wfc2   = symaddr(g_wfc2);

    // ---- weight prep (tf32 rounding; rp_w also transposed) ----
    round_kernel<<<(DD*1152+255)/256, 256>>>(ca_qkv_w, p_wqkv, DD*1152);
    round_kernel<<<(DD*DD+255)/256, 256>>>(ca_proj_w, p_wproj, DD*DD);
    round_kernel<<<(C2*C4+255)/256, 256>>>(fc1_w, p_wfc1, C2*C4);
    round_kernel<<<(C4*C2+255)/256, 256>>>(fc2_w, p_wfc2, C4*C2);
    transpose_round_kernel<<<dim3(DD/32, C2/32), dim3(32,8)>>>(rp_w, p_wrpT);

    // ---- channel attention for both streams (shared weights) ----
    for(int s=0;s<2;s++){
        const float* x   = (s==0) ? x1 : x2;
        float* ch        = (s==0) ? p_ch1 : p_ch2;

        ln_kernel<true><<<T_TOK, 128>>>(x, ln1_g, ln1_b, p_ln, DD);

        // qkv: [T,384] @ [384,1152]
        mma_gemm_kernel<false,false,false><<<dim3(1152/128, T_TOK/128, 1), 256>>>(
            p_ln, p_wqkv, nullptr, nullptr, p_qkv,
            T_TOK, 1152, DD, DD, 1152, 1152, 0, 0, 0);

        l2norm_qk_kernel<<<2*BB*HEADS*HD, 256>>>(p_qkv, p_qn, p_kn);
        qk_kernel<<<dim3(8, BB*HEADS), 256>>>(p_qn, p_kn, p_attnp);
        softmax_attn_kernel<<<BB*HEADS*HD, 64>>>(p_attnp, p_attn, ca_temp);
        pv_kernel<<<dim3(16, BB*HEADS), 256>>>(p_attn, p_qkv, p_attnout);

        // proj + bias + residual x
        mma_gemm_kernel<true,true,false><<<dim3(DD/128, T_TOK/128, 1), 256>>>(
            p_attnout, p_wproj, ca_proj_b, x, ch,
            T_TOK, DD, DD, DD, DD, DD, 0, 0, 0);
    }

    // ---- ln3 ----
    ln_kernel<true><<<T_TOK, 128>>>(p_ch1, ln3_g, ln3_b, p_n1, DD);
    ln_kernel<true><<<T_TOK, 128>>>(p_ch2, ln3_g, ln3_b, p_n2, DD);

    // ---- cross attention ----
    colsoftmax_kernel<<<BB*DD, 256>>>(p_n2, p_key);      // softmax over tokens
    rowsoftmax_kernel<<<T_TOK, 128>>>(p_n2, p_query);    // softmax over channels

    // context[b] = key[b] (D x N) @ n1[b] (N x D); output rounded (feeds att2 B)
    mma_gemm_kernel<false,false,true><<<dim3(DD/128, DD/128, BB), 256>>>(
        p_key, p_n1, nullptr, nullptr, p_ctx,
        DD, DD, NN_TOK, NN_TOK, DD, DD,
        (long long)DD*NN_TOK, (long long)NN_TOK*DD, (long long)DD*DD);

    // attended[b] = query[b] (N x D) @ context[b] (D x D); rounded (feeds rep A)
    mma_gemm_kernel<false,false,true><<<dim3(DD/128, NN_TOK/128, BB), 256>>>(
        p_query, p_ctx, nullptr, nullptr, p_att2,
        NN_TOK, DD, DD, DD, DD, DD,
        (long long)NN_TOK*DD, (long long)DD*DD, (long long)NN_TOK*DD);

    // rep = attended (T x 384) @ rpT (384 x 768) + rp_b
    mma_gemm_kernel<true,false,false><<<dim3(C2/128, T_TOK/128, 1), 256>>>(
        p_att2, p_wrpT, rp_b, nullptr, p_rep,
        T_TOK, C2, DD, DD, C2, C2, 0, 0, 0);

    ln_kernel<false><<<T_TOK, 128>>>(p_rep, cn_g, cn_b, p_crossln, C2);

    // ---- tx = concat + cross ----
    tx_add_kernel<<<(T_TOK*C2)/256, 256>>>(p_ch1, p_ch2, p_crossln, p_tx);

    // ---- MixFFN ----
    ln_kernel<true><<<T_TOK, 128>>>(p_tx, ln2_g, ln2_b, p_ln, C2);

    mma_gemm_kernel<true,false,false><<<dim3(C4/128, T_TOK/128, 1), 256>>>(
        p_ln, p_wfc1, fc1_b, nullptr, p_h1,
        T_TOK, C4, C2, C2, C4, C4, 0, 0, 0);

    dwconv_gelu_kernel<<<dim3(C4/256, 32, BB), 256>>>(p_h1, dw_w, dw_b, p_h2);

    mma_gemm_kernel<true,true,false><<<dim3(C2/128, T_TOK/128, 1), 256>>>(
        p_h2, p_wfc2, fc2_b, p_tx, out,
        T_TOK, C2, C4, C4, C2, C2, 0, 0, 0);
}

// round 6
// speedup vs baseline: 3.6505x; 1.2392x over previous
#include <cuda_runtime.h>
#include <cuda_bf16.h>
#include <math.h>
#include <stdint.h>

// Problem constants
#define BB 16
#define NN_TOK 1024
#define DD 384
#define C2 768
#define C4 1536
#define HEADS 8
#define HD 48
#define T_TOK (BB*NN_TOK)      // 16384
#define T2 (2*T_TOK)           // 32768 (both streams)

// ---------------- scratch (device globals; no allocation allowed) -------------
__device__ float g_x[(size_t)T2*DD];              // packed x1 || x2
__device__ float g_ln[(size_t)T2*DD];             // ln1 outputs (both streams)
__device__ float g_lnw[(size_t)T_TOK*C2];         // ln2 output (wide)
__device__ float g_qkv[(size_t)T2*1152];
__device__ float g_qn[(size_t)2*BB*HEADS*HD*NN_TOK];
__device__ float g_kn[(size_t)2*BB*HEADS*HD*NN_TOK];
__device__ float g_attnp[(size_t)8*2*BB*HEADS*HD*HD];   // 8 split-K partials
__device__ float g_attn[(size_t)2*BB*HEADS*HD*HD];
__device__ float g_attnout[(size_t)T2*DD];
__device__ float g_ch[(size_t)T2*DD];             // channel1 || channel2
__device__ float g_n[(size_t)T2*DD];              // n1 || n2
__device__ float g_key[(size_t)BB*DD*NN_TOK];     // [B,D,N]
__device__ float g_query[(size_t)T_TOK*DD];       // token-major
__device__ float g_ctx[(size_t)BB*DD*DD];
__device__ float g_att2[(size_t)T_TOK*DD];
__device__ float g_rep[(size_t)T_TOK*C2];
__device__ float g_crossln[(size_t)T_TOK*C2];
__device__ float g_tx[(size_t)T_TOK*C2];
__device__ float g_h1[(size_t)T_TOK*C4];
__device__ float g_h2[(size_t)T_TOK*C4];
// pre-rounded / pre-transposed weights
__device__ float g_wqkv[(size_t)DD*1152];
__device__ float g_wproj[(size_t)DD*DD];
__device__ float g_wrpT[(size_t)DD*C2];     // transposed rp_w
__device__ float g_wfc1[(size_t)C2*C4];
__device__ float g_wfc2[(size_t)C4*C2];

// ---------------- reductions -------------------------------------------------
__device__ __forceinline__ float warpSum(float v){
    #pragma unroll
    for(int o=16;o>0;o>>=1) v += __shfl_down_sync(0xffffffffu, v, o);
    return v;
}
__device__ __forceinline__ float warpMax(float v){
    #pragma unroll
    for(int o=16;o>0;o>>=1) v = fmaxf(v, __shfl_down_sync(0xffffffffu, v, o));
    return v;
}
__device__ __forceinline__ float blockSum(float v, float* sh){
    int lane = threadIdx.x & 31, wid = threadIdx.x >> 5;
    v = warpSum(v);
    if(lane==0) sh[wid]=v;
    __syncthreads();
    int nw = blockDim.x >> 5;
    float r = (threadIdx.x < (unsigned)nw) ? sh[threadIdx.x] : 0.f;
    if(wid==0){ r = warpSum(r); if(lane==0) sh[0]=r; }
    __syncthreads();
    r = sh[0];
    __syncthreads();
    return r;
}
__device__ __forceinline__ float blockMax(float v, float* sh){
    int lane = threadIdx.x & 31, wid = threadIdx.x >> 5;
    v = warpMax(v);
    if(lane==0) sh[wid]=v;
    __syncthreads();
    int nw = blockDim.x >> 5;
    float r = (threadIdx.x < (unsigned)nw) ? sh[threadIdx.x] : -INFINITY;
    if(wid==0){ r = warpMax(r); if(lane==0) sh[0]=r; }
    __syncthreads();
    r = sh[0];
    __syncthreads();
    return r;
}

// ---------------- tf32 helpers ------------------------------------------------
__device__ __forceinline__ float to_tf32(float x){
    unsigned u;
    asm("cvt.rna.tf32.f32 %0, %1;" : "=r"(u) : "f"(x));
    return __uint_as_float(u);
}
__device__ __forceinline__ void mma_tf32(float* c, const float* a, const float* b){
    asm volatile(
        "mma.sync.aligned.m16n8k8.row.col.f32.tf32.tf32.f32 "
        "{%0,%1,%2,%3}, {%4,%5,%6,%7}, {%8,%9}, {%0,%1,%2,%3};\n"
        : "+f"(c[0]), "+f"(c[1]), "+f"(c[2]), "+f"(c[3])
        : "r"(__float_as_uint(a[0])), "r"(__float_as_uint(a[1])),
          "r"(__float_as_uint(a[2])), "r"(__float_as_uint(a[3])),
          "r"(__float_as_uint(b[0])), "r"(__float_as_uint(b[1])));
}
__device__ __forceinline__ void cp16(uint32_t s, const void* g){
    asm volatile("cp.async.cg.shared.global [%0], [%1], 16;\n" :: "r"(s), "l"(g));
}
__device__ __forceinline__ void cp_commit(){ asm volatile("cp.async.commit_group;\n"); }
__device__ __forceinline__ void cp_wait1(){ asm volatile("cp.async.wait_group 1;\n"); }
__device__ __forceinline__ void cp_wait0(){ asm volatile("cp.async.wait_group 0;\n"); }

// ---------------- pack x1||x2 -------------------------------------------------
__global__ void pack_kernel(const float* __restrict__ x1, const float* __restrict__ x2,
                            float* __restrict__ x){
    long i = ((long)blockIdx.x*blockDim.x + threadIdx.x)*4;
    const long half = (long)T_TOK*DD;
    float4 v = (i < half) ? *(const float4*)&x1[i] : *(const float4*)&x2[i-half];
    *(float4*)&x[i] = v;
}

// ---------------- weight prep: round to tf32 ----------------------------------
__global__ void round_kernel(const float* __restrict__ in, float* __restrict__ out, int n){
    int i = blockIdx.x*blockDim.x + threadIdx.x;
    if(i < n) out[i] = to_tf32(in[i]);
}
// rp_w [768][384] -> rpT [384][768], rounded
__global__ void transpose_round_kernel(const float* __restrict__ in, float* __restrict__ out){
    __shared__ float t[32][33];
    int k0 = blockIdx.x*32, n0 = blockIdx.y*32;
    int tx = threadIdx.x, ty = threadIdx.y;   // 32 x 8
    #pragma unroll
    for(int j=0;j<4;j++) t[ty+8*j][tx] = in[(n0+ty+8*j)*DD + k0+tx];
    __syncthreads();
    #pragma unroll
    for(int j=0;j<4;j++) out[(k0+ty+8*j)*C2 + n0+tx] = to_tf32(t[tx][ty+8*j]);
}

// ---------------- LayerNorm (W = 384 or 768; block=128) ----------------------
template<bool ROUND>
__global__ void ln_kernel(const float* __restrict__ x, const float* __restrict__ g,
                          const float* __restrict__ b, float* __restrict__ y, int W){
    long row = blockIdx.x;
    const float* xr = x + row*(long)W;
    int vpt = W >> 7;
    float v[6];
    float s=0.f, s2=0.f;
    for(int i=0;i<vpt;i++){
        float t = xr[i*128 + threadIdx.x];
        v[i]=t; s+=t; s2+=t*t;
    }
    __shared__ float sh[32];
    s  = blockSum(s, sh);
    s2 = blockSum(s2, sh);
    float mu = s / (float)W;
    float var = s2 / (float)W - mu*mu;
    float rstd = rsqrtf(var + 1e-5f);
    float* yr = y + row*(long)W;
    for(int i=0;i<vpt;i++){
        int c = i*128 + threadIdx.x;
        float o = (v[i]-mu)*rstd*g[c] + b[c];
        yr[c] = ROUND ? to_tf32(o) : o;
    }
}

// ---------------- L2-norm over tokens + transpose to [S,B,h,d,N] --------------
// grid = 2 streams * 2 (q/k) * B*H*HD
__global__ void l2norm_qk_kernel(const float* __restrict__ qkv,
                                 float* __restrict__ qn, float* __restrict__ kn){
    int idx = blockIdx.x;
    int stream = idx / (2*BB*HEADS*HD);
    int rest = idx % (2*BB*HEADS*HD);
    int which = rest / (BB*HEADS*HD);     // 0 = q, 1 = k
    int r = rest % (BB*HEADS*HD);
    int b = r / (HEADS*HD);
    int hj = r % (HEADS*HD);
    int col = which*DD + hj;
    const float* base = qkv + ((long)stream*T_TOK + (long)b*NN_TOK)*1152 + col;
    float v[4]; float s=0.f;
    #pragma unroll
    for(int i=0;i<4;i++){
        int n = threadIdx.x + i*256;
        float t = base[(long)n*1152];
        v[i]=t; s+=t*t;
    }
    __shared__ float sh[32];
    s = blockSum(s, sh);
    float nrm = sqrtf(s);
    float scale = 1.0f / fmaxf(nrm, 1e-12f);
    float* out = (which==0 ? qn : kn)
               + ((long)stream*BB*HEADS*HD + (long)b*(HEADS*HD) + hj)*NN_TOK;
    #pragma unroll
    for(int i=0;i<4;i++){
        int n = threadIdx.x + i*256;
        out[n] = v[i]*scale;
    }
}

// ---------------- attn logits: split-K partials (no atomics) ------------------
// grid = (8, 2*B*H), block = 256. smem stride 65 => conflict-free.
__global__ __launch_bounds__(256) void qk_kernel(const float* __restrict__ qn,
                                                 const float* __restrict__ kn,
                                                 float* __restrict__ attnp){
    int bh = blockIdx.y;           // 0..255 (stream-major)
    int s = blockIdx.x;
    const float* q = qn + (long)bh*HD*NN_TOK;
    const float* k = kn + (long)bh*HD*NN_TOK;
    __shared__ float qs[48*65];
    __shared__ float ks[48*65];
    int tid = threadIdx.x;
    int tx = tid & 15, ty = tid >> 4;
    float acc[3][3];
    #pragma unroll
    for(int r=0;r<3;r++)
        #pragma unroll
        for(int c=0;c<3;c++) acc[r][c]=0.f;

    for(int sub=0; sub<2; sub++){
        int n0 = s*128 + sub*64;
        __syncthreads();
        #pragma unroll
        for(int i=0;i<12;i++){
            int e = tid + i*256;
            int rr = e>>6, cc = e&63;
            qs[rr*65+cc] = q[rr*NN_TOK + n0 + cc];
            ks[rr*65+cc] = k[rr*NN_TOK + n0 + cc];
        }
        __syncthreads();
        #pragma unroll 4
        for(int kk=0;kk<64;kk++){
            float qv[3], kv[3];
            #pragma unroll
            for(int r=0;r<3;r++) qv[r] = qs[(ty*3+r)*65 + kk];
            #pragma unroll
            for(int c=0;c<3;c++) kv[c] = ks[(tx*3+c)*65 + kk];
            #pragma unroll
            for(int r=0;r<3;r++)
                #pragma unroll
                for(int c=0;c<3;c++) acc[r][c] = fmaf(qv[r], kv[c], acc[r][c]);
        }
    }
    float* ab = attnp + ((long)s*(2*BB*HEADS) + bh)*2304;
    #pragma unroll
    for(int r=0;r<3;r++)
        #pragma unroll
        for(int c=0;c<3;c++)
            ab[(ty*3+r)*48 + tx*3+c] = acc[r][c];
}

// ---------------- softmax over last-48: reduce 8 partials, temp, softmax ------
// grid = 2*B*H*HD
__global__ void softmax_attn_kernel(const float* __restrict__ attnp,
                                    float* __restrict__ attn,
                                    const float* __restrict__ temp){
    int row = blockIdx.x;              // bh*48 + i
    int bh = row / HD;                 // stream-major; h = low 3 bits still valid
    int h = bh & (HEADS-1);
    float t = temp[h];
    int tid = threadIdx.x;
    float v = -INFINITY;
    if(tid < HD){
        float s = 0.f;
        #pragma unroll
        for(int p=0;p<8;p++)
            s += attnp[((long)p*(2*BB*HEADS) + bh)*2304 + (row % HD)*48 + tid];
        v = s * t;
    }
    __shared__ float sh[32];
    float m = blockMax(v, sh);
    float e = (tid<HD) ? expf(v - m) : 0.f;
    float s = blockSum(e, sh);
    if(tid<HD) attn[(long)row*HD + tid] = e / s;
}

// ---------------- attn @ v, chunked over tokens (stride 49: conflict-free) ----
// grid = (16, 2*B*H)
__global__ __launch_bounds__(256) void pv_kernel(const float* __restrict__ attn,
                                                 const float* __restrict__ qkv,
                                                 float* __restrict__ out){
    int bh2 = blockIdx.y;
    int n0 = blockIdx.x * 64;
    int stream = bh2 >> 7;
    int bh = bh2 & 127;
    int b = bh >> 3, h = bh & 7;
    long tokbase = (long)stream*T_TOK + (long)b*NN_TOK;
    __shared__ float as[48*49];
    __shared__ float vs[64*49];
    int tid = threadIdx.x;
    for(int i=tid;i<2304;i+=256){
        int r = i/48, c = i%48;
        as[r*49+c] = attn[(long)bh2*2304 + i];
    }
    const float* vbase = qkv + tokbase*1152 + 2*DD + h*HD;
    #pragma unroll
    for(int i=0;i<12;i++){
        int e = tid + i*256;
        int nn = e/48, j = e%48;
        vs[nn*49+j] = vbase[(long)(n0+nn)*1152 + j];
    }
    __syncthreads();
    int tx = tid & 15;   // output channel block
    int ty = tid >> 4;   // token block
    float acc[4][3];
    #pragma unroll
    for(int s=0;s<4;s++)
        #pragma unroll
        for(int r=0;r<3;r++) acc[s][r]=0.f;
    #pragma unroll 4
    for(int j=0;j<48;j++){
        float av[3], vv[4];
        #pragma unroll
        for(int r=0;r<3;r++) av[r] = as[(tx*3+r)*49 + j];
        #pragma unroll
        for(int s=0;s<4;s++) vv[s] = vs[(ty*4+s)*49 + j];
        #pragma unroll
        for(int s=0;s<4;s++)
            #pragma unroll
            for(int r=0;r<3;r++) acc[s][r] = fmaf(av[r], vv[s], acc[s][r]);
    }
    #pragma unroll
    for(int s=0;s<4;s++)
        #pragma unroll
        for(int r=0;r<3;r++)
            out[(tokbase + n0 + ty*4+s)*DD + h*HD + tx*3 + r] = to_tf32(acc[s][r]);
}

// ---------------- column softmax (over tokens) -> key [B,D,N], tf32-rounded --
__global__ void colsoftmax_kernel(const float* __restrict__ x, float* __restrict__ key){
    int idx = blockIdx.x;
    int b = idx / DD, d = idx % DD;
    const float* base = x + (long)b*NN_TOK*DD + d;
    float v[4]; float m = -INFINITY;
    #pragma unroll
    for(int i=0;i<4;i++){
        int n = threadIdx.x + i*256;
        float t = base[(long)n*DD];
        v[i]=t; m = fmaxf(m,t);
    }
    __shared__ float sh[32];
    m = blockMax(m, sh);
    float s = 0.f;
    #pragma unroll
    for(int i=0;i<4;i++){ v[i] = expf(v[i]-m); s += v[i]; }
    s = blockSum(s, sh);
    float inv = 1.0f / s;
    float* out = key + ((long)b*DD + d)*NN_TOK;
    #pragma unroll
    for(int i=0;i<4;i++) out[threadIdx.x + i*256] = to_tf32(v[i]*inv);
}

// ---------------- row softmax (over channels) -> query, tf32-rounded ----------
__global__ void rowsoftmax_kernel(const float* __restrict__ x, float* __restrict__ y){
    long row = blockIdx.x;
    const float* xr = x + row*DD;
    float v[3]; float m = -INFINITY;
    #pragma unroll
    for(int i=0;i<3;i++){
        float t = xr[i*128 + threadIdx.x];
        v[i]=t; m=fmaxf(m,t);
    }
    __shared__ float sh[32];
    m = blockMax(m, sh);
    float s=0.f;
    #pragma unroll
    for(int i=0;i<3;i++){ v[i]=expf(v[i]-m); s+=v[i]; }
    s = blockSum(s, sh);
    float inv = 1.0f/s;
    float* yr = y + row*DD;
    #pragma unroll
    for(int i=0;i<3;i++) yr[i*128 + threadIdx.x] = to_tf32(v[i]*inv);
}

// ---------------- tx = concat(ch1,ch2) + cross --------------------------------
__global__ void tx_add_kernel(const float* __restrict__ ch1, const float* __restrict__ ch2,
                              const float* __restrict__ cl, float* __restrict__ tx){
    long i = (long)blockIdx.x*blockDim.x + threadIdx.x;
    long t = i / C2; int f = (int)(i % C2);
    float base = (f < DD) ? ch1[t*DD + f] : ch2[t*DD + f - DD];
    tx[i] = base + cl[i];
}

// ---------------- depthwise 3x3 + exact GELU: sliding window ------------------
// grid = (C4/256, 32, B), block = 256. Each thread: one channel, one row.
__global__ void dwconv_gelu_kernel(const float* __restrict__ h1, const float* __restrict__ w,
                                   const float* __restrict__ bias, float* __restrict__ h2){
    int c = blockIdx.x*blockDim.x + threadIdx.x;
    int y = blockIdx.y, b = blockIdx.z;
    const float* rowc = h1 + ((long)b*NN_TOK + y*32)*C4 + c;
    const float* rowm = rowc - 32*C4;
    const float* rowp = rowc + 32*C4;
    bool ym = (y > 0), yp = (y < 31);
    const float* wc = w + c*9;
    float w0=wc[0],w1=wc[1],w2=wc[2],w3=wc[3],w4=wc[4],w5=wc[5],w6=wc[6],w7=wc[7],w8=wc[8];
    float bs = bias[c];
    float* outr = h2 + ((long)b*NN_TOK + y*32)*C4 + c;

    float pt=0.f, pm=0.f, pb=0.f;                               // col x-1
    float ct = ym ? rowm[0] : 0.f;                              // col x
    float cm = rowc[0];
    float cb = yp ? rowp[0] : 0.f;
    #pragma unroll 4
    for(int x=0;x<32;x++){
        float nt=0.f, nm=0.f, nb=0.f;                           // col x+1
        if(x < 31){
            long o = (long)(x+1)*C4;
            nt = ym ? rowm[o] : 0.f;
            nm = rowc[o];
            nb = yp ? rowp[o] : 0.f;
        }
        float acc = bs;
        acc = fmaf(pt,w0,acc); acc = fmaf(ct,w1,acc); acc = fmaf(nt,w2,acc);
        acc = fmaf(pm,w3,acc); acc = fmaf(cm,w4,acc); acc = fmaf(nm,w5,acc);
        acc = fmaf(pb,w6,acc); acc = fmaf(cb,w7,acc); acc = fmaf(nb,w8,acc);
        float g = 0.5f*acc*(1.f + erff(acc*0.70710678118654752f));
        outr[(long)x*C4] = to_tf32(g);
        pt=ct; pm=cm; pb=cb; ct=nt; cm=nm; cb=nb;
    }
}

// ---------------- cp.async double-buffered tf32 GEMM (dynamic smem, K=32) -----
// C = A@B (+bias)(+res)(tf32-round out). Inputs must be pre-rounded to tf32.
// 128x128x32 tile, 2 stages, 256 threads, warp tile 32x64.
// M%128==0, N%128==0, K%32==0.
#define AST 36
#define BST 136
#define A_STAGE (128*AST)
#define B_STAGE (32*BST)
#define SMEM_GEMM ((2*A_STAGE + 2*B_STAGE)*4)   // 71680 bytes

template<bool BIAS, bool RES, bool ROUND>
__global__ __launch_bounds__(256,2)
void mma_gemm_kernel(const float* __restrict__ A, const float* __restrict__ Bm,
                     const float* __restrict__ bias, const float* __restrict__ res,
                     float* __restrict__ C,
                     int M, int N, int K, int lda, int ldb, int ldc,
                     long long sA, long long sB, long long sC){
    int bz = blockIdx.z;
    A  += (long long)bz*sA;
    Bm += (long long)bz*sB;
    C  += (long long)bz*sC;
    const float* R = RES ? res + (long long)bz*sC : nullptr;

    extern __shared__ float dsm[];
    float* As = dsm;                    // [2][128][AST]
    float* Bs = dsm + 2*A_STAGE;        // [2][32][BST]

    const int rowT = blockIdx.y*128, colT = blockIdx.x*128;
    const int tid = threadIdx.x;
    const int warp = tid >> 5, lane = tid & 31;
    const int grp = lane >> 2, tg = lane & 3;
    const int warpRow = (warp & 3) * 32;
    const int warpCol = (warp >> 2) * 64;

    // per-thread load coordinates
    const int ar = tid >> 3,  ac4 = (tid & 7) * 4;     // 32 rows per pass, 4 passes
    const int br = tid >> 5,  bc4 = (tid & 31) * 4;    // 8 rows per pass, 4 passes

    const int nIt = K >> 5;

    auto issue = [&](int it, int st){
        int k0 = it << 5;
        float* Ad = As + st*A_STAGE;
        float* Bd = Bs + st*B_STAGE;
        #pragma unroll
        for(int i=0;i<4;i++){
            int r = ar + i*32;
            cp16((uint32_t)__cvta_generic_to_shared(&Ad[r*AST + ac4]),
                 &A[(long)(rowT+r)*lda + k0 + ac4]);
        }
        #pragma unroll
        for(int i=0;i<4;i++){
            int r = br + i*8;
            cp16((uint32_t)__cvta_generic_to_shared(&Bd[r*BST + bc4]),
                 &Bm[(long)(k0+r)*ldb + colT + bc4]);
        }
        cp_commit();
    };

    float acc[2][8][4];
    #pragma unroll
    for(int mi=0;mi<2;mi++)
        #pragma unroll
        for(int ni=0;ni<8;ni++)
            #pragma unroll
            for(int t=0;t<4;t++) acc[mi][ni][t]=0.f;

    issue(0, 0);
    for(int it=0; it<nIt; it++){
        bool more = (it+1 < nIt);
        if(more) issue(it+1, (it+1)&1);
        if(more) cp_wait1(); else cp_wait0();
        __syncthreads();
        const float* Ac = As + (it&1)*A_STAGE;
        const float* Bc = Bs + (it&1)*B_STAGE;
        #pragma unroll
        for(int kk=0;kk<4;kk++){
            float a[2][4], b[8][2];
            #pragma unroll
            for(int mi=0;mi<2;mi++){
                int rb = warpRow + mi*16 + grp;
                a[mi][0] = Ac[rb*AST + kk*8 + tg];
                a[mi][1] = Ac[(rb+8)*AST + kk*8 + tg];
                a[mi][2] = Ac[rb*AST + kk*8 + tg + 4];
                a[mi][3] = Ac[(rb+8)*AST + kk*8 + tg + 4];
            }
            #pragma unroll
            for(int ni=0;ni<8;ni++){
                int cb = warpCol + ni*8 + grp;
                b[ni][0] = Bc[(kk*8 + tg)*BST + cb];
                b[ni][1] = Bc[(kk*8 + tg + 4)*BST + cb];
            }
            #pragma unroll
            for(int mi=0;mi<2;mi++)
                #pragma unroll
                for(int ni=0;ni<8;ni++)
                    mma_tf32(acc[mi][ni], a[mi], b[ni]);
        }
        __syncthreads();
    }

    // epilogue
    #pragma unroll
    for(int mi=0;mi<2;mi++){
        #pragma unroll
        for(int ni=0;ni<8;ni++){
            int r0 = rowT + warpRow + mi*16 + grp;
            int col = colT + warpCol + ni*8 + tg*2;
            float2 o0, o1;
            o0.x = acc[mi][ni][0]; o0.y = acc[mi][ni][1];
            o1.x = acc[mi][ni][2]; o1.y = acc[mi][ni][3];
            if(BIAS){
                float b0 = bias[col], b1 = bias[col+1];
                o0.x += b0; o0.y += b1;
                o1.x += b0; o1.y += b1;
            }
            if(RES){
                const float2 r0v = *(const float2*)&R[(long)r0*ldc + col];
                const float2 r1v = *(const float2*)&R[(long)(r0+8)*ldc + col];
                o0.x += r0v.x; o0.y += r0v.y;
                o1.x += r1v.x; o1.y += r1v.y;
            }
            if(ROUND){
                o0.x = to_tf32(o0.x); o0.y = to_tf32(o0.y);
                o1.x = to_tf32(o1.x); o1.y = to_tf32(o1.y);
            }
            *(float2*)&C[(long)r0*ldc + col] = o0;
            *(float2*)&C[(long)(r0+8)*ldc + col] = o1;
        }
    }
}

// ---------------- host side ---------------------------------------------------
static float* symaddr(const void* sym){
    void* p = nullptr;
    cudaGetSymbolAddress(&p, sym);
    return (float*)p;
}

extern "C" void kernel_launch(void* const* d_in, const int* in_sizes, int n_in,
                              void* d_out, int out_size){
    const float* x1       = (const float*)d_in[0];
    const float* x2       = (const float*)d_in[1];
    const float* ln1_g    = (const float*)d_in[2];
    const float* ln1_b    = (const float*)d_in[3];
    const float* ca_qkv_w = (const float*)d_in[4];
    const float* ca_temp  = (const float*)d_in[5];
    const float* ca_proj_w= (const float*)d_in[6];
    const float* ca_proj_b= (const float*)d_in[7];
    const float* ln3_g    = (const float*)d_in[8];
    const float* ln3_b    = (const float*)d_in[9];
    const float* rp_w     = (const float*)d_in[10];
    const float* rp_b     = (const float*)d_in[11];
    const float* cn_g     = (const float*)d_in[12];
    const float* cn_b     = (const float*)d_in[13];
    const float* ln2_g    = (const float*)d_in[14];
    const float* ln2_b    = (const float*)d_in[15];
    const float* fc1_w    = (const float*)d_in[16];
    const float* fc1_b    = (const float*)d_in[17];
    const float* dw_w     = (const float*)d_in[18];
    const float* dw_b     = (const float*)d_in[19];
    const float* fc2_w    = (const float*)d_in[20];
    const float* fc2_b    = (const float*)d_in[21];
    float* out = (float*)d_out;

    float* p_x      = symaddr(g_x);
    float* p_ln     = symaddr(g_ln);
    float* p_lnw    = symaddr(g_lnw);
    float* p_qkv    = symaddr(g_qkv);
    float* p_qn     = symaddr(g_qn);
    float* p_kn     = symaddr(g_kn);
    float* p_attnp  = symaddr(g_attnp);
    float* p_attn   = symaddr(g_attn);
    float* p_attnout= symaddr(g_attnout);
    float* p_ch     = symaddr(g_ch);
    float* p_n      = symaddr(g_n);
    float* p_key    = symaddr(g_key);
    float* p_query  = symaddr(g_query);
    float* p_ctx    = symaddr(g_ctx);
    float* p_att2   = symaddr(g_att2);
    float* p_rep    = symaddr(g_rep);
    float* p_crossln= symaddr(g_crossln);
    float* p_tx     = symaddr(g_tx);
    float* p_h1     = symaddr(g_h1);
    float* p_h2     = symaddr(g_h2);
    float* p_wqkv   = symaddr(g_wqkv);
    float* p_wproj  = symaddr(g_wproj);
    float* p_wrpT   = symaddr(g_wrpT);
    float* p_wfc1   = symaddr(g_wfc1);
    float* p_wfc2   = symaddr(g_wfc2);

    // allow 70KB dynamic smem (idempotent, no static guard, no stream op)
    cudaFuncSetAttribute(mma_gemm_kernel<false,false,false>, cudaFuncAttributeMaxDynamicSharedMemorySize, SMEM_GEMM);
    cudaFuncSetAttribute(mma_gemm_kernel<true ,true ,false>, cudaFuncAttributeMaxDynamicSharedMemorySize, SMEM_GEMM);
    cudaFuncSetAttribute(mma_gemm_kernel<false,false,true >, cudaFuncAttributeMaxDynamicSharedMemorySize, SMEM_GEMM);
    cudaFuncSetAttribute(mma_gemm_kernel<true ,false,false>, cudaFuncAttributeMaxDynamicSharedMemorySize, SMEM_GEMM);

    // ---- pack + weight prep ----
    pack_kernel<<<(T2*DD/4)/256, 256>>>(x1, x2, p_x);
    round_kernel<<<(DD*1152+255)/256, 256>>>(ca_qkv_w, p_wqkv, DD*1152);
    round_kernel<<<(DD*DD+255)/256, 256>>>(ca_proj_w, p_wproj, DD*DD);
    round_kernel<<<(C2*C4+255)/256, 256>>>(fc1_w, p_wfc1, C2*C4);
    round_kernel<<<(C4*C2+255)/256, 256>>>(fc2_w, p_wfc2, C4*C2);
    transpose_round_kernel<<<dim3(DD/32, C2/32), dim3(32,8)>>>(rp_w, p_wrpT);

    // ---- channel attention, both streams batched ----
    ln_kernel<true><<<T2, 128>>>(p_x, ln1_g, ln1_b, p_ln, DD);

    // qkv: [2T,384] @ [384,1152]
    mma_gemm_kernel<false,false,false><<<dim3(1152/128, T2/128, 1), 256, SMEM_GEMM>>>(
        p_ln, p_wqkv, nullptr, nullptr, p_qkv,
        T2, 1152, DD, DD, 1152, 1152, 0, 0, 0);

    l2norm_qk_kernel<<<2*2*BB*HEADS*HD, 256>>>(p_qkv, p_qn, p_kn);
    qk_kernel<<<dim3(8, 2*BB*HEADS), 256>>>(p_qn, p_kn, p_attnp);
    softmax_attn_kernel<<<2*BB*HEADS*HD, 64>>>(p_attnp, p_attn, ca_temp);
    pv_kernel<<<dim3(16, 2*BB*HEADS), 256>>>(p_attn, p_qkv, p_attnout);

    // proj + bias + residual (packed x)
    mma_gemm_kernel<true,true,false><<<dim3(DD/128, T2/128, 1), 256, SMEM_GEMM>>>(
        p_attnout, p_wproj, ca_proj_b, p_x, p_ch,
        T2, DD, DD, DD, DD, DD, 0, 0, 0);

    // ---- ln3 (both streams) ----
    ln_kernel<true><<<T2, 128>>>(p_ch, ln3_g, ln3_b, p_n, DD);
    float* p_n1 = p_n;
    float* p_n2 = p_n + (size_t)T_TOK*DD;

    // ---- cross attention ----
    colsoftmax_kernel<<<BB*DD, 256>>>(p_n2, p_key);      // softmax over tokens
    rowsoftmax_kernel<<<T_TOK, 128>>>(p_n2, p_query);    // softmax over channels

    // context[b] = key[b] (D x N) @ n1[b] (N x D); rounded (feeds att2 B)
    mma_gemm_kernel<false,false,true><<<dim3(DD/128, DD/128, BB), 256, SMEM_GEMM>>>(
        p_key, p_n1, nullptr, nullptr, p_ctx,
        DD, DD, NN_TOK, NN_TOK, DD, DD,
        (long long)DD*NN_TOK, (long long)NN_TOK*DD, (long long)DD*DD);

    // attended[b] = query[b] (N x D) @ context[b] (D x D); rounded (feeds rep A)
    mma_gemm_kernel<false,false,true><<<dim3(DD/128, NN_TOK/128, BB), 256, SMEM_GEMM>>>(
        p_query, p_ctx, nullptr, nullptr, p_att2,
        NN_TOK, DD, DD, DD, DD, DD,
        (long long)NN_TOK*DD, (long long)DD*DD, (long long)NN_TOK*DD);

    // rep = attended (T x 384) @ rpT (384 x 768) + rp_b
    mma_gemm_kernel<true,false,false><<<dim3(C2/128, T_TOK/128, 1), 256, SMEM_GEMM>>>(
        p_att2, p_wrpT, rp_b, nullptr, p_rep,
        T_TOK, C2, DD, DD, C2, C2, 0, 0, 0);

    ln_kernel<false><<<T_TOK, 128>>>(p_rep, cn_g, cn_b, p_crossln, C2);

    // ---- tx = concat + cross ----
    tx_add_kernel<<<(T_TOK*C2)/256, 256>>>(p_ch, p_ch + (size_t)T_TOK*DD, p_crossln, p_tx);

    // ---- MixFFN ----
    ln_kernel<true><<<T_TOK, 128>>>(p_tx, ln2_g, ln2_b, p_lnw, C2);

    mma_gemm_kernel<true,false,false><<<dim3(C4/128, T_TOK/128, 1), 256, SMEM_GEMM>>>(
        p_lnw, p_wfc1, fc1_b, nullptr, p_h1,
        T_TOK, C4, C2, C2, C4, C4, 0, 0, 0);

    dwconv_gelu_kernel<<<dim3(C4/256, 32, BB), 256>>>(p_h1, dw_w, dw_b, p_h2);

    mma_gemm_kernel<true,true,false><<<dim3(C2/128, T_TOK/128, 1), 256, SMEM_GEMM>>>(
        p_h2, p_wfc2, fc2_b, p_tx, out,
        T_TOK, C2, C4, C4, C2, C2, 0, 0, 0);
}

// round 7
// speedup vs baseline: 3.7215x; 1.0194x over previous
#include <cuda_runtime.h>
#include <cuda_bf16.h>
#include <math.h>
#include <stdint.h>

// Problem constants
#define BB 16
#define NN_TOK 1024
#define DD 384
#define C2 768
#define C4 1536
#define HEADS 8
#define HD 48
#define T_TOK (BB*NN_TOK)      // 16384
#define T2 (2*T_TOK)           // 32768 (both streams)

// ---------------- scratch (device globals; no allocation allowed) -------------
__device__ float g_x[(size_t)T2*DD];              // packed x1 || x2
__device__ float g_ln[(size_t)T2*DD];             // ln1 outputs (both streams)
__device__ float g_lnw[(size_t)T_TOK*C2];         // ln2 output (wide)
__device__ float g_qkv[(size_t)T2*1152];
__device__ float g_qn[(size_t)2*BB*HEADS*HD*NN_TOK];
__device__ float g_kn[(size_t)2*BB*HEADS*HD*NN_TOK];
__device__ float g_attnp[(size_t)8*2*BB*HEADS*HD*HD];   // 8 split-K partials
__device__ float g_attn[(size_t)2*BB*HEADS*HD*HD];
__device__ float g_attnout[(size_t)T2*DD];
__device__ float g_ch[(size_t)T2*DD];             // channel1 || channel2
__device__ float g_n[(size_t)T2*DD];              // n1 || n2
__device__ float g_key[(size_t)BB*DD*NN_TOK];     // [B,D,N]
__device__ float g_query[(size_t)T_TOK*DD];       // token-major
__device__ float g_ctx[(size_t)BB*DD*DD];
__device__ float g_att2[(size_t)T_TOK*DD];
__device__ float g_rep[(size_t)T_TOK*C2];
__device__ float g_crossln[(size_t)T_TOK*C2];
__device__ float g_tx[(size_t)T_TOK*C2];
__device__ float g_h1[(size_t)T_TOK*C4];
__device__ float g_h2[(size_t)T_TOK*C4];
// pre-rounded / pre-transposed weights
__device__ float g_wqkv[(size_t)DD*1152];
__device__ float g_wproj[(size_t)DD*DD];
__device__ float g_wrpT[(size_t)DD*C2];     // transposed rp_w
__device__ float g_wfc1[(size_t)C2*C4];
__device__ float g_wfc2[(size_t)C4*C2];

// ---------------- reductions -------------------------------------------------
__device__ __forceinline__ float warpSum(float v){
    #pragma unroll
    for(int o=16;o>0;o>>=1) v += __shfl_down_sync(0xffffffffu, v, o);
    return v;
}
__device__ __forceinline__ float warpMax(float v){
    #pragma unroll
    for(int o=16;o>0;o>>=1) v = fmaxf(v, __shfl_down_sync(0xffffffffu, v, o));
    return v;
}
__device__ __forceinline__ float blockSum(float v, float* sh){
    int lane = threadIdx.x & 31, wid = threadIdx.x >> 5;
    v = warpSum(v);
    if(lane==0) sh[wid]=v;
    __syncthreads();
    int nw = blockDim.x >> 5;
    float r = (threadIdx.x < (unsigned)nw) ? sh[threadIdx.x] : 0.f;
    if(wid==0){ r = warpSum(r); if(lane==0) sh[0]=r; }
    __syncthreads();
    r = sh[0];
    __syncthreads();
    return r;
}
__device__ __forceinline__ float blockMax(float v, float* sh){
    int lane = threadIdx.x & 31, wid = threadIdx.x >> 5;
    v = warpMax(v);
    if(lane==0) sh[wid]=v;
    __syncthreads();
    int nw = blockDim.x >> 5;
    float r = (threadIdx.x < (unsigned)nw) ? sh[threadIdx.x] : -INFINITY;
    if(wid==0){ r = warpMax(r); if(lane==0) sh[0]=r; }
    __syncthreads();
    r = sh[0];
    __syncthreads();
    return r;
}

// ---------------- tf32 helpers ------------------------------------------------
__device__ __forceinline__ float to_tf32(float x){
    unsigned u;
    asm("cvt.rna.tf32.f32 %0, %1;" : "=r"(u) : "f"(x));
    return __uint_as_float(u);
}
__device__ __forceinline__ void mma_tf32(float* c, const float* a, const float* b){
    asm volatile(
        "mma.sync.aligned.m16n8k8.row.col.f32.tf32.tf32.f32 "
        "{%0,%1,%2,%3}, {%4,%5,%6,%7}, {%8,%9}, {%0,%1,%2,%3};\n"
        : "+f"(c[0]), "+f"(c[1]), "+f"(c[2]), "+f"(c[3])
        : "r"(__float_as_uint(a[0])), "r"(__float_as_uint(a[1])),
          "r"(__float_as_uint(a[2])), "r"(__float_as_uint(a[3])),
          "r"(__float_as_uint(b[0])), "r"(__float_as_uint(b[1])));
}
__device__ __forceinline__ void cp16(uint32_t s, const void* g){
    asm volatile("cp.async.cg.shared.global [%0], [%1], 16;\n" :: "r"(s), "l"(g));
}
__device__ __forceinline__ void cp_commit(){ asm volatile("cp.async.commit_group;\n"); }
__device__ __forceinline__ void cp_wait2(){ asm volatile("cp.async.wait_group 2;\n"); }
__device__ __forceinline__ void cp_wait1(){ asm volatile("cp.async.wait_group 1;\n"); }
__device__ __forceinline__ void cp_wait0(){ asm volatile("cp.async.wait_group 0;\n"); }

// ---------------- pack x1||x2 -------------------------------------------------
__global__ void pack_kernel(const float* __restrict__ x1, const float* __restrict__ x2,
                            float* __restrict__ x){
    long i = ((long)blockIdx.x*blockDim.x + threadIdx.x)*4;
    const long half = (long)T_TOK*DD;
    float4 v = (i < half) ? *(const float4*)&x1[i] : *(const float4*)&x2[i-half];
    *(float4*)&x[i] = v;
}

// ---------------- weight prep: round 4 weight matrices in one launch ----------
#define NW1 (DD*1152)
#define NW2 (DD*DD)
#define NW3 (C2*C4)
#define NW4 (C4*C2)
__global__ void round4_kernel(const float* __restrict__ a, float* __restrict__ oa,
                              const float* __restrict__ b, float* __restrict__ ob,
                              const float* __restrict__ c, float* __restrict__ oc,
                              const float* __restrict__ d, float* __restrict__ od){
    int i = blockIdx.x*blockDim.x + threadIdx.x;
    if(i < NW1){ oa[i] = to_tf32(a[i]); return; }
    i -= NW1;
    if(i < NW2){ ob[i] = to_tf32(b[i]); return; }
    i -= NW2;
    if(i < NW3){ oc[i] = to_tf32(c[i]); return; }
    i -= NW3;
    if(i < NW4){ od[i] = to_tf32(d[i]); }
}
// rp_w [768][384] -> rpT [384][768], rounded
__global__ void transpose_round_kernel(const float* __restrict__ in, float* __restrict__ out){
    __shared__ float t[32][33];
    int k0 = blockIdx.x*32, n0 = blockIdx.y*32;
    int tx = threadIdx.x, ty = threadIdx.y;   // 32 x 8
    #pragma unroll
    for(int j=0;j<4;j++) t[ty+8*j][tx] = in[(n0+ty+8*j)*DD + k0+tx];
    __syncthreads();
    #pragma unroll
    for(int j=0;j<4;j++) out[(k0+ty+8*j)*C2 + n0+tx] = to_tf32(t[tx][ty+8*j]);
}

// ---------------- LayerNorm (W = 384 or 768; block=128) ----------------------
template<bool ROUND>
__global__ void ln_kernel(const float* __restrict__ x, const float* __restrict__ g,
                          const float* __restrict__ b, float* __restrict__ y, int W){
    long row = blockIdx.x;
    const float* xr = x + row*(long)W;
    int vpt = W >> 7;
    float v[6];
    float s=0.f, s2=0.f;
    for(int i=0;i<vpt;i++){
        float t = xr[i*128 + threadIdx.x];
        v[i]=t; s+=t; s2+=t*t;
    }
    __shared__ float sh[32];
    s  = blockSum(s, sh);
    s2 = blockSum(s2, sh);
    float mu = s / (float)W;
    float var = s2 / (float)W - mu*mu;
    float rstd = rsqrtf(var + 1e-5f);
    float* yr = y + row*(long)W;
    for(int i=0;i<vpt;i++){
        int c = i*128 + threadIdx.x;
        float o = (v[i]-mu)*rstd*g[c] + b[c];
        yr[c] = ROUND ? to_tf32(o) : o;
    }
}

// ---------------- fused: tx = concat(ch)+crossln; y = tf32(LN2(tx)) -----------
// grid = T_TOK, block = 128
__global__ void tx_ln_kernel(const float* __restrict__ ch, const float* __restrict__ cl,
                             const float* __restrict__ g, const float* __restrict__ b,
                             float* __restrict__ tx, float* __restrict__ y){
    long row = blockIdx.x;
    const float* clr = cl + row*C2;
    float v[6];
    float s=0.f, s2=0.f;
    #pragma unroll
    for(int i=0;i<6;i++){
        int c = i*128 + threadIdx.x;
        float base = (c < DD) ? ch[row*DD + c] : ch[((long)T_TOK + row)*DD + c - DD];
        float t = base + clr[c];
        v[i]=t; s+=t; s2+=t*t;
    }
    __shared__ float sh[32];
    s  = blockSum(s, sh);
    s2 = blockSum(s2, sh);
    float mu = s / (float)C2;
    float var = s2 / (float)C2 - mu*mu;
    float rstd = rsqrtf(var + 1e-5f);
    float* txr = tx + row*C2;
    float* yr  = y + row*C2;
    #pragma unroll
    for(int i=0;i<6;i++){
        int c = i*128 + threadIdx.x;
        txr[c] = v[i];
        yr[c] = to_tf32((v[i]-mu)*rstd*g[c] + b[c]);
    }
}

// ---------------- L2-norm over tokens + transpose to [S,B,h,d,N] --------------
__global__ void l2norm_qk_kernel(const float* __restrict__ qkv,
                                 float* __restrict__ qn, float* __restrict__ kn){
    int idx = blockIdx.x;
    int stream = idx / (2*BB*HEADS*HD);
    int rest = idx % (2*BB*HEADS*HD);
    int which = rest / (BB*HEADS*HD);     // 0 = q, 1 = k
    int r = rest % (BB*HEADS*HD);
    int b = r / (HEADS*HD);
    int hj = r % (HEADS*HD);
    int col = which*DD + hj;
    const float* base = qkv + ((long)stream*T_TOK + (long)b*NN_TOK)*1152 + col;
    float v[4]; float s=0.f;
    #pragma unroll
    for(int i=0;i<4;i++){
        int n = threadIdx.x + i*256;
        float t = base[(long)n*1152];
        v[i]=t; s+=t*t;
    }
    __shared__ float sh[32];
    s = blockSum(s, sh);
    float nrm = sqrtf(s);
    float scale = 1.0f / fmaxf(nrm, 1e-12f);
    float* out = (which==0 ? qn : kn)
               + ((long)stream*BB*HEADS*HD + (long)b*(HEADS*HD) + hj)*NN_TOK;
    #pragma unroll
    for(int i=0;i<4;i++){
        int n = threadIdx.x + i*256;
        out[n] = v[i]*scale;
    }
}

// ---------------- attn logits: split-K partials (no atomics) ------------------
__global__ __launch_bounds__(256) void qk_kernel(const float* __restrict__ qn,
                                                 const float* __restrict__ kn,
                                                 float* __restrict__ attnp){
    int bh = blockIdx.y;           // 0..255 (stream-major)
    int s = blockIdx.x;
    const float* q = qn + (long)bh*HD*NN_TOK;
    const float* k = kn + (long)bh*HD*NN_TOK;
    __shared__ float qs[48*65];
    __shared__ float ks[48*65];
    int tid = threadIdx.x;
    int tx = tid & 15, ty = tid >> 4;
    float acc[3][3];
    #pragma unroll
    for(int r=0;r<3;r++)
        #pragma unroll
        for(int c=0;c<3;c++) acc[r][c]=0.f;

    for(int sub=0; sub<2; sub++){
        int n0 = s*128 + sub*64;
        __syncthreads();
        #pragma unroll
        for(int i=0;i<12;i++){
            int e = tid + i*256;
            int rr = e>>6, cc = e&63;
            qs[rr*65+cc] = q[rr*NN_TOK + n0 + cc];
            ks[rr*65+cc] = k[rr*NN_TOK + n0 + cc];
        }
        __syncthreads();
        #pragma unroll 4
        for(int kk=0;kk<64;kk++){
            float qv[3], kv[3];
            #pragma unroll
            for(int r=0;r<3;r++) qv[r] = qs[(ty*3+r)*65 + kk];
            #pragma unroll
            for(int c=0;c<3;c++) kv[c] = ks[(tx*3+c)*65 + kk];
            #pragma unroll
            for(int r=0;r<3;r++)
                #pragma unroll
                for(int c=0;c<3;c++) acc[r][c] = fmaf(qv[r], kv[c], acc[r][c]);
        }
    }
    float* ab = attnp + ((long)s*(2*BB*HEADS) + bh)*2304;
    #pragma unroll
    for(int r=0;r<3;r++)
        #pragma unroll
        for(int c=0;c<3;c++)
            ab[(ty*3+r)*48 + tx*3+c] = acc[r][c];
}

// ---------------- softmax over last-48: reduce 8 partials, temp, softmax ------
__global__ void softmax_attn_kernel(const float* __restrict__ attnp,
                                    float* __restrict__ attn,
                                    const float* __restrict__ temp){
    int row = blockIdx.x;              // bh*48 + i
    int bh = row / HD;
    int h = bh & (HEADS-1);
    float t = temp[h];
    int tid = threadIdx.x;
    float v = -INFINITY;
    if(tid < HD){
        float s = 0.f;
        #pragma unroll
        for(int p=0;p<8;p++)
            s += attnp[((long)p*(2*BB*HEADS) + bh)*2304 + (row % HD)*48 + tid];
        v = s * t;
    }
    __shared__ float sh[32];
    float m = blockMax(v, sh);
    float e = (tid<HD) ? expf(v - m) : 0.f;
    float s = blockSum(e, sh);
    if(tid<HD) attn[(long)row*HD + tid] = e / s;
}

// ---------------- attn @ v, chunked over tokens (stride 49: conflict-free) ----
__global__ __launch_bounds__(256) void pv_kernel(const float* __restrict__ attn,
                                                 const float* __restrict__ qkv,
                                                 float* __restrict__ out){
    int bh2 = blockIdx.y;
    int n0 = blockIdx.x * 64;
    int stream = bh2 >> 7;
    int bh = bh2 & 127;
    int b = bh >> 3, h = bh & 7;
    long tokbase = (long)stream*T_TOK + (long)b*NN_TOK;
    __shared__ float as[48*49];
    __shared__ float vs[64*49];
    int tid = threadIdx.x;
    for(int i=tid;i<2304;i+=256){
        int r = i/48, c = i%48;
        as[r*49+c] = attn[(long)bh2*2304 + i];
    }
    const float* vbase = qkv + tokbase*1152 + 2*DD + h*HD;
    #pragma unroll
    for(int i=0;i<12;i++){
        int e = tid + i*256;
        int nn = e/48, j = e%48;
        vs[nn*49+j] = vbase[(long)(n0+nn)*1152 + j];
    }
    __syncthreads();
    int tx = tid & 15;
    int ty = tid >> 4;
    float acc[4][3];
    #pragma unroll
    for(int s=0;s<4;s++)
        #pragma unroll
        for(int r=0;r<3;r++) acc[s][r]=0.f;
    #pragma unroll 4
    for(int j=0;j<48;j++){
        float av[3], vv[4];
        #pragma unroll
        for(int r=0;r<3;r++) av[r] = as[(tx*3+r)*49 + j];
        #pragma unroll
        for(int s=0;s<4;s++) vv[s] = vs[(ty*4+s)*49 + j];
        #pragma unroll
        for(int s=0;s<4;s++)
            #pragma unroll
            for(int r=0;r<3;r++) acc[s][r] = fmaf(av[r], vv[s], acc[s][r]);
    }
    #pragma unroll
    for(int s=0;s<4;s++)
        #pragma unroll
        for(int r=0;r<3;r++)
            out[(tokbase + n0 + ty*4+s)*DD + h*HD + tx*3 + r] = to_tf32(acc[s][r]);
}

// ---------------- column softmax (over tokens) -> key [B,D,N], tf32-rounded --
__global__ void colsoftmax_kernel(const float* __restrict__ x, float* __restrict__ key){
    int idx = blockIdx.x;
    int b = idx / DD, d = idx % DD;
    const float* base = x + (long)b*NN_TOK*DD + d;
    float v[4]; float m = -INFINITY;
    #pragma unroll
    for(int i=0;i<4;i++){
        int n = threadIdx.x + i*256;
        float t = base[(long)n*DD];
        v[i]=t; m = fmaxf(m,t);
    }
    __shared__ float sh[32];
    m = blockMax(m, sh);
    float s = 0.f;
    #pragma unroll
    for(int i=0;i<4;i++){ v[i] = expf(v[i]-m); s += v[i]; }
    s = blockSum(s, sh);
    float inv = 1.0f / s;
    float* out = key + ((long)b*DD + d)*NN_TOK;
    #pragma unroll
    for(int i=0;i<4;i++) out[threadIdx.x + i*256] = to_tf32(v[i]*inv);
}

// ---------------- row softmax (over channels) -> query, tf32-rounded ----------
__global__ void rowsoftmax_kernel(const float* __restrict__ x, float* __restrict__ y){
    long row = blockIdx.x;
    const float* xr = x + row*DD;
    float v[3]; float m = -INFINITY;
    #pragma unroll
    for(int i=0;i<3;i++){
        float t = xr[i*128 + threadIdx.x];
        v[i]=t; m=fmaxf(m,t);
    }
    __shared__ float sh[32];
    m = blockMax(m, sh);
    float s=0.f;
    #pragma unroll
    for(int i=0;i<3;i++){ v[i]=expf(v[i]-m); s+=v[i]; }
    s = blockSum(s, sh);
    float inv = 1.0f/s;
    float* yr = y + row*DD;
    #pragma unroll
    for(int i=0;i<3;i++) yr[i*128 + threadIdx.x] = to_tf32(v[i]*inv);
}

// ---------------- depthwise 3x3 + exact GELU: sliding window ------------------
__global__ void dwconv_gelu_kernel(const float* __restrict__ h1, const float* __restrict__ w,
                                   const float* __restrict__ bias, float* __restrict__ h2){
    int c = blockIdx.x*blockDim.x + threadIdx.x;
    int y = blockIdx.y, b = blockIdx.z;
    const float* rowc = h1 + ((long)b*NN_TOK + y*32)*C4 + c;
    const float* rowm = rowc - 32*C4;
    const float* rowp = rowc + 32*C4;
    bool ym = (y > 0), yp = (y < 31);
    const float* wc = w + c*9;
    float w0=wc[0],w1=wc[1],w2=wc[2],w3=wc[3],w4=wc[4],w5=wc[5],w6=wc[6],w7=wc[7],w8=wc[8];
    float bs = bias[c];
    float* outr = h2 + ((long)b*NN_TOK + y*32)*C4 + c;

    float pt=0.f, pm=0.f, pb=0.f;
    float ct = ym ? rowm[0] : 0.f;
    float cm = rowc[0];
    float cb = yp ? rowp[0] : 0.f;
    #pragma unroll 4
    for(int x=0;x<32;x++){
        float nt=0.f, nm=0.f, nb=0.f;
        if(x < 31){
            long o = (long)(x+1)*C4;
            nt = ym ? rowm[o] : 0.f;
            nm = rowc[o];
            nb = yp ? rowp[o] : 0.f;
        }
        float acc = bs;
        acc = fmaf(pt,w0,acc); acc = fmaf(ct,w1,acc); acc = fmaf(nt,w2,acc);
        acc = fmaf(pm,w3,acc); acc = fmaf(cm,w4,acc); acc = fmaf(nm,w5,acc);
        acc = fmaf(pb,w6,acc); acc = fmaf(cb,w7,acc); acc = fmaf(nb,w8,acc);
        float g = 0.5f*acc*(1.f + erff(acc*0.70710678118654752f));
        outr[(long)x*C4] = to_tf32(g);
        pt=ct; pm=cm; pb=cb; ct=nt; cm=nm; cb=nb;
    }
}

// ---------------- 3-stage cp.async tf32 GEMM (dynamic smem) -------------------
// C = A@B (+bias)(+res)(tf32-round out). Inputs must be pre-rounded to tf32.
// 128x128x32 tile, 3 stages, 256 threads, warp tile 32x64.
// M%128==0, N%128==0, K%32==0.
#define AST 36
#define BST 136
#define A_STAGE (128*AST)
#define B_STAGE (32*BST)
#define STAGE_F (A_STAGE + B_STAGE)
#define SMEM_GEMM (3*STAGE_F*4)   // 107520 bytes

template<bool BIAS, bool RES, bool ROUND>
__global__ __launch_bounds__(256,2)
void mma_gemm_kernel(const float* __restrict__ A, const float* __restrict__ Bm,
                     const float* __restrict__ bias, const float* __restrict__ res,
                     float* __restrict__ C,
                     int M, int N, int K, int lda, int ldb, int ldc,
                     long long sA, long long sB, long long sC){
    int bz = blockIdx.z;
    A  += (long long)bz*sA;
    Bm += (long long)bz*sB;
    C  += (long long)bz*sC;
    const float* R = RES ? res + (long long)bz*sC : nullptr;

    extern __shared__ float dsm[];   // [3][STAGE_F]: A tile then B tile per stage

    const int rowT = blockIdx.y*128, colT = blockIdx.x*128;
    const int tid = threadIdx.x;
    const int warp = tid >> 5, lane = tid & 31;
    const int grp = lane >> 2, tg = lane & 3;
    const int warpRow = (warp & 3) * 32;
    const int warpCol = (warp >> 2) * 64;

    const int ar = tid >> 3,  ac4 = (tid & 7) * 4;
    const int br = tid >> 5,  bc4 = (tid & 31) * 4;

    const int nIt = K >> 5;

    auto issue = [&](int it, int st){
        int k0 = it << 5;
        float* Ad = dsm + st*STAGE_F;
        float* Bd = Ad + A_STAGE;
        #pragma unroll
        for(int i=0;i<4;i++){
            int r = ar + i*32;
            cp16((uint32_t)__cvta_generic_to_shared(&Ad[r*AST + ac4]),
                 &A[(long)(rowT+r)*lda + k0 + ac4]);
        }
        #pragma unroll
        for(int i=0;i<4;i++){
            int r = br + i*8;
            cp16((uint32_t)__cvta_generic_to_shared(&Bd[r*BST + bc4]),
                 &Bm[(long)(k0+r)*ldb + colT + bc4]);
        }
        cp_commit();
    };

    float acc[2][8][4];
    #pragma unroll
    for(int mi=0;mi<2;mi++)
        #pragma unroll
        for(int ni=0;ni<8;ni++)
            #pragma unroll
            for(int t=0;t<4;t++) acc[mi][ni][t]=0.f;

    issue(0, 0);
    if(nIt > 1) issue(1, 1);
    int st = 0;
    for(int it=0; it<nIt; it++){
        if(it+2 < nIt){
            int s2 = st+2; if(s2>=3) s2-=3;
            issue(it+2, s2);
            cp_wait2();
        } else if(it+1 < nIt){
            cp_wait1();
        } else {
            cp_wait0();
        }
        __syncthreads();
        const float* Ac = dsm + st*STAGE_F;
        const float* Bc = Ac + A_STAGE;
        #pragma unroll
        for(int kk=0;kk<4;kk++){
            float a[2][4], b[8][2];
            #pragma unroll
            for(int mi=0;mi<2;mi++){
                int rb = warpRow + mi*16 + grp;
                a[mi][0] = Ac[rb*AST + kk*8 + tg];
                a[mi][1] = Ac[(rb+8)*AST + kk*8 + tg];
                a[mi][2] = Ac[rb*AST + kk*8 + tg + 4];
                a[mi][3] = Ac[(rb+8)*AST + kk*8 + tg + 4];
            }
            #pragma unroll
            for(int ni=0;ni<8;ni++){
                int cb = warpCol + ni*8 + grp;
                b[ni][0] = Bc[(kk*8 + tg)*BST + cb];
                b[ni][1] = Bc[(kk*8 + tg + 4)*BST + cb];
            }
            #pragma unroll
            for(int mi=0;mi<2;mi++)
                #pragma unroll
                for(int ni=0;ni<8;ni++)
                    mma_tf32(acc[mi][ni], a[mi], b[ni]);
        }
        __syncthreads();
        if(++st == 3) st = 0;
    }

    // epilogue
    #pragma unroll
    for(int mi=0;mi<2;mi++){
        #pragma unroll
        for(int ni=0;ni<8;ni++){
            int r0 = rowT + warpRow + mi*16 + grp;
            int col = colT + warpCol + ni*8 + tg*2;
            float2 o0, o1;
            o0.x = acc[mi][ni][0]; o0.y = acc[mi][ni][1];
            o1.x = acc[mi][ni][2]; o1.y = acc[mi][ni][3];
            if(BIAS){
                float b0 = bias[col], b1 = bias[col+1];
                o0.x += b0; o0.y += b1;
                o1.x += b0; o1.y += b1;
            }
            if(RES){
                const float2 r0v = *(const float2*)&R[(long)r0*ldc + col];
                const float2 r1v = *(const float2*)&R[(long)(r0+8)*ldc + col];
                o0.x += r0v.x; o0.y += r0v.y;
                o1.x += r1v.x; o1.y += r1v.y;
            }
            if(ROUND){
                o0.x = to_tf32(o0.x); o0.y = to_tf32(o0.y);
                o1.x = to_tf32(o1.x); o1.y = to_tf32(o1.y);
            }
            *(float2*)&C[(long)r0*ldc + col] = o0;
            *(float2*)&C[(long)(r0+8)*ldc + col] = o1;
        }
    }
}

// ---------------- host side ---------------------------------------------------
static float* symaddr(const void* sym){
    void* p = nullptr;
    cudaGetSymbolAddress(&p, sym);
    return (float*)p;
}

extern "C" void kernel_launch(void* const* d_in, const int* in_sizes, int n_in,
                              void* d_out, int out_size){
    const float* x1       = (const float*)d_in[0];
    const float* x2       = (const float*)d_in[1];
    const float* ln1_g    = (const float*)d_in[2];
    const float* ln1_b    = (const float*)d_in[3];
    const float* ca_qkv_w = (const float*)d_in[4];
    const float* ca_temp  = (const float*)d_in[5];
    const float* ca_proj_w= (const float*)d_in[6];
    const float* ca_proj_b= (const float*)d_in[7];
    const float* ln3_g    = (const float*)d_in[8];
    const float* ln3_b    = (const float*)d_in[9];
    const float* rp_w     = (const float*)d_in[10];
    const float* rp_b     = (const float*)d_in[11];
    const float* cn_g     = (const float*)d_in[12];
    const float* cn_b     = (const float*)d_in[13];
    const float* ln2_g    = (const float*)d_in[14];
    const float* ln2_b    = (const float*)d_in[15];
    const float* fc1_w    = (const float*)d_in[16];
    const float* fc1_b    = (const float*)d_in[17];
    const float* dw_w     = (const float*)d_in[18];
    const float* dw_b     = (const float*)d_in[19];
    const float* fc2_w    = (const float*)d_in[20];
    const float* fc2_b    = (const float*)d_in[21];
    float* out = (float*)d_out;

    float* p_x      = symaddr(g_x);
    float* p_ln     = symaddr(g_ln);
    float* p_lnw    = symaddr(g_lnw);
    float* p_qkv    = symaddr(g_qkv);
    float* p_qn     = symaddr(g_qn);
    float* p_kn     = symaddr(g_kn);
    float* p_attnp  = symaddr(g_attnp);
    float* p_attn   = symaddr(g_attn);
    float* p_attnout= symaddr(g_attnout);
    float* p_ch     = symaddr(g_ch);
    float* p_n      = symaddr(g_n);
    float* p_key    = symaddr(g_key);
    float* p_query  = symaddr(g_query);
    float* p_ctx    = symaddr(g_ctx);
    float* p_att2   = symaddr(g_att2);
    float* p_rep    = symaddr(g_rep);
    float* p_crossln= symaddr(g_crossln);
    float* p_tx     = symaddr(g_tx);
    float* p_h1     = symaddr(g_h1);
    float* p_h2     = symaddr(g_h2);
    float* p_wqkv   = symaddr(g_wqkv);
    float* p_wproj  = symaddr(g_wproj);
    float* p_wrpT   = symaddr(g_wrpT);
    float* p_wfc1   = symaddr(g_wfc1);
    float* p_wfc2   = symaddr(g_wfc2);

    // allow 105KB dynamic smem (idempotent, no static guard, no stream op)
    cudaFuncSetAttribute(mma_gemm_kernel<false,false,false>, cudaFuncAttributeMaxDynamicSharedMemorySize, SMEM_GEMM);
    cudaFuncSetAttribute(mma_gemm_kernel<true ,true ,false>, cudaFuncAttributeMaxDynamicSharedMemorySize, SMEM_GEMM);
    cudaFuncSetAttribute(mma_gemm_kernel<false,false,true >, cudaFuncAttributeMaxDynamicSharedMemorySize, SMEM_GEMM);
    cudaFuncSetAttribute(mma_gemm_kernel<true ,false,false>, cudaFuncAttributeMaxDynamicSharedMemorySize, SMEM_GEMM);

    // ---- pack + weight prep ----
    pack_kernel<<<(T2*DD/4)/256, 256>>>(x1, x2, p_x);
    round4_kernel<<<(NW1+NW2+NW3+NW4+255)/256, 256>>>(
        ca_qkv_w, p_wqkv, ca_proj_w, p_wproj, fc1_w, p_wfc1, fc2_w, p_wfc2);
    transpose_round_kernel<<<dim3(DD/32, C2/32), dim3(32,8)>>>(rp_w, p_wrpT);

    // ---- channel attention, both streams batched ----
    ln_kernel<true><<<T2, 128>>>(p_x, ln1_g, ln1_b, p_ln, DD);

    mma_gemm_kernel<false,false,false><<<dim3(1152/128, T2/128, 1), 256, SMEM_GEMM>>>(
        p_ln, p_wqkv, nullptr, nullptr, p_qkv,
        T2, 1152, DD, DD, 1152, 1152, 0, 0, 0);

    l2norm_qk_kernel<<<2*2*BB*HEADS*HD, 256>>>(p_qkv, p_qn, p_kn);
    qk_kernel<<<dim3(8, 2*BB*HEADS), 256>>>(p_qn, p_kn, p_attnp);
    softmax_attn_kernel<<<2*BB*HEADS*HD, 64>>>(p_attnp, p_attn, ca_temp);
    pv_kernel<<<dim3(16, 2*BB*HEADS), 256>>>(p_attn, p_qkv, p_attnout);

    mma_gemm_kernel<true,true,false><<<dim3(DD/128, T2/128, 1), 256, SMEM_GEMM>>>(
        p_attnout, p_wproj, ca_proj_b, p_x, p_ch,
        T2, DD, DD, DD, DD, DD, 0, 0, 0);

    // ---- ln3 (both streams) ----
    ln_kernel<true><<<T2, 128>>>(p_ch, ln3_g, ln3_b, p_n, DD);
    float* p_n1 = p_n;
    float* p_n2 = p_n + (size_t)T_TOK*DD;

    // ---- cross attention ----
    colsoftmax_kernel<<<BB*DD, 256>>>(p_n2, p_key);
    rowsoftmax_kernel<<<T_TOK, 128>>>(p_n2, p_query);

    mma_gemm_kernel<false,false,true><<<dim3(DD/128, DD/128, BB), 256, SMEM_GEMM>>>(
        p_key, p_n1, nullptr, nullptr, p_ctx,
        DD, DD, NN_TOK, NN_TOK, DD, DD,
        (long long)DD*NN_TOK, (long long)NN_TOK*DD, (long long)DD*DD);

    mma_gemm_kernel<false,false,true><<<dim3(DD/128, NN_TOK/128, BB), 256, SMEM_GEMM>>>(
        p_query, p_ctx, nullptr, nullptr, p_att2,
        NN_TOK, DD, DD, DD, DD, DD,
        (long long)NN_TOK*DD, (long long)DD*DD, (long long)NN_TOK*DD);

    mma_gemm_kernel<true,false,false><<<dim3(C2/128, T_TOK/128, 1), 256, SMEM_GEMM>>>(
        p_att2, p_wrpT, rp_b, nullptr, p_rep,
        T_TOK, C2, DD, DD, C2, C2, 0, 0, 0);

    ln_kernel<false><<<T_TOK, 128>>>(p_rep, cn_g, cn_b, p_crossln, C2);

    // ---- fused tx = concat+cross, ln2 ----
    tx_ln_kernel<<<T_TOK, 128>>>(p_ch, p_crossln, ln2_g, ln2_b, p_tx, p_lnw);

    // ---- MixFFN ----
    mma_gemm_kernel<true,false,false><<<dim3(C4/128, T_TOK/128, 1), 256, SMEM_GEMM>>>(
        p_lnw, p_wfc1, fc1_b, nullptr, p_h1,
        T_TOK, C4, C2, C2, C4, C4, 0, 0, 0);

    dwconv_gelu_kernel<<<dim3(C4/256, 32, BB), 256>>>(p_h1, dw_w, dw_b, p_h2);

    mma_gemm_kernel<true,true,false><<<dim3(C2/128, T_TOK/128, 1), 256, SMEM_GEMM>>>(
        p_h2, p_wfc2, fc2_b, p_tx, out,
        T_TOK, C2, C4, C4, C2, C2, 0, 0, 0);
}

// round 8
// speedup vs baseline: 3.9691x; 1.0665x over previous
#include <cuda_runtime.h>
#include <cuda_fp16.h>
#include <math.h>
#include <stdint.h>

// Problem constants
#define BB 16
#define NN_TOK 1024
#define DD 384
#define C2 768
#define C4 1536
#define HEADS 8
#define HD 48
#define T_TOK (BB*NN_TOK)      // 16384
#define T2 (2*T_TOK)           // 32768 (both streams)

// ---------------- scratch (device globals; no allocation allowed) -------------
__device__ float  g_x[(size_t)T2*DD];              // packed x1 || x2 (fp32, residual)
__device__ __half g_ln[(size_t)T2*DD];             // ln1 outputs (half, GEMM A)
__device__ __half g_lnw[(size_t)T_TOK*C2];         // ln2 output (half, GEMM A)
__device__ float  g_qkv[(size_t)T2*1152];
__device__ float  g_qn[(size_t)2*BB*HEADS*HD*NN_TOK];
__device__ float  g_kn[(size_t)2*BB*HEADS*HD*NN_TOK];
__device__ float  g_attnp[(size_t)8*2*BB*HEADS*HD*HD];
__device__ float  g_attn[(size_t)2*BB*HEADS*HD*HD];
__device__ __half g_attnout[(size_t)T2*DD];        // half (GEMM A)
__device__ float  g_ch[(size_t)T2*DD];             // channel1 || channel2
__device__ __half g_n[(size_t)T2*DD];              // n1 || n2 (half)
__device__ __half g_key[(size_t)BB*DD*NN_TOK];     // [B,D,N] half
__device__ __half g_query[(size_t)T_TOK*DD];       // half
__device__ __half g_ctx[(size_t)BB*DD*DD];         // half (GEMM out+in)
__device__ __half g_att2[(size_t)T_TOK*DD];        // half
__device__ float  g_rep[(size_t)T_TOK*C2];
__device__ float  g_crossln[(size_t)T_TOK*C2];
__device__ float  g_tx[(size_t)T_TOK*C2];
__device__ float  g_h1[(size_t)T_TOK*C4];
__device__ __half g_h2[(size_t)T_TOK*C4];          // half (GEMM A)
// pre-converted / pre-transposed weights (half)
__device__ __half g_wqkv[(size_t)DD*1152];
__device__ __half g_wproj[(size_t)DD*DD];
__device__ __half g_wrpT[(size_t)DD*C2];
__device__ __half g_wfc1[(size_t)C2*C4];
__device__ __half g_wfc2[(size_t)C4*C2];

// ---------------- reductions -------------------------------------------------
__device__ __forceinline__ float warpSum(float v){
    #pragma unroll
    for(int o=16;o>0;o>>=1) v += __shfl_down_sync(0xffffffffu, v, o);
    return v;
}
__device__ __forceinline__ float warpMax(float v){
    #pragma unroll
    for(int o=16;o>0;o>>=1) v = fmaxf(v, __shfl_down_sync(0xffffffffu, v, o));
    return v;
}
__device__ __forceinline__ float blockSum(float v, float* sh){
    int lane = threadIdx.x & 31, wid = threadIdx.x >> 5;
    v = warpSum(v);
    if(lane==0) sh[wid]=v;
    __syncthreads();
    int nw = blockDim.x >> 5;
    float r = (threadIdx.x < (unsigned)nw) ? sh[threadIdx.x] : 0.f;
    if(wid==0){ r = warpSum(r); if(lane==0) sh[0]=r; }
    __syncthreads();
    r = sh[0];
    __syncthreads();
    return r;
}
__device__ __forceinline__ float blockMax(float v, float* sh){
    int lane = threadIdx.x & 31, wid = threadIdx.x >> 5;
    v = warpMax(v);
    if(lane==0) sh[wid]=v;
    __syncthreads();
    int nw = blockDim.x >> 5;
    float r = (threadIdx.x < (unsigned)nw) ? sh[threadIdx.x] : -INFINITY;
    if(wid==0){ r = warpMax(r); if(lane==0) sh[0]=r; }
    __syncthreads();
    r = sh[0];
    __syncthreads();
    return r;
}

// ---------------- mma / ldmatrix / cp.async helpers ---------------------------
__device__ __forceinline__ void mma_f16(float* c, const uint32_t* a, const uint32_t* b){
    asm volatile(
        "mma.sync.aligned.m16n8k16.row.col.f32.f16.f16.f32 "
        "{%0,%1,%2,%3}, {%4,%5,%6,%7}, {%8,%9}, {%0,%1,%2,%3};\n"
        : "+f"(c[0]), "+f"(c[1]), "+f"(c[2]), "+f"(c[3])
        : "r"(a[0]), "r"(a[1]), "r"(a[2]), "r"(a[3]),
          "r"(b[0]), "r"(b[1]));
}
__device__ __forceinline__ void ldsm4(uint32_t* r, uint32_t addr){
    asm volatile("ldmatrix.sync.aligned.m8n8.x4.shared.b16 {%0,%1,%2,%3}, [%4];\n"
                 : "=r"(r[0]), "=r"(r[1]), "=r"(r[2]), "=r"(r[3]) : "r"(addr));
}
__device__ __forceinline__ void ldsm4t(uint32_t* r, uint32_t addr){
    asm volatile("ldmatrix.sync.aligned.m8n8.x4.trans.shared.b16 {%0,%1,%2,%3}, [%4];\n"
                 : "=r"(r[0]), "=r"(r[1]), "=r"(r[2]), "=r"(r[3]) : "r"(addr));
}
__device__ __forceinline__ void cp16(uint32_t s, const void* g){
    asm volatile("cp.async.cg.shared.global [%0], [%1], 16;\n" :: "r"(s), "l"(g));
}
__device__ __forceinline__ void cp_commit(){ asm volatile("cp.async.commit_group;\n"); }
__device__ __forceinline__ void cp_wait2(){ asm volatile("cp.async.wait_group 2;\n"); }
__device__ __forceinline__ void cp_wait1(){ asm volatile("cp.async.wait_group 1;\n"); }
__device__ __forceinline__ void cp_wait0(){ asm volatile("cp.async.wait_group 0;\n"); }

__device__ __forceinline__ void storev(float* p, float v){ *p = v; }
__device__ __forceinline__ void storev(__half* p, float v){ *p = __float2half_rn(v); }

// ---------------- pack x1||x2 -------------------------------------------------
__global__ void pack_kernel(const float* __restrict__ x1, const float* __restrict__ x2,
                            float* __restrict__ x){
    long i = ((long)blockIdx.x*blockDim.x + threadIdx.x)*4;
    const long half_ = (long)T_TOK*DD;
    float4 v = (i < half_) ? *(const float4*)&x1[i] : *(const float4*)&x2[i-half_];
    *(float4*)&x[i] = v;
}

// ---------------- weight prep: convert 4 weight matrices to half --------------
#define NW1 (DD*1152)
#define NW2 (DD*DD)
#define NW3 (C2*C4)
#define NW4 (C4*C2)
__global__ void cvt4_kernel(const float* __restrict__ a, __half* __restrict__ oa,
                            const float* __restrict__ b, __half* __restrict__ ob,
                            const float* __restrict__ c, __half* __restrict__ oc,
                            const float* __restrict__ d, __half* __restrict__ od){
    int i = blockIdx.x*blockDim.x + threadIdx.x;
    if(i < NW1){ oa[i] = __float2half_rn(a[i]); return; }
    i -= NW1;
    if(i < NW2){ ob[i] = __float2half_rn(b[i]); return; }
    i -= NW2;
    if(i < NW3){ oc[i] = __float2half_rn(c[i]); return; }
    i -= NW3;
    if(i < NW4){ od[i] = __float2half_rn(d[i]); }
}
// rp_w [768][384] -> rpT [384][768], half
__global__ void transpose_cvt_kernel(const float* __restrict__ in, __half* __restrict__ out){
    __shared__ float t[32][33];
    int k0 = blockIdx.x*32, n0 = blockIdx.y*32;
    int tx = threadIdx.x, ty = threadIdx.y;   // 32 x 8
    #pragma unroll
    for(int j=0;j<4;j++) t[ty+8*j][tx] = in[(n0+ty+8*j)*DD + k0+tx];
    __syncthreads();
    #pragma unroll
    for(int j=0;j<4;j++) out[(k0+ty+8*j)*C2 + n0+tx] = __float2half_rn(t[tx][ty+8*j]);
}

// ---------------- LayerNorm (W = 384 or 768; block=128) ----------------------
template<typename OUT>
__global__ void ln_kernel(const float* __restrict__ x, const float* __restrict__ g,
                          const float* __restrict__ b, OUT* __restrict__ y, int W){
    long row = blockIdx.x;
    const float* xr = x + row*(long)W;
    int vpt = W >> 7;
    float v[6];
    float s=0.f, s2=0.f;
    for(int i=0;i<vpt;i++){
        float t = xr[i*128 + threadIdx.x];
        v[i]=t; s+=t; s2+=t*t;
    }
    __shared__ float sh[32];
    s  = blockSum(s, sh);
    s2 = blockSum(s2, sh);
    float mu = s / (float)W;
    float var = s2 / (float)W - mu*mu;
    float rstd = rsqrtf(var + 1e-5f);
    OUT* yr = y + row*(long)W;
    for(int i=0;i<vpt;i++){
        int c = i*128 + threadIdx.x;
        storev(&yr[c], (v[i]-mu)*rstd*g[c] + b[c]);
    }
}

// ---------------- fused: tx = concat(ch)+crossln; lnw = half(LN2(tx)) ---------
__global__ void tx_ln_kernel(const float* __restrict__ ch, const float* __restrict__ cl,
                             const float* __restrict__ g, const float* __restrict__ b,
                             float* __restrict__ tx, __half* __restrict__ y){
    long row = blockIdx.x;
    const float* clr = cl + row*C2;
    float v[6];
    float s=0.f, s2=0.f;
    #pragma unroll
    for(int i=0;i<6;i++){
        int c = i*128 + threadIdx.x;
        float base = (c < DD) ? ch[row*DD + c] : ch[((long)T_TOK + row)*DD + c - DD];
        float t = base + clr[c];
        v[i]=t; s+=t; s2+=t*t;
    }
    __shared__ float sh[32];
    s  = blockSum(s, sh);
    s2 = blockSum(s2, sh);
    float mu = s / (float)C2;
    float var = s2 / (float)C2 - mu*mu;
    float rstd = rsqrtf(var + 1e-5f);
    float* txr = tx + row*C2;
    __half* yr  = y + row*C2;
    #pragma unroll
    for(int i=0;i<6;i++){
        int c = i*128 + threadIdx.x;
        txr[c] = v[i];
        yr[c] = __float2half_rn((v[i]-mu)*rstd*g[c] + b[c]);
    }
}

// ---------------- L2-norm over tokens + transpose to [S,B,h,d,N] --------------
__global__ void l2norm_qk_kernel(const float* __restrict__ qkv,
                                 float* __restrict__ qn, float* __restrict__ kn){
    int idx = blockIdx.x;
    int stream = idx / (2*BB*HEADS*HD);
    int rest = idx % (2*BB*HEADS*HD);
    int which = rest / (BB*HEADS*HD);     // 0 = q, 1 = k
    int r = rest % (BB*HEADS*HD);
    int b = r / (HEADS*HD);
    int hj = r % (HEADS*HD);
    int col = which*DD + hj;
    const float* base = qkv + ((long)stream*T_TOK + (long)b*NN_TOK)*1152 + col;
    float v[4]; float s=0.f;
    #pragma unroll
    for(int i=0;i<4;i++){
        int n = threadIdx.x + i*256;
        float t = base[(long)n*1152];
        v[i]=t; s+=t*t;
    }
    __shared__ float sh[32];
    s = blockSum(s, sh);
    float nrm = sqrtf(s);
    float scale = 1.0f / fmaxf(nrm, 1e-12f);
    float* out = (which==0 ? qn : kn)
               + ((long)stream*BB*HEADS*HD + (long)b*(HEADS*HD) + hj)*NN_TOK;
    #pragma unroll
    for(int i=0;i<4;i++){
        int n = threadIdx.x + i*256;
        out[n] = v[i]*scale;
    }
}

// ---------------- attn logits: split-K partials (no atomics) ------------------
__global__ __launch_bounds__(256) void qk_kernel(const float* __restrict__ qn,
                                                 const float* __restrict__ kn,
                                                 float* __restrict__ attnp){
    int bh = blockIdx.y;
    int s = blockIdx.x;
    const float* q = qn + (long)bh*HD*NN_TOK;
    const float* k = kn + (long)bh*HD*NN_TOK;
    __shared__ float qs[48*65];
    __shared__ float ks[48*65];
    int tid = threadIdx.x;
    int tx = tid & 15, ty = tid >> 4;
    float acc[3][3];
    #pragma unroll
    for(int r=0;r<3;r++)
        #pragma unroll
        for(int c=0;c<3;c++) acc[r][c]=0.f;

    for(int sub=0; sub<2; sub++){
        int n0 = s*128 + sub*64;
        __syncthreads();
        #pragma unroll
        for(int i=0;i<12;i++){
            int e = tid + i*256;
            int rr = e>>6, cc = e&63;
            qs[rr*65+cc] = q[rr*NN_TOK + n0 + cc];
            ks[rr*65+cc] = k[rr*NN_TOK + n0 + cc];
        }
        __syncthreads();
        #pragma unroll 4
        for(int kk=0;kk<64;kk++){
            float qv[3], kv[3];
            #pragma unroll
            for(int r=0;r<3;r++) qv[r] = qs[(ty*3+r)*65 + kk];
            #pragma unroll
            for(int c=0;c<3;c++) kv[c] = ks[(tx*3+c)*65 + kk];
            #pragma unroll
            for(int r=0;r<3;r++)
                #pragma unroll
                for(int c=0;c<3;c++) acc[r][c] = fmaf(qv[r], kv[c], acc[r][c]);
        }
    }
    float* ab = attnp + ((long)s*(2*BB*HEADS) + bh)*2304;
    #pragma unroll
    for(int r=0;r<3;r++)
        #pragma unroll
        for(int c=0;c<3;c++)
            ab[(ty*3+r)*48 + tx*3+c] = acc[r][c];
}

// ---------------- softmax over last-48: reduce 8 partials, temp, softmax ------
__global__ void softmax_attn_kernel(const float* __restrict__ attnp,
                                    float* __restrict__ attn,
                                    const float* __restrict__ temp){
    int row = blockIdx.x;
    int bh = row / HD;
    int h = bh & (HEADS-1);
    float t = temp[h];
    int tid = threadIdx.x;
    float v = -INFINITY;
    if(tid < HD){
        float s = 0.f;
        #pragma unroll
        for(int p=0;p<8;p++)
            s += attnp[((long)p*(2*BB*HEADS) + bh)*2304 + (row % HD)*48 + tid];
        v = s * t;
    }
    __shared__ float sh[32];
    float m = blockMax(v, sh);
    float e = (tid<HD) ? expf(v - m) : 0.f;
    float s = blockSum(e, sh);
    if(tid<HD) attn[(long)row*HD + tid] = e / s;
}

// ---------------- attn @ v, chunked over tokens -------------------------------
__global__ __launch_bounds__(256) void pv_kernel(const float* __restrict__ attn,
                                                 const float* __restrict__ qkv,
                                                 __half* __restrict__ out){
    int bh2 = blockIdx.y;
    int n0 = blockIdx.x * 64;
    int stream = bh2 >> 7;
    int bh = bh2 & 127;
    int b = bh >> 3, h = bh & 7;
    long tokbase = (long)stream*T_TOK + (long)b*NN_TOK;
    __shared__ float as[48*49];
    __shared__ float vs[64*49];
    int tid = threadIdx.x;
    for(int i=tid;i<2304;i+=256){
        int r = i/48, c = i%48;
        as[r*49+c] = attn[(long)bh2*2304 + i];
    }
    const float* vbase = qkv + tokbase*1152 + 2*DD + h*HD;
    #pragma unroll
    for(int i=0;i<12;i++){
        int e = tid + i*256;
        int nn = e/48, j = e%48;
        vs[nn*49+j] = vbase[(long)(n0+nn)*1152 + j];
    }
    __syncthreads();
    int tx = tid & 15;
    int ty = tid >> 4;
    float acc[4][3];
    #pragma unroll
    for(int s=0;s<4;s++)
        #pragma unroll
        for(int r=0;r<3;r++) acc[s][r]=0.f;
    #pragma unroll 4
    for(int j=0;j<48;j++){
        float av[3], vv[4];
        #pragma unroll
        for(int r=0;r<3;r++) av[r] = as[(tx*3+r)*49 + j];
        #pragma unroll
        for(int s=0;s<4;s++) vv[s] = vs[(ty*4+s)*49 + j];
        #pragma unroll
        for(int s=0;s<4;s++)
            #pragma unroll
            for(int r=0;r<3;r++) acc[s][r] = fmaf(av[r], vv[s], acc[s][r]);
    }
    #pragma unroll
    for(int s=0;s<4;s++)
        #pragma unroll
        for(int r=0;r<3;r++)
            out[(tokbase + n0 + ty*4+s)*DD + h*HD + tx*3 + r] = __float2half_rn(acc[s][r]);
}

// ---------------- column softmax (over tokens) -> key half --------------------
__global__ void colsoftmax_kernel(const __half* __restrict__ x, __half* __restrict__ key){
    int idx = blockIdx.x;
    int b = idx / DD, d = idx % DD;
    const __half* base = x + (long)b*NN_TOK*DD + d;
    float v[4]; float m = -INFINITY;
    #pragma unroll
    for(int i=0;i<4;i++){
        int n = threadIdx.x + i*256;
        float t = __half2float(base[(long)n*DD]);
        v[i]=t; m = fmaxf(m,t);
    }
    __shared__ float sh[32];
    m = blockMax(m, sh);
    float s = 0.f;
    #pragma unroll
    for(int i=0;i<4;i++){ v[i] = expf(v[i]-m); s += v[i]; }
    s = blockSum(s, sh);
    float inv = 1.0f / s;
    __half* out = key + ((long)b*DD + d)*NN_TOK;
    #pragma unroll
    for(int i=0;i<4;i++) out[threadIdx.x + i*256] = __float2half_rn(v[i]*inv);
}

// ---------------- row softmax (over channels) -> query half -------------------
__global__ void rowsoftmax_kernel(const __half* __restrict__ x, __half* __restrict__ y){
    long row = blockIdx.x;
    const __half* xr = x + row*DD;
    float v[3]; float m = -INFINITY;
    #pragma unroll
    for(int i=0;i<3;i++){
        float t = __half2float(xr[i*128 + threadIdx.x]);
        v[i]=t; m=fmaxf(m,t);
    }
    __shared__ float sh[32];
    m = blockMax(m, sh);
    float s=0.f;
    #pragma unroll
    for(int i=0;i<3;i++){ v[i]=expf(v[i]-m); s+=v[i]; }
    s = blockSum(s, sh);
    float inv = 1.0f/s;
    __half* yr = y + row*DD;
    #pragma unroll
    for(int i=0;i<3;i++) yr[i*128 + threadIdx.x] = __float2half_rn(v[i]*inv);
}

// ---------------- depthwise 3x3 + exact GELU -> half --------------------------
__global__ void dwconv_gelu_kernel(const float* __restrict__ h1, const float* __restrict__ w,
                                   const float* __restrict__ bias, __half* __restrict__ h2){
    int c = blockIdx.x*blockDim.x + threadIdx.x;
    int y = blockIdx.y, b = blockIdx.z;
    const float* rowc = h1 + ((long)b*NN_TOK + y*32)*C4 + c;
    const float* rowm = rowc - 32*C4;
    const float* rowp = rowc + 32*C4;
    bool ym = (y > 0), yp = (y < 31);
    const float* wc = w + c*9;
    float w0=wc[0],w1=wc[1],w2=wc[2],w3=wc[3],w4=wc[4],w5=wc[5],w6=wc[6],w7=wc[7],w8=wc[8];
    float bs = bias[c];
    __half* outr = h2 + ((long)b*NN_TOK + y*32)*C4 + c;

    float pt=0.f, pm=0.f, pb=0.f;
    float ct = ym ? rowm[0] : 0.f;
    float cm = rowc[0];
    float cb = yp ? rowp[0] : 0.f;
    #pragma unroll 4
    for(int x=0;x<32;x++){
        float nt=0.f, nm=0.f, nb=0.f;
        if(x < 31){
            long o = (long)(x+1)*C4;
            nt = ym ? rowm[o] : 0.f;
            nm = rowc[o];
            nb = yp ? rowp[o] : 0.f;
        }
        float acc = bs;
        acc = fmaf(pt,w0,acc); acc = fmaf(ct,w1,acc); acc = fmaf(nt,w2,acc);
        acc = fmaf(pm,w3,acc); acc = fmaf(cm,w4,acc); acc = fmaf(nm,w5,acc);
        acc = fmaf(pb,w6,acc); acc = fmaf(cb,w7,acc); acc = fmaf(nb,w8,acc);
        float g = 0.5f*acc*(1.f + erff(acc*0.70710678118654752f));
        outr[(long)x*C4] = __float2half_rn(g);
        pt=ct; pm=cm; pb=cb; ct=nt; cm=nm; cb=nb;
    }
}

// ---------------- 3-stage cp.async fp16 GEMM (m16n8k16 + ldmatrix) ------------
// C = A@B (+bias)(+res); A,B half; C float or half (OUTH).
// 128x128x64 tile, 3 stages, 256 threads, warp tile 32x64.
// M%128==0, N%128==0, K%64==0, lda/ldb % 8 == 0.
#define ASTH 72                    // halfs per A row (64 + 8 pad); 144B, 16B-mult
#define BSTH 136                   // halfs per B row (128 + 8 pad); 272B
#define A_STAGEH (128*ASTH)        // 9216 halfs
#define B_STAGEH (64*BSTH)         // 8704 halfs
#define STAGEH (A_STAGEH + B_STAGEH)
#define SMEM_GEMM (3*STAGEH*2)     // 107520 bytes

template<bool BIAS, bool RES, bool OUTH>
__global__ __launch_bounds__(256,2)
void mma_gemm_kernel(const __half* __restrict__ A, const __half* __restrict__ Bm,
                     const float* __restrict__ bias, const float* __restrict__ res,
                     void* __restrict__ Cv,
                     int M, int N, int K, int lda, int ldb, int ldc,
                     long long sA, long long sB, long long sC){
    int bz = blockIdx.z;
    A  += (long long)bz*sA;
    Bm += (long long)bz*sB;
    float* Cf = (float*)Cv + (OUTH ? 0 : (long long)bz*sC);
    __half* Ch = (__half*)Cv + (OUTH ? (long long)bz*sC : 0);
    const float* R = RES ? res + (long long)bz*sC : nullptr;

    extern __shared__ __align__(16) __half hsm[];   // [3][STAGEH]

    const int rowT = blockIdx.y*128, colT = blockIdx.x*128;
    const int tid = threadIdx.x;
    const int warp = tid >> 5, lane = tid & 31;
    const int grp = lane >> 2, tg = lane & 3;
    const int warpRow = (warp & 3) * 32;
    const int warpCol = (warp >> 2) * 64;

    // cp.async coordinates: A 128 rows x 8 chunks(16B); B 64 rows x 16 chunks
    const int a_r = tid & 127, a_cb = (tid >> 7) * 4;   // 4 chunks each
    const int b_r = tid & 63,  b_cb = (tid >> 6) * 4;

    const int nIt = K >> 6;

    auto issue = [&](int it, int st){
        int k0 = it << 6;
        __half* Ad = hsm + st*STAGEH;
        __half* Bd = Ad + A_STAGEH;
        #pragma unroll
        for(int i=0;i<4;i++){
            int c8 = (a_cb + i) * 8;
            cp16((uint32_t)__cvta_generic_to_shared(&Ad[a_r*ASTH + c8]),
                 &A[(long)(rowT+a_r)*lda + k0 + c8]);
        }
        #pragma unroll
        for(int i=0;i<4;i++){
            int c8 = (b_cb + i) * 8;
            cp16((uint32_t)__cvta_generic_to_shared(&Bd[b_r*BSTH + c8]),
                 &Bm[(long)(k0+b_r)*ldb + colT + c8]);
        }
        cp_commit();
    };

    float acc[2][8][4];
    #pragma unroll
    for(int mi=0;mi<2;mi++)
        #pragma unroll
        for(int ni=0;ni<8;ni++)
            #pragma unroll
            for(int t=0;t<4;t++) acc[mi][ni][t]=0.f;

    issue(0, 0);
    if(nIt > 1) issue(1, 1);
    int st = 0;
    for(int it=0; it<nIt; it++){
        if(it+2 < nIt){
            int s2 = st+2; if(s2>=3) s2-=3;
            issue(it+2, s2);
            cp_wait2();
        } else if(it+1 < nIt){
            cp_wait1();
        } else {
            cp_wait0();
        }
        __syncthreads();
        const __half* Ac = hsm + st*STAGEH;
        const __half* Bc = Ac + A_STAGEH;
        uint32_t a_base = (uint32_t)__cvta_generic_to_shared(Ac);
        uint32_t b_base = (uint32_t)__cvta_generic_to_shared(Bc);
        #pragma unroll
        for(int kk=0;kk<4;kk++){
            uint32_t a[2][4], b[4][4];
            #pragma unroll
            for(int mi=0;mi<2;mi++){
                uint32_t addr = a_base +
                    ((warpRow + mi*16 + (lane & 15))*ASTH + kk*16 + (lane >> 4)*8)*2;
                ldsm4(a[mi], addr);
            }
            #pragma unroll
            for(int np=0;np<4;np++){
                uint32_t addr = b_base +
                    ((kk*16 + (lane & 15))*BSTH + warpCol + np*16 + (lane >> 4)*8)*2;
                ldsm4t(b[np], addr);
            }
            #pragma unroll
            for(int mi=0;mi<2;mi++)
                #pragma unroll
                for(int np=0;np<4;np++){
                    mma_f16(acc[mi][np*2+0], a[mi], &b[np][0]);
                    mma_f16(acc[mi][np*2+1], a[mi], &b[np][2]);
                }
        }
        __syncthreads();
        if(++st == 3) st = 0;
    }

    // epilogue
    #pragma unroll
    for(int mi=0;mi<2;mi++){
        #pragma unroll
        for(int ni=0;ni<8;ni++){
            int r0 = rowT + warpRow + mi*16 + grp;
            int col = colT + warpCol + ni*8 + tg*2;
            float2 o0, o1;
            o0.x = acc[mi][ni][0]; o0.y = acc[mi][ni][1];
            o1.x = acc[mi][ni][2]; o1.y = acc[mi][ni][3];
            if(BIAS){
                float b0 = bias[col], b1 = bias[col+1];
                o0.x += b0; o0.y += b1;
                o1.x += b0; o1.y += b1;
            }
            if(RES){
                const float2 r0v = *(const float2*)&R[(long)r0*ldc + col];
                const float2 r1v = *(const float2*)&R[(long)(r0+8)*ldc + col];
                o0.x += r0v.x; o0.y += r0v.y;
                o1.x += r1v.x; o1.y += r1v.y;
            }
            if(OUTH){
                __half2 h0 = __floats2half2_rn(o0.x, o0.y);
                __half2 h1 = __floats2half2_rn(o1.x, o1.y);
                *(__half2*)&Ch[(long)r0*ldc + col] = h0;
                *(__half2*)&Ch[(long)(r0+8)*ldc + col] = h1;
            }else{
                *(float2*)&Cf[(long)r0*ldc + col] = o0;
                *(float2*)&Cf[(long)(r0+8)*ldc + col] = o1;
            }
        }
    }
}

// ---------------- host side ---------------------------------------------------
static void* symaddr(const void* sym){
    void* p = nullptr;
    cudaGetSymbolAddress(&p, sym);
    return p;
}

extern "C" void kernel_launch(void* const* d_in, const int* in_sizes, int n_in,
                              void* d_out, int out_size){
    const float* x1       = (const float*)d_in[0];
    const float* x2       = (const float*)d_in[1];
    const float* ln1_g    = (const float*)d_in[2];
    const float* ln1_b    = (const float*)d_in[3];
    const float* ca_qkv_w = (const float*)d_in[4];
    const float* ca_temp  = (const float*)d_in[5];
    const float* ca_proj_w= (const float*)d_in[6];
    const float* ca_proj_b= (const float*)d_in[7];
    const float* ln3_g    = (const float*)d_in[8];
    const float* ln3_b    = (const float*)d_in[9];
    const float* rp_w     = (const float*)d_in[10];
    const float* rp_b     = (const float*)d_in[11];
    const float* cn_g     = (const float*)d_in[12];
    const float* cn_b     = (const float*)d_in[13];
    const float* ln2_g    = (const float*)d_in[14];
    const float* ln2_b    = (const float*)d_in[15];
    const float* fc1_w    = (const float*)d_in[16];
    const float* fc1_b    = (const float*)d_in[17];
    const float* dw_w     = (const float*)d_in[18];
    const float* dw_b     = (const float*)d_in[19];
    const float* fc2_w    = (const float*)d_in[20];
    const float* fc2_b    = (const float*)d_in[21];
    float* out = (float*)d_out;

    float*  p_x      = (float*) symaddr(g_x);
    __half* p_ln     = (__half*)symaddr(g_ln);
    __half* p_lnw    = (__half*)symaddr(g_lnw);
    float*  p_qkv    = (float*) symaddr(g_qkv);
    float*  p_qn     = (float*) symaddr(g_qn);
    float*  p_kn     = (float*) symaddr(g_kn);
    float*  p_attnp  = (float*) symaddr(g_attnp);
    float*  p_attn   = (float*) symaddr(g_attn);
    __half* p_attnout= (__half*)symaddr(g_attnout);
    float*  p_ch     = (float*) symaddr(g_ch);
    __half* p_n      = (__half*)symaddr(g_n);
    __half* p_key    = (__half*)symaddr(g_key);
    __half* p_query  = (__half*)symaddr(g_query);
    __half* p_ctx    = (__half*)symaddr(g_ctx);
    __half* p_att2   = (__half*)symaddr(g_att2);
    float*  p_rep    = (float*) symaddr(g_rep);
    float*  p_crossln= (float*) symaddr(g_crossln);
    float*  p_tx     = (float*) symaddr(g_tx);
    float*  p_h1     = (float*) symaddr(g_h1);
    __half* p_h2     = (__half*)symaddr(g_h2);
    __half* p_wqkv   = (__half*)symaddr(g_wqkv);
    __half* p_wproj  = (__half*)symaddr(g_wproj);
    __half* p_wrpT   = (__half*)symaddr(g_wrpT);
    __half* p_wfc1   = (__half*)symaddr(g_wfc1);
    __half* p_wfc2   = (__half*)symaddr(g_wfc2);

    cudaFuncSetAttribute(mma_gemm_kernel<false,false,false>, cudaFuncAttributeMaxDynamicSharedMemorySize, SMEM_GEMM);
    cudaFuncSetAttribute(mma_gemm_kernel<true ,true ,false>, cudaFuncAttributeMaxDynamicSharedMemorySize, SMEM_GEMM);
    cudaFuncSetAttribute(mma_gemm_kernel<false,false,true >, cudaFuncAttributeMaxDynamicSharedMemorySize, SMEM_GEMM);
    cudaFuncSetAttribute(mma_gemm_kernel<true ,false,false>, cudaFuncAttributeMaxDynamicSharedMemorySize, SMEM_GEMM);

    // ---- pack + weight prep ----
    pack_kernel<<<(T2*DD/4)/256, 256>>>(x1, x2, p_x);
    cvt4_kernel<<<(NW1+NW2+NW3+NW4+255)/256, 256>>>(
        ca_qkv_w, p_wqkv, ca_proj_w, p_wproj, fc1_w, p_wfc1, fc2_w, p_wfc2);
    transpose_cvt_kernel<<<dim3(DD/32, C2/32), dim3(32,8)>>>(rp_w, p_wrpT);

    // ---- channel attention, both streams batched ----
    ln_kernel<__half><<<T2, 128>>>(p_x, ln1_g, ln1_b, p_ln, DD);

    mma_gemm_kernel<false,false,false><<<dim3(1152/128, T2/128, 1), 256, SMEM_GEMM>>>(
        p_ln, p_wqkv, nullptr, nullptr, p_qkv,
        T2, 1152, DD, DD, 1152, 1152, 0, 0, 0);

    l2norm_qk_kernel<<<2*2*BB*HEADS*HD, 256>>>(p_qkv, p_qn, p_kn);
    qk_kernel<<<dim3(8, 2*BB*HEADS), 256>>>(p_qn, p_kn, p_attnp);
    softmax_attn_kernel<<<2*BB*HEADS*HD, 64>>>(p_attnp, p_attn, ca_temp);
    pv_kernel<<<dim3(16, 2*BB*HEADS), 256>>>(p_attn, p_qkv, p_attnout);

    mma_gemm_kernel<true,true,false><<<dim3(DD/128, T2/128, 1), 256, SMEM_GEMM>>>(
        p_attnout, p_wproj, ca_proj_b, p_x, p_ch,
        T2, DD, DD, DD, DD, DD, 0, 0, 0);

    // ---- ln3 (both streams) -> half ----
    ln_kernel<__half><<<T2, 128>>>(p_ch, ln3_g, ln3_b, p_n, DD);
    __half* p_n1 = p_n;
    __half* p_n2 = p_n + (size_t)T_TOK*DD;

    // ---- cross attention ----
    colsoftmax_kernel<<<BB*DD, 256>>>(p_n2, p_key);
    rowsoftmax_kernel<<<T_TOK, 128>>>(p_n2, p_query);

    // ctx[b] = key[b] (D x N) @ n1[b] (N x D) -> half
    mma_gemm_kernel<false,false,true><<<dim3(DD/128, DD/128, BB), 256, SMEM_GEMM>>>(
        p_key, p_n1, nullptr, nullptr, p_ctx,
        DD, DD, NN_TOK, NN_TOK, DD, DD,
        (long long)DD*NN_TOK, (long long)NN_TOK*DD, (long long)DD*DD);

    // att2[b] = query[b] (N x D) @ ctx[b] (D x D) -> half
    mma_gemm_kernel<false,false,true><<<dim3(DD/128, NN_TOK/128, BB), 256, SMEM_GEMM>>>(
        p_query, p_ctx, nullptr, nullptr, p_att2,
        NN_TOK, DD, DD, DD, DD, DD,
        (long long)NN_TOK*DD, (long long)DD*DD, (long long)NN_TOK*DD);

    // rep = att2 (T x 384) @ rpT (384 x 768) + rp_b -> float
    mma_gemm_kernel<true,false,false><<<dim3(C2/128, T_TOK/128, 1), 256, SMEM_GEMM>>>(
        p_att2, p_wrpT, rp_b, nullptr, p_rep,
        T_TOK, C2, DD, DD, C2, C2, 0, 0, 0);

    ln_kernel<float><<<T_TOK, 128>>>(p_rep, cn_g, cn_b, p_crossln, C2);

    // ---- fused tx = concat+cross, ln2 -> half ----
    tx_ln_kernel<<<T_TOK, 128>>>(p_ch, p_crossln, ln2_g, ln2_b, p_tx, p_lnw);

    // ---- MixFFN ----
    mma_gemm_kernel<true,false,false><<<dim3(C4/128, T_TOK/128, 1), 256, SMEM_GEMM>>>(
        p_lnw, p_wfc1, fc1_b, nullptr, p_h1,
        T_TOK, C4, C2, C2, C4, C4, 0, 0, 0);

    dwconv_gelu_kernel<<<dim3(C4/256, 32, BB), 256>>>(p_h1, dw_w, dw_b, p_h2);

    mma_gemm_kernel<true,true,false><<<dim3(C2/128, T_TOK/128, 1), 256, SMEM_GEMM>>>(
        p_h2, p_wfc2, fc2_b, p_tx, out,
        T_TOK, C2, C4, C4, C2, C2, 0, 0, 0);
}

// round 9
// speedup vs baseline: 3.9723x; 1.0008x over previous
#include <cuda_runtime.h>
#include <cuda_fp16.h>
#include <math.h>
#include <stdint.h>

// Problem constants
#define BB 16
#define NN_TOK 1024
#define DD 384
#define C2 768
#define C4 1536
#define HEADS 8
#define HD 48
#define T_TOK (BB*NN_TOK)      // 16384
#define T2 (2*T_TOK)           // 32768 (both streams)

// ---------------- scratch (device globals; no allocation allowed) -------------
__device__ float  g_x[(size_t)T2*DD];              // packed x1 || x2 (fp32, residual)
__device__ __half g_ln[(size_t)T2*DD];             // ln1 outputs (half, GEMM A)
__device__ __half g_lnw[(size_t)T_TOK*C2];         // ln2 output (half, GEMM A)
__device__ float  g_qkv[(size_t)T2*1152];
__device__ float  g_qn[(size_t)2*BB*HEADS*HD*NN_TOK];
__device__ float  g_kn[(size_t)2*BB*HEADS*HD*NN_TOK];
__device__ float  g_attnp[(size_t)8*2*BB*HEADS*HD*HD];
__device__ float  g_attn[(size_t)2*BB*HEADS*HD*HD];
__device__ __half g_attnout[(size_t)T2*DD];        // half (GEMM A)
__device__ float  g_ch[(size_t)T2*DD];             // channel1 || channel2
__device__ __half g_n[(size_t)T2*DD];              // n1 || n2 (half)
__device__ __half g_key[(size_t)BB*DD*NN_TOK];     // [B,D,N] half
__device__ __half g_query[(size_t)T_TOK*DD];       // half
__device__ __half g_ctx[(size_t)BB*DD*DD];         // half (GEMM out+in)
__device__ __half g_att2[(size_t)T_TOK*DD];        // half
__device__ float  g_rep[(size_t)T_TOK*C2];
__device__ float  g_crossln[(size_t)T_TOK*C2];
__device__ float  g_tx[(size_t)T_TOK*C2];
__device__ float  g_h1[(size_t)T_TOK*C4];
__device__ __half g_h2[(size_t)T_TOK*C4];          // half (GEMM A)
// pre-converted / pre-transposed weights (half)
__device__ __half g_wqkv[(size_t)DD*1152];
__device__ __half g_wproj[(size_t)DD*DD];
__device__ __half g_wrpT[(size_t)DD*C2];
__device__ __half g_wfc1[(size_t)C2*C4];
__device__ __half g_wfc2[(size_t)C4*C2];

// ---------------- reductions -------------------------------------------------
__device__ __forceinline__ float warpSum(float v){
    #pragma unroll
    for(int o=16;o>0;o>>=1) v += __shfl_down_sync(0xffffffffu, v, o);
    return v;
}
__device__ __forceinline__ float warpMax(float v){
    #pragma unroll
    for(int o=16;o>0;o>>=1) v = fmaxf(v, __shfl_down_sync(0xffffffffu, v, o));
    return v;
}
__device__ __forceinline__ float blockSum(float v, float* sh){
    int lane = threadIdx.x & 31, wid = threadIdx.x >> 5;
    v = warpSum(v);
    if(lane==0) sh[wid]=v;
    __syncthreads();
    int nw = blockDim.x >> 5;
    float r = (threadIdx.x < (unsigned)nw) ? sh[threadIdx.x] : 0.f;
    if(wid==0){ r = warpSum(r); if(lane==0) sh[0]=r; }
    __syncthreads();
    r = sh[0];
    __syncthreads();
    return r;
}
__device__ __forceinline__ float blockMax(float v, float* sh){
    int lane = threadIdx.x & 31, wid = threadIdx.x >> 5;
    v = warpMax(v);
    if(lane==0) sh[wid]=v;
    __syncthreads();
    int nw = blockDim.x >> 5;
    float r = (threadIdx.x < (unsigned)nw) ? sh[threadIdx.x] : -INFINITY;
    if(wid==0){ r = warpMax(r); if(lane==0) sh[0]=r; }
    __syncthreads();
    r = sh[0];
    __syncthreads();
    return r;
}

// ---------------- mma / ldmatrix / cp.async helpers ---------------------------
__device__ __forceinline__ void mma_f16(float* c, const uint32_t* a, const uint32_t* b){
    asm volatile(
        "mma.sync.aligned.m16n8k16.row.col.f32.f16.f16.f32 "
        "{%0,%1,%2,%3}, {%4,%5,%6,%7}, {%8,%9}, {%0,%1,%2,%3};\n"
        : "+f"(c[0]), "+f"(c[1]), "+f"(c[2]), "+f"(c[3])
        : "r"(a[0]), "r"(a[1]), "r"(a[2]), "r"(a[3]),
          "r"(b[0]), "r"(b[1]));
}
__device__ __forceinline__ void ldsm4(uint32_t* r, uint32_t addr){
    asm volatile("ldmatrix.sync.aligned.m8n8.x4.shared.b16 {%0,%1,%2,%3}, [%4];\n"
                 : "=r"(r[0]), "=r"(r[1]), "=r"(r[2]), "=r"(r[3]) : "r"(addr));
}
__device__ __forceinline__ void ldsm4t(uint32_t* r, uint32_t addr){
    asm volatile("ldmatrix.sync.aligned.m8n8.x4.trans.shared.b16 {%0,%1,%2,%3}, [%4];\n"
                 : "=r"(r[0]), "=r"(r[1]), "=r"(r[2]), "=r"(r[3]) : "r"(addr));
}
__device__ __forceinline__ void cp16(uint32_t s, const void* g){
    asm volatile("cp.async.cg.shared.global [%0], [%1], 16;\n" :: "r"(s), "l"(g));
}
__device__ __forceinline__ void cp_commit(){ asm volatile("cp.async.commit_group;\n"); }
__device__ __forceinline__ void cp_wait2(){ asm volatile("cp.async.wait_group 2;\n"); }
__device__ __forceinline__ void cp_wait1(){ asm volatile("cp.async.wait_group 1;\n"); }
__device__ __forceinline__ void cp_wait0(){ asm volatile("cp.async.wait_group 0;\n"); }

__device__ __forceinline__ void storev(float* p, float v){ *p = v; }
__device__ __forceinline__ void storev(__half* p, float v){ *p = __float2half_rn(v); }

// ---------------- pack x1||x2 -------------------------------------------------
__global__ void pack_kernel(const float* __restrict__ x1, const float* __restrict__ x2,
                            float* __restrict__ x){
    long i = ((long)blockIdx.x*blockDim.x + threadIdx.x)*4;
    const long half_ = (long)T_TOK*DD;
    float4 v = (i < half_) ? *(const float4*)&x1[i] : *(const float4*)&x2[i-half_];
    *(float4*)&x[i] = v;
}

// ---------------- weight prep: convert 4 weight matrices to half --------------
#define NW1 (DD*1152)
#define NW2 (DD*DD)
#define NW3 (C2*C4)
#define NW4 (C4*C2)
__global__ void cvt4_kernel(const float* __restrict__ a, __half* __restrict__ oa,
                            const float* __restrict__ b, __half* __restrict__ ob,
                            const float* __restrict__ c, __half* __restrict__ oc,
                            const float* __restrict__ d, __half* __restrict__ od){
    int i = blockIdx.x*blockDim.x + threadIdx.x;
    if(i < NW1){ oa[i] = __float2half_rn(a[i]); return; }
    i -= NW1;
    if(i < NW2){ ob[i] = __float2half_rn(b[i]); return; }
    i -= NW2;
    if(i < NW3){ oc[i] = __float2half_rn(c[i]); return; }
    i -= NW3;
    if(i < NW4){ od[i] = __float2half_rn(d[i]); }
}
// rp_w [768][384] -> rpT [384][768], half
__global__ void transpose_cvt_kernel(const float* __restrict__ in, __half* __restrict__ out){
    __shared__ float t[32][33];
    int k0 = blockIdx.x*32, n0 = blockIdx.y*32;
    int tx = threadIdx.x, ty = threadIdx.y;   // 32 x 8
    #pragma unroll
    for(int j=0;j<4;j++) t[ty+8*j][tx] = in[(n0+ty+8*j)*DD + k0+tx];
    __syncthreads();
    #pragma unroll
    for(int j=0;j<4;j++) out[(k0+ty+8*j)*C2 + n0+tx] = __float2half_rn(t[tx][ty+8*j]);
}

// ---------------- LayerNorm (W = 384 or 768; block=128) ----------------------
template<typename OUT>
__global__ void ln_kernel(const float* __restrict__ x, const float* __restrict__ g,
                          const float* __restrict__ b, OUT* __restrict__ y, int W){
    long row = blockIdx.x;
    const float* xr = x + row*(long)W;
    int vpt = W >> 7;
    float v[6];
    float s=0.f, s2=0.f;
    for(int i=0;i<vpt;i++){
        float t = xr[i*128 + threadIdx.x];
        v[i]=t; s+=t; s2+=t*t;
    }
    __shared__ float sh[32];
    s  = blockSum(s, sh);
    s2 = blockSum(s2, sh);
    float mu = s / (float)W;
    float var = s2 / (float)W - mu*mu;
    float rstd = rsqrtf(var + 1e-5f);
    OUT* yr = y + row*(long)W;
    for(int i=0;i<vpt;i++){
        int c = i*128 + threadIdx.x;
        storev(&yr[c], (v[i]-mu)*rstd*g[c] + b[c]);
    }
}

// ---------------- fused: tx = concat(ch)+crossln; lnw = half(LN2(tx)) ---------
__global__ void tx_ln_kernel(const float* __restrict__ ch, const float* __restrict__ cl,
                             const float* __restrict__ g, const float* __restrict__ b,
                             float* __restrict__ tx, __half* __restrict__ y){
    long row = blockIdx.x;
    const float* clr = cl + row*C2;
    float v[6];
    float s=0.f, s2=0.f;
    #pragma unroll
    for(int i=0;i<6;i++){
        int c = i*128 + threadIdx.x;
        float base = (c < DD) ? ch[row*DD + c] : ch[((long)T_TOK + row)*DD + c - DD];
        float t = base + clr[c];
        v[i]=t; s+=t; s2+=t*t;
    }
    __shared__ float sh[32];
    s  = blockSum(s, sh);
    s2 = blockSum(s2, sh);
    float mu = s / (float)C2;
    float var = s2 / (float)C2 - mu*mu;
    float rstd = rsqrtf(var + 1e-5f);
    float* txr = tx + row*C2;
    __half* yr  = y + row*C2;
    #pragma unroll
    for(int i=0;i<6;i++){
        int c = i*128 + threadIdx.x;
        txr[c] = v[i];
        yr[c] = __float2half_rn((v[i]-mu)*rstd*g[c] + b[c]);
    }
}

// ---------------- L2-norm over tokens + transpose to [S,B,h,d,N] --------------
__global__ void l2norm_qk_kernel(const float* __restrict__ qkv,
                                 float* __restrict__ qn, float* __restrict__ kn){
    int idx = blockIdx.x;
    int stream = idx / (2*BB*HEADS*HD);
    int rest = idx % (2*BB*HEADS*HD);
    int which = rest / (BB*HEADS*HD);     // 0 = q, 1 = k
    int r = rest % (BB*HEADS*HD);
    int b = r / (HEADS*HD);
    int hj = r % (HEADS*HD);
    int col = which*DD + hj;
    const float* base = qkv + ((long)stream*T_TOK + (long)b*NN_TOK)*1152 + col;
    float v[4]; float s=0.f;
    #pragma unroll
    for(int i=0;i<4;i++){
        int n = threadIdx.x + i*256;
        float t = base[(long)n*1152];
        v[i]=t; s+=t*t;
    }
    __shared__ float sh[32];
    s = blockSum(s, sh);
    float nrm = sqrtf(s);
    float scale = 1.0f / fmaxf(nrm, 1e-12f);
    float* out = (which==0 ? qn : kn)
               + ((long)stream*BB*HEADS*HD + (long)b*(HEADS*HD) + hj)*NN_TOK;
    #pragma unroll
    for(int i=0;i<4;i++){
        int n = threadIdx.x + i*256;
        out[n] = v[i]*scale;
    }
}

// ---------------- attn logits: split-K partials (no atomics) ------------------
__global__ __launch_bounds__(256) void qk_kernel(const float* __restrict__ qn,
                                                 const float* __restrict__ kn,
                                                 float* __restrict__ attnp){
    int bh = blockIdx.y;
    int s = blockIdx.x;
    const float* q = qn + (long)bh*HD*NN_TOK;
    const float* k = kn + (long)bh*HD*NN_TOK;
    __shared__ float qs[48*65];
    __shared__ float ks[48*65];
    int tid = threadIdx.x;
    int tx = tid & 15, ty = tid >> 4;
    float acc[3][3];
    #pragma unroll
    for(int r=0;r<3;r++)
        #pragma unroll
        for(int c=0;c<3;c++) acc[r][c]=0.f;

    for(int sub=0; sub<2; sub++){
        int n0 = s*128 + sub*64;
        __syncthreads();
        #pragma unroll
        for(int i=0;i<12;i++){
            int e = tid + i*256;
            int rr = e>>6, cc = e&63;
            qs[rr*65+cc] = q[rr*NN_TOK + n0 + cc];
            ks[rr*65+cc] = k[rr*NN_TOK + n0 + cc];
        }
        __syncthreads();
        #pragma unroll 4
        for(int kk=0;kk<64;kk++){
            float qv[3], kv[3];
            #pragma unroll
            for(int r=0;r<3;r++) qv[r] = qs[(ty*3+r)*65 + kk];
            #pragma unroll
            for(int c=0;c<3;c++) kv[c] = ks[(tx*3+c)*65 + kk];
            #pragma unroll
            for(int r=0;r<3;r++)
                #pragma unroll
                for(int c=0;c<3;c++) acc[r][c] = fmaf(qv[r], kv[c], acc[r][c]);
        }
    }
    float* ab = attnp + ((long)s*(2*BB*HEADS) + bh)*2304;
    #pragma unroll
    for(int r=0;r<3;r++)
        #pragma unroll
        for(int c=0;c<3;c++)
            ab[(ty*3+r)*48 + tx*3+c] = acc[r][c];
}

// ---------------- softmax over last-48: reduce 8 partials, temp, softmax ------
__global__ void softmax_attn_kernel(const float* __restrict__ attnp,
                                    float* __restrict__ attn,
                                    const float* __restrict__ temp){
    int row = blockIdx.x;
    int bh = row / HD;
    int h = bh & (HEADS-1);
    float t = temp[h];
    int tid = threadIdx.x;
    float v = -INFINITY;
    if(tid < HD){
        float s = 0.f;
        #pragma unroll
        for(int p=0;p<8;p++)
            s += attnp[((long)p*(2*BB*HEADS) + bh)*2304 + (row % HD)*48 + tid];
        v = s * t;
    }
    __shared__ float sh[32];
    float m = blockMax(v, sh);
    float e = (tid<HD) ? expf(v - m) : 0.f;
    float s = blockSum(e, sh);
    if(tid<HD) attn[(long)row*HD + tid] = e / s;
}

// ---------------- attn @ v, chunked over tokens -------------------------------
__global__ __launch_bounds__(256) void pv_kernel(const float* __restrict__ attn,
                                                 const float* __restrict__ qkv,
                                                 __half* __restrict__ out){
    int bh2 = blockIdx.y;
    int n0 = blockIdx.x * 64;
    int stream = bh2 >> 7;
    int bh = bh2 & 127;
    int b = bh >> 3, h = bh & 7;
    long tokbase = (long)stream*T_TOK + (long)b*NN_TOK;
    __shared__ float as[48*49];
    __shared__ float vs[64*49];
    int tid = threadIdx.x;
    for(int i=tid;i<2304;i+=256){
        int r = i/48, c = i%48;
        as[r*49+c] = attn[(long)bh2*2304 + i];
    }
    const float* vbase = qkv + tokbase*1152 + 2*DD + h*HD;
    #pragma unroll
    for(int i=0;i<12;i++){
        int e = tid + i*256;
        int nn = e/48, j = e%48;
        vs[nn*49+j] = vbase[(long)(n0+nn)*1152 + j];
    }
    __syncthreads();
    int tx = tid & 15;
    int ty = tid >> 4;
    float acc[4][3];
    #pragma unroll
    for(int s=0;s<4;s++)
        #pragma unroll
        for(int r=0;r<3;r++) acc[s][r]=0.f;
    #pragma unroll 4
    for(int j=0;j<48;j++){
        float av[3], vv[4];
        #pragma unroll
        for(int r=0;r<3;r++) av[r] = as[(tx*3+r)*49 + j];
        #pragma unroll
        for(int s=0;s<4;s++) vv[s] = vs[(ty*4+s)*49 + j];
        #pragma unroll
        for(int s=0;s<4;s++)
            #pragma unroll
            for(int r=0;r<3;r++) acc[s][r] = fmaf(av[r], vv[s], acc[s][r]);
    }
    #pragma unroll
    for(int s=0;s<4;s++)
        #pragma unroll
        for(int r=0;r<3;r++)
            out[(tokbase + n0 + ty*4+s)*DD + h*HD + tx*3 + r] = __float2half_rn(acc[s][r]);
}

// ---------------- column softmax (over tokens) -> key half --------------------
__global__ void colsoftmax_kernel(const __half* __restrict__ x, __half* __restrict__ key){
    int idx = blockIdx.x;
    int b = idx / DD, d = idx % DD;
    const __half* base = x + (long)b*NN_TOK*DD + d;
    float v[4]; float m = -INFINITY;
    #pragma unroll
    for(int i=0;i<4;i++){
        int n = threadIdx.x + i*256;
        float t = __half2float(base[(long)n*DD]);
        v[i]=t; m = fmaxf(m,t);
    }
    __shared__ float sh[32];
    m = blockMax(m, sh);
    float s = 0.f;
    #pragma unroll
    for(int i=0;i<4;i++){ v[i] = expf(v[i]-m); s += v[i]; }
    s = blockSum(s, sh);
    float inv = 1.0f / s;
    __half* out = key + ((long)b*DD + d)*NN_TOK;
    #pragma unroll
    for(int i=0;i<4;i++) out[threadIdx.x + i*256] = __float2half_rn(v[i]*inv);
}

// ---------------- row softmax (over channels) -> query half -------------------
__global__ void rowsoftmax_kernel(const __half* __restrict__ x, __half* __restrict__ y){
    long row = blockIdx.x;
    const __half* xr = x + row*DD;
    float v[3]; float m = -INFINITY;
    #pragma unroll
    for(int i=0;i<3;i++){
        float t = __half2float(xr[i*128 + threadIdx.x]);
        v[i]=t; m=fmaxf(m,t);
    }
    __shared__ float sh[32];
    m = blockMax(m, sh);
    float s=0.f;
    #pragma unroll
    for(int i=0;i<3;i++){ v[i]=expf(v[i]-m); s+=v[i]; }
    s = blockSum(s, sh);
    float inv = 1.0f/s;
    __half* yr = y + row*DD;
    #pragma unroll
    for(int i=0;i<3;i++) yr[i*128 + threadIdx.x] = __float2half_rn(v[i]*inv);
}

// ---------------- depthwise 3x3 + exact GELU -> half --------------------------
__global__ void dwconv_gelu_kernel(const float* __restrict__ h1, const float* __restrict__ w,
                                   const float* __restrict__ bias, __half* __restrict__ h2){
    int c = blockIdx.x*blockDim.x + threadIdx.x;
    int y = blockIdx.y, b = blockIdx.z;
    const float* rowc = h1 + ((long)b*NN_TOK + y*32)*C4 + c;
    const float* rowm = rowc - 32*C4;
    const float* rowp = rowc + 32*C4;
    bool ym = (y > 0), yp = (y < 31);
    const float* wc = w + c*9;
    float w0=wc[0],w1=wc[1],w2=wc[2],w3=wc[3],w4=wc[4],w5=wc[5],w6=wc[6],w7=wc[7],w8=wc[8];
    float bs = bias[c];
    __half* outr = h2 + ((long)b*NN_TOK + y*32)*C4 + c;

    float pt=0.f, pm=0.f, pb=0.f;
    float ct = ym ? rowm[0] : 0.f;
    float cm = rowc[0];
    float cb = yp ? rowp[0] : 0.f;
    #pragma unroll 4
    for(int x=0;x<32;x++){
        float nt=0.f, nm=0.f, nb=0.f;
        if(x < 31){
            long o = (long)(x+1)*C4;
            nt = ym ? rowm[o] : 0.f;
            nm = rowc[o];
            nb = yp ? rowp[o] : 0.f;
        }
        float acc = bs;
        acc = fmaf(pt,w0,acc); acc = fmaf(ct,w1,acc); acc = fmaf(nt,w2,acc);
        acc = fmaf(pm,w3,acc); acc = fmaf(cm,w4,acc); acc = fmaf(nm,w5,acc);
        acc = fmaf(pb,w6,acc); acc = fmaf(cb,w7,acc); acc = fmaf(nb,w8,acc);
        float g = 0.5f*acc*(1.f + erff(acc*0.70710678118654752f));
        outr[(long)x*C4] = __float2half_rn(g);
        pt=ct; pm=cm; pb=cb; ct=nt; cm=nm; cb=nb;
    }
}

// ---------------- 3-stage cp.async fp16 GEMM (m16n8k16 + ldmatrix) ------------
// C = A@B (+bias)(+res); A,B half; C float or half (OUTH).
// 128x128x64 tile, 3 stages, 256 threads, warp tile 32x64.
// M%128==0, N%128==0, K%64==0, lda/ldb % 8 == 0.
#define ASTH 72                    // halfs per A row (64 + 8 pad); 144B, 16B-mult
#define BSTH 136                   // halfs per B row (128 + 8 pad); 272B
#define A_STAGEH (128*ASTH)        // 9216 halfs
#define B_STAGEH (64*BSTH)         // 8704 halfs
#define STAGEH (A_STAGEH + B_STAGEH)
#define SMEM_GEMM (3*STAGEH*2)     // 107520 bytes

template<bool BIAS, bool RES, bool OUTH>
__global__ __launch_bounds__(256,2)
void mma_gemm_kernel(const __half* __restrict__ A, const __half* __restrict__ Bm,
                     const float* __restrict__ bias, const float* __restrict__ res,
                     void* __restrict__ Cv,
                     int M, int N, int K, int lda, int ldb, int ldc,
                     long long sA, long long sB, long long sC){
    int bz = blockIdx.z;
    A  += (long long)bz*sA;
    Bm += (long long)bz*sB;
    float* Cf = (float*)Cv + (OUTH ? 0 : (long long)bz*sC);
    __half* Ch = (__half*)Cv + (OUTH ? (long long)bz*sC : 0);
    const float* R = RES ? res + (long long)bz*sC : nullptr;

    extern __shared__ __align__(16) __half hsm[];   // [3][STAGEH]

    const int rowT = blockIdx.y*128, colT = blockIdx.x*128;
    const int tid = threadIdx.x;
    const int warp = tid >> 5, lane = tid & 31;
    const int grp = lane >> 2, tg = lane & 3;
    const int warpRow = (warp & 3) * 32;
    const int warpCol = (warp >> 2) * 64;

    // cp.async coordinates: A 128 rows x 8 chunks(16B); B 64 rows x 16 chunks
    const int a_r = tid & 127, a_cb = (tid >> 7) * 4;   // 4 chunks each
    const int b_r = tid & 63,  b_cb = (tid >> 6) * 4;

    const int nIt = K >> 6;

    auto issue = [&](int it, int st){
        int k0 = it << 6;
        __half* Ad = hsm + st*STAGEH;
        __half* Bd = Ad + A_STAGEH;
        #pragma unroll
        for(int i=0;i<4;i++){
            int c8 = (a_cb + i) * 8;
            cp16((uint32_t)__cvta_generic_to_shared(&Ad[a_r*ASTH + c8]),
                 &A[(long)(rowT+a_r)*lda + k0 + c8]);
        }
        #pragma unroll
        for(int i=0;i<4;i++){
            int c8 = (b_cb + i) * 8;
            cp16((uint32_t)__cvta_generic_to_shared(&Bd[b_r*BSTH + c8]),
                 &Bm[(long)(k0+b_r)*ldb + colT + c8]);
        }
        cp_commit();
    };

    float acc[2][8][4];
    #pragma unroll
    for(int mi=0;mi<2;mi++)
        #pragma unroll
        for(int ni=0;ni<8;ni++)
            #pragma unroll
            for(int t=0;t<4;t++) acc[mi][ni][t]=0.f;

    issue(0, 0);
    if(nIt > 1) issue(1, 1);
    int st = 0;
    for(int it=0; it<nIt; it++){
        if(it+2 < nIt){
            int s2 = st+2; if(s2>=3) s2-=3;
            issue(it+2, s2);
            cp_wait2();
        } else if(it+1 < nIt){
            cp_wait1();
        } else {
            cp_wait0();
        }
        __syncthreads();
        const __half* Ac = hsm + st*STAGEH;
        const __half* Bc = Ac + A_STAGEH;
        uint32_t a_base = (uint32_t)__cvta_generic_to_shared(Ac);
        uint32_t b_base = (uint32_t)__cvta_generic_to_shared(Bc);
        #pragma unroll
        for(int kk=0;kk<4;kk++){
            uint32_t a[2][4], b[4][4];
            #pragma unroll
            for(int mi=0;mi<2;mi++){
                uint32_t addr = a_base +
                    ((warpRow + mi*16 + (lane & 15))*ASTH + kk*16 + (lane >> 4)*8)*2;
                ldsm4(a[mi], addr);
            }
            #pragma unroll
            for(int np=0;np<4;np++){
                uint32_t addr = b_base +
                    ((kk*16 + (lane & 15))*BSTH + warpCol + np*16 + (lane >> 4)*8)*2;
                ldsm4t(b[np], addr);
            }
            #pragma unroll
            for(int mi=0;mi<2;mi++)
                #pragma unroll
                for(int np=0;np<4;np++){
                    mma_f16(acc[mi][np*2+0], a[mi], &b[np][0]);
                    mma_f16(acc[mi][np*2+1], a[mi], &b[np][2]);
                }
        }
        __syncthreads();
        if(++st == 3) st = 0;
    }

    // epilogue
    #pragma unroll
    for(int mi=0;mi<2;mi++){
        #pragma unroll
        for(int ni=0;ni<8;ni++){
            int r0 = rowT + warpRow + mi*16 + grp;
            int col = colT + warpCol + ni*8 + tg*2;
            float2 o0, o1;
            o0.x = acc[mi][ni][0]; o0.y = acc[mi][ni][1];
            o1.x = acc[mi][ni][2]; o1.y = acc[mi][ni][3];
            if(BIAS){
                float b0 = bias[col], b1 = bias[col+1];
                o0.x += b0; o0.y += b1;
                o1.x += b0; o1.y += b1;
            }
            if(RES){
                const float2 r0v = *(const float2*)&R[(long)r0*ldc + col];
                const float2 r1v = *(const float2*)&R[(long)(r0+8)*ldc + col];
                o0.x += r0v.x; o0.y += r0v.y;
                o1.x += r1v.x; o1.y += r1v.y;
            }
            if(OUTH){
                __half2 h0 = __floats2half2_rn(o0.x, o0.y);
                __half2 h1 = __floats2half2_rn(o1.x, o1.y);
                *(__half2*)&Ch[(long)r0*ldc + col] = h0;
                *(__half2*)&Ch[(long)(r0+8)*ldc + col] = h1;
            }else{
                *(float2*)&Cf[(long)r0*ldc + col] = o0;
                *(float2*)&Cf[(long)(r0+8)*ldc + col] = o1;
            }
        }
    }
}

// ---------------- host side ---------------------------------------------------
static void* symaddr(const void* sym){
    void* p = nullptr;
    cudaGetSymbolAddress(&p, sym);
    return p;
}

extern "C" void kernel_launch(void* const* d_in, const int* in_sizes, int n_in,
                              void* d_out, int out_size){
    const float* x1       = (const float*)d_in[0];
    const float* x2       = (const float*)d_in[1];
    const float* ln1_g    = (const float*)d_in[2];
    const float* ln1_b    = (const float*)d_in[3];
    const float* ca_qkv_w = (const float*)d_in[4];
    const float* ca_temp  = (const float*)d_in[5];
    const float* ca_proj_w= (const float*)d_in[6];
    const float* ca_proj_b= (const float*)d_in[7];
    const float* ln3_g    = (const float*)d_in[8];
    const float* ln3_b    = (const float*)d_in[9];
    const float* rp_w     = (const float*)d_in[10];
    const float* rp_b     = (const float*)d_in[11];
    const float* cn_g     = (const float*)d_in[12];
    const float* cn_b     = (const float*)d_in[13];
    const float* ln2_g    = (const float*)d_in[14];
    const float* ln2_b    = (const float*)d_in[15];
    const float* fc1_w    = (const float*)d_in[16];
    const float* fc1_b    = (const float*)d_in[17];
    const float* dw_w     = (const float*)d_in[18];
    const float* dw_b     = (const float*)d_in[19];
    const float* fc2_w    = (const float*)d_in[20];
    const float* fc2_b    = (const float*)d_in[21];
    float* out = (float*)d_out;

    float*  p_x      = (float*) symaddr(g_x);
    __half* p_ln     = (__half*)symaddr(g_ln);
    __half* p_lnw    = (__half*)symaddr(g_lnw);
    float*  p_qkv    = (float*) symaddr(g_qkv);
    float*  p_qn     = (float*) symaddr(g_qn);
    float*  p_kn     = (float*) symaddr(g_kn);
    float*  p_attnp  = (float*) symaddr(g_attnp);
    float*  p_attn   = (float*) symaddr(g_attn);
    __half* p_attnout= (__half*)symaddr(g_attnout);
    float*  p_ch     = (float*) symaddr(g_ch);
    __half* p_n      = (__half*)symaddr(g_n);
    __half* p_key    = (__half*)symaddr(g_key);
    __half* p_query  = (__half*)symaddr(g_query);
    __half* p_ctx    = (__half*)symaddr(g_ctx);
    __half* p_att2   = (__half*)symaddr(g_att2);
    float*  p_rep    = (float*) symaddr(g_rep);
    float*  p_crossln= (float*) symaddr(g_crossln);
    float*  p_tx     = (float*) symaddr(g_tx);
    float*  p_h1     = (float*) symaddr(g_h1);
    __half* p_h2     = (__half*)symaddr(g_h2);
    __half* p_wqkv   = (__half*)symaddr(g_wqkv);
    __half* p_wproj  = (__half*)symaddr(g_wproj);
    __half* p_wrpT   = (__half*)symaddr(g_wrpT);
    __half* p_wfc1   = (__half*)symaddr(g_wfc1);
    __half* p_wfc2   = (__half*)symaddr(g_wfc2);

    cudaFuncSetAttribute(mma_gemm_kernel<false,false,false>, cudaFuncAttributeMaxDynamicSharedMemorySize, SMEM_GEMM);
    cudaFuncSetAttribute(mma_gemm_kernel<true ,true ,false>, cudaFuncAttributeMaxDynamicSharedMemorySize, SMEM_GEMM);
    cudaFuncSetAttribute(mma_gemm_kernel<false,false,true >, cudaFuncAttributeMaxDynamicSharedMemorySize, SMEM_GEMM);
    cudaFuncSetAttribute(mma_gemm_kernel<true ,false,false>, cudaFuncAttributeMaxDynamicSharedMemorySize, SMEM_GEMM);

    // ---- pack + weight prep ----
    pack_kernel<<<(T2*DD/4)/256, 256>>>(x1, x2, p_x);
    cvt4_kernel<<<(NW1+NW2+NW3+NW4+255)/256, 256>>>(
        ca_qkv_w, p_wqkv, ca_proj_w, p_wproj, fc1_w, p_wfc1, fc2_w, p_wfc2);
    transpose_cvt_kernel<<<dim3(DD/32, C2/32), dim3(32,8)>>>(rp_w, p_wrpT);

    // ---- channel attention, both streams batched ----
    ln_kernel<__half><<<T2, 128>>>(p_x, ln1_g, ln1_b, p_ln, DD);

    mma_gemm_kernel<false,false,false><<<dim3(1152/128, T2/128, 1), 256, SMEM_GEMM>>>(
        p_ln, p_wqkv, nullptr, nullptr, p_qkv,
        T2, 1152, DD, DD, 1152, 1152, 0, 0, 0);

    l2norm_qk_kernel<<<2*2*BB*HEADS*HD, 256>>>(p_qkv, p_qn, p_kn);
    qk_kernel<<<dim3(8, 2*BB*HEADS), 256>>>(p_qn, p_kn, p_attnp);
    softmax_attn_kernel<<<2*BB*HEADS*HD, 64>>>(p_attnp, p_attn, ca_temp);
    pv_kernel<<<dim3(16, 2*BB*HEADS), 256>>>(p_attn, p_qkv, p_attnout);

    mma_gemm_kernel<true,true,false><<<dim3(DD/128, T2/128, 1), 256, SMEM_GEMM>>>(
        p_attnout, p_wproj, ca_proj_b, p_x, p_ch,
        T2, DD, DD, DD, DD, DD, 0, 0, 0);

    // ---- ln3 (both streams) -> half ----
    ln_kernel<__half><<<T2, 128>>>(p_ch, ln3_g, ln3_b, p_n, DD);
    __half* p_n1 = p_n;
    __half* p_n2 = p_n + (size_t)T_TOK*DD;

    // ---- cross attention ----
    colsoftmax_kernel<<<BB*DD, 256>>>(p_n2, p_key);
    rowsoftmax_kernel<<<T_TOK, 128>>>(p_n2, p_query);

    // ctx[b] = key[b] (D x N) @ n1[b] (N x D) -> half
    mma_gemm_kernel<false,false,true><<<dim3(DD/128, DD/128, BB), 256, SMEM_GEMM>>>(
        p_key, p_n1, nullptr, nullptr, p_ctx,
        DD, DD, NN_TOK, NN_TOK, DD, DD,
        (long long)DD*NN_TOK, (long long)NN_TOK*DD, (long long)DD*DD);

    // att2[b] = query[b] (N x D) @ ctx[b] (D x D) -> half
    mma_gemm_kernel<false,false,true><<<dim3(DD/128, NN_TOK/128, BB), 256, SMEM_GEMM>>>(
        p_query, p_ctx, nullptr, nullptr, p_att2,
        NN_TOK, DD, DD, DD, DD, DD,
        (long long)NN_TOK*DD, (long long)DD*DD, (long long)NN_TOK*DD);

    // rep = att2 (T x 384) @ rpT (384 x 768) + rp_b -> float
    mma_gemm_kernel<true,false,false><<<dim3(C2/128, T_TOK/128, 1), 256, SMEM_GEMM>>>(
        p_att2, p_wrpT, rp_b, nullptr, p_rep,
        T_TOK, C2, DD, DD, C2, C2, 0, 0, 0);

    ln_kernel<float><<<T_TOK, 128>>>(p_rep, cn_g, cn_b, p_crossln, C2);

    // ---- fused tx = concat+cross, ln2 -> half ----
    tx_ln_kernel<<<T_TOK, 128>>>(p_ch, p_crossln, ln2_g, ln2_b, p_tx, p_lnw);

    // ---- MixFFN ----
    mma_gemm_kernel<true,false,false><<<dim3(C4/128, T_TOK/128, 1), 256, SMEM_GEMM>>>(
        p_lnw, p_wfc1, fc1_b, nullptr, p_h1,
        T_TOK, C4, C2, C2, C4, C4, 0, 0, 0);

    dwconv_gelu_kernel<<<dim3(C4/256, 32, BB), 256>>>(p_h1, dw_w, dw_b, p_h2);

    mma_gemm_kernel<true,true,false><<<dim3(C2/128, T_TOK/128, 1), 256, SMEM_GEMM>>>(
        p_h2, p_wfc2, fc2_b, p_tx, out,
        T_TOK, C2, C4, C4, C2, C2, 0, 0, 0);
}